// round 1
// baseline (speedup 1.0000x reference)
#include <cuda_runtime.h>
#include <cuda_bf16.h>
#include <cstdint>

// Problem constants
#define Bc 4
#define Tc 2048
#define Fc 512
#define Hc 8
#define DKc 64
#define Mdim (Bc*Tc)   // 8192
#define Ndim Fc        // 512
#define Kdim Fc        // 512

// Scratch (allowed: __device__ globals, no runtime allocation)
__device__ float g_Q[Bc*Hc*Tc*DKc];
__device__ float g_K[Bc*Hc*Tc*DKc];
__device__ float g_V[Bc*Hc*Tc*DKc];
__device__ float g_CTX[Bc*Tc*Fc];

// ---------------------------------------------------------------------------
// Tiled SGEMM: C[m,n] = sum_k A[m,k]*W[n,k] + bias[n]
// A: [M,K] row-major, W: [N,K] row-major (so this computes A @ W^T + bias).
// BM=BN=128, BK=16, 256 threads, 8x8 micro-tile per thread.
// SCATTER=true  -> write to [B,H,T,DK] layout (for Q/K/V projections)
// SCATTER=false -> write row-major [M,N] (context @ Wo^T -> d_out)
// ---------------------------------------------------------------------------
template<bool SCATTER>
__global__ __launch_bounds__(256, 2)
void gemm128_kernel(const float* __restrict__ A, const float* __restrict__ W,
                    const float* __restrict__ bias, float* __restrict__ C)
{
    __shared__ float As[16][132];
    __shared__ float Bs[16][132];

    const int tid = threadIdx.x;
    const int tx = tid & 15;
    const int ty = tid >> 4;
    const int bm = blockIdx.y * 128;
    const int bn = blockIdx.x * 128;

    const int lr = tid >> 2;          // 0..63
    const int lc = (tid & 3) << 2;    // 0,4,8,12

    const float* Ap = A + (size_t)(bm + lr) * Kdim + lc;
    const float* Wp = W + (size_t)(bn + lr) * Kdim + lc;

    float acc[8][8];
    #pragma unroll
    for (int i = 0; i < 8; i++)
        #pragma unroll
        for (int j = 0; j < 8; j++) acc[i][j] = 0.f;

    for (int k0 = 0; k0 < Kdim; k0 += 16) {
        float4 a0 = *(const float4*)(Ap + k0);
        float4 a1 = *(const float4*)(Ap + k0 + 64 * Kdim);
        float4 w0 = *(const float4*)(Wp + k0);
        float4 w1 = *(const float4*)(Wp + k0 + 64 * Kdim);

        __syncthreads();
        As[lc+0][lr]    = a0.x; As[lc+1][lr]    = a0.y; As[lc+2][lr]    = a0.z; As[lc+3][lr]    = a0.w;
        As[lc+0][lr+64] = a1.x; As[lc+1][lr+64] = a1.y; As[lc+2][lr+64] = a1.z; As[lc+3][lr+64] = a1.w;
        Bs[lc+0][lr]    = w0.x; Bs[lc+1][lr]    = w0.y; Bs[lc+2][lr]    = w0.z; Bs[lc+3][lr]    = w0.w;
        Bs[lc+0][lr+64] = w1.x; Bs[lc+1][lr+64] = w1.y; Bs[lc+2][lr+64] = w1.z; Bs[lc+3][lr+64] = w1.w;
        __syncthreads();

        #pragma unroll
        for (int kk = 0; kk < 16; kk++) {
            float a[8], b[8];
            *(float4*)(a)     = *(float4*)&As[kk][ty*8];
            *(float4*)(a + 4) = *(float4*)&As[kk][ty*8 + 4];
            *(float4*)(b)     = *(float4*)&Bs[kk][tx*8];
            *(float4*)(b + 4) = *(float4*)&Bs[kk][tx*8 + 4];
            #pragma unroll
            for (int i = 0; i < 8; i++)
                #pragma unroll
                for (int j = 0; j < 8; j++)
                    acc[i][j] = fmaf(a[i], b[j], acc[i][j]);
        }
    }

    float bb[8];
    #pragma unroll
    for (int j = 0; j < 8; j++) bb[j] = bias[bn + tx*8 + j];

    #pragma unroll
    for (int i = 0; i < 8; i++) {
        const int m = bm + ty*8 + i;
        #pragma unroll
        for (int jj = 0; jj < 2; jj++) {
            const int n = bn + tx*8 + jj*4;
            float4 r;
            r.x = acc[i][jj*4+0] + bb[jj*4+0];
            r.y = acc[i][jj*4+1] + bb[jj*4+1];
            r.z = acc[i][jj*4+2] + bb[jj*4+2];
            r.w = acc[i][jj*4+3] + bb[jj*4+3];
            if (!SCATTER) {
                *(float4*)(C + (size_t)m * Ndim + n) = r;
            } else {
                const int b_ = m >> 11;        // m / T
                const int t  = m & 2047;       // m % T
                const int h  = n >> 6;         // n / DK
                const int dk = n & 63;         // n % DK
                *(float4*)(C + ((((size_t)b_*Hc + h)*Tc + t) * DKc) + dk) = r;
            }
        }
    }
}

// ---------------------------------------------------------------------------
// Flash attention (fp32, online softmax, key-position mask).
// Block: 256 threads, handles one (b, h, 64-row Q tile). Iterates 64-key chunks.
// Matches reference semantics: masked scores -> -inf (p forced to 0), so the
// post-softmax where(m,0,·) is implicit. l==0 rows output 0.
// ---------------------------------------------------------------------------
#define SD 68   // padded smem row stride (floats), %4==0 for float4 alignment
#define ATTN_SMEM (4 * 64 * SD * (int)sizeof(float))   // 69632 bytes

__global__ __launch_bounds__(256, 2)
void attn_kernel(const float* __restrict__ Q, const float* __restrict__ K,
                 const float* __restrict__ V, const int* __restrict__ mask,
                 float* __restrict__ CTX)
{
    extern __shared__ float sm[];
    float* sQ = sm;
    float* sK = sm + 64*SD;
    float* sV = sm + 2*64*SD;
    float* sP = sm + 3*64*SD;
    __shared__ int smask[64];

    const int tid = threadIdx.x;
    const int tx = tid & 15;
    const int ty = tid >> 4;
    const int qt = blockIdx.x;   // 0..31
    const int h  = blockIdx.y;
    const int b  = blockIdx.z;

    const size_t head_base = (((size_t)b * Hc + h) * Tc) * DKc;
    const float* Qb = Q + head_base + (size_t)qt * 64 * DKc;
    const float* Kb = K + head_base;
    const float* Vb = V + head_base;

    // Load Q tile (64x64) into smem
    #pragma unroll
    for (int it = 0; it < 4; it++) {
        const int idx = tid + it * 256;
        const int r = idx >> 4;
        const int c = (idx & 15) << 2;
        *(float4*)(sQ + r*SD + c) = *(const float4*)(Qb + r*DKc + c);
    }

    float acc[4][4];
    float mi[4], li[4];
    #pragma unroll
    for (int i = 0; i < 4; i++) {
        mi[i] = -1e30f; li[i] = 0.f;
        #pragma unroll
        for (int j = 0; j < 4; j++) acc[i][j] = 0.f;
    }

    for (int kc = 0; kc < 32; kc++) {
        __syncthreads();   // protect sK/sV/sP from previous iteration's readers
        const float* Kc = Kb + (size_t)kc * 64 * DKc;
        const float* Vc = Vb + (size_t)kc * 64 * DKc;
        #pragma unroll
        for (int it = 0; it < 4; it++) {
            const int idx = tid + it * 256;
            const int r = idx >> 4;
            const int c = (idx & 15) << 2;
            *(float4*)(sK + r*SD + c) = *(const float4*)(Kc + r*DKc + c);
            *(float4*)(sV + r*SD + c) = *(const float4*)(Vc + r*DKc + c);
        }
        if (tid < 64) smask[tid] = mask[b * Tc + kc*64 + tid];
        __syncthreads();

        // S = (Q K^T) * 0.125, 4x4 per thread
        float s[4][4];
        #pragma unroll
        for (int i = 0; i < 4; i++)
            #pragma unroll
            for (int j = 0; j < 4; j++) s[i][j] = 0.f;

        #pragma unroll
        for (int d4 = 0; d4 < 16; d4++) {
            float4 qv[4], kv[4];
            #pragma unroll
            for (int i = 0; i < 4; i++) qv[i] = *(float4*)(sQ + (ty*4+i)*SD + d4*4);
            #pragma unroll
            for (int j = 0; j < 4; j++) kv[j] = *(float4*)(sK + (tx*4+j)*SD + d4*4);
            #pragma unroll
            for (int i = 0; i < 4; i++)
                #pragma unroll
                for (int j = 0; j < 4; j++) {
                    s[i][j] = fmaf(qv[i].x, kv[j].x, s[i][j]);
                    s[i][j] = fmaf(qv[i].y, kv[j].y, s[i][j]);
                    s[i][j] = fmaf(qv[i].z, kv[j].z, s[i][j]);
                    s[i][j] = fmaf(qv[i].w, kv[j].w, s[i][j]);
                }
        }

        int vmask[4];
        #pragma unroll
        for (int j = 0; j < 4; j++) vmask[j] = smask[tx*4 + j];

        #pragma unroll
        for (int i = 0; i < 4; i++) {
            float mx = -1e30f;
            #pragma unroll
            for (int j = 0; j < 4; j++) {
                const float se = vmask[j] ? s[i][j] * 0.125f : -1e30f;
                s[i][j] = se;
                mx = fmaxf(mx, se);
            }
            #pragma unroll
            for (int off = 8; off >= 1; off >>= 1)
                mx = fmaxf(mx, __shfl_xor_sync(0xffffffffu, mx, off, 16));

            const float mnew = fmaxf(mi[i], mx);
            const float alpha = __expf(mi[i] - mnew);
            mi[i] = mnew;

            float4 pr;
            float rs = 0.f;
            {
                float p0 = vmask[0] ? __expf(s[i][0] - mnew) : 0.f;
                float p1 = vmask[1] ? __expf(s[i][1] - mnew) : 0.f;
                float p2 = vmask[2] ? __expf(s[i][2] - mnew) : 0.f;
                float p3 = vmask[3] ? __expf(s[i][3] - mnew) : 0.f;
                pr.x = p0; pr.y = p1; pr.z = p2; pr.w = p3;
                rs = p0 + p1 + p2 + p3;
            }
            #pragma unroll
            for (int off = 8; off >= 1; off >>= 1)
                rs += __shfl_xor_sync(0xffffffffu, rs, off, 16);

            li[i] = li[i] * alpha + rs;
            *(float4*)(sP + (ty*4+i)*SD + tx*4) = pr;

            #pragma unroll
            for (int j = 0; j < 4; j++) acc[i][j] *= alpha;
        }
        __syncthreads();

        // O += P @ V
        #pragma unroll 4
        for (int c = 0; c < 64; c++) {
            const float4 vv = *(float4*)(sV + c*SD + tx*4);
            #pragma unroll
            for (int i = 0; i < 4; i++) {
                const float p = sP[(ty*4+i)*SD + c];
                acc[i][0] = fmaf(p, vv.x, acc[i][0]);
                acc[i][1] = fmaf(p, vv.y, acc[i][1]);
                acc[i][2] = fmaf(p, vv.z, acc[i][2]);
                acc[i][3] = fmaf(p, vv.w, acc[i][3]);
            }
        }
    }

    // Normalize and write context in [B, T, F=h*DK+dk] layout
    #pragma unroll
    for (int i = 0; i < 4; i++) {
        const float inv = (li[i] > 0.f) ? (1.0f / li[i]) : 0.f;
        const int t = qt*64 + ty*4 + i;
        float4 r;
        r.x = acc[i][0] * inv;
        r.y = acc[i][1] * inv;
        r.z = acc[i][2] * inv;
        r.w = acc[i][3] * inv;
        *(float4*)(CTX + ((size_t)b * Tc + t) * Fc + h*DKc + tx*4) = r;
    }
}

// ---------------------------------------------------------------------------
// Launcher
// ---------------------------------------------------------------------------
extern "C" void kernel_launch(void* const* d_in, const int* in_sizes, int n_in,
                              void* d_out, int out_size)
{
    const float* query = (const float*)d_in[0];
    const float* key   = (const float*)d_in[1];
    const float* value = (const float*)d_in[2];
    const int*   amask = (const int*)  d_in[3];
    const float* Wq = (const float*)d_in[4];
    const float* bq = (const float*)d_in[5];
    const float* Wk = (const float*)d_in[6];
    const float* bk = (const float*)d_in[7];
    const float* Wv = (const float*)d_in[8];
    const float* bv = (const float*)d_in[9];
    const float* Wo = (const float*)d_in[10];
    const float* bo = (const float*)d_in[11];
    float* out = (float*)d_out;

    float *pQ, *pK, *pV, *pC;
    cudaGetSymbolAddress((void**)&pQ, g_Q);
    cudaGetSymbolAddress((void**)&pK, g_K);
    cudaGetSymbolAddress((void**)&pV, g_V);
    cudaGetSymbolAddress((void**)&pC, g_CTX);

    cudaFuncSetAttribute(attn_kernel,
                         cudaFuncAttributeMaxDynamicSharedMemorySize, ATTN_SMEM);

    const dim3 gemm_grid(Ndim / 128, Mdim / 128);  // (4, 64)

    gemm128_kernel<true><<<gemm_grid, 256>>>(query, Wq, bq, pQ);
    gemm128_kernel<true><<<gemm_grid, 256>>>(key,   Wk, bk, pK);
    gemm128_kernel<true><<<gemm_grid, 256>>>(value, Wv, bv, pV);

    attn_kernel<<<dim3(Tc/64, Hc, Bc), 256, ATTN_SMEM>>>(pQ, pK, pV, amask, pC);

    gemm128_kernel<false><<<gemm_grid, 256>>>(pC, Wo, bo, out);
}

// round 2
// speedup vs baseline: 1.4459x; 1.4459x over previous
#include <cuda_runtime.h>
#include <cuda_bf16.h>
#include <cstdint>

// Problem constants
#define Bc 4
#define Tc 2048
#define Fc 512
#define Hc 8
#define DKc 64
#define Mdim (Bc*Tc)   // 8192
#define Ndim Fc        // 512
#define Kdim Fc        // 512

typedef unsigned long long u64;

// ---- packed f32x2 helpers (FFMA2: full-rate fp32 on Blackwell) ----
__device__ __forceinline__ u64 dup2(float x) {
    u64 r; asm("mov.b64 %0, {%1, %1};" : "=l"(r) : "f"(x)); return r;
}
__device__ __forceinline__ void ffma2(u64& d, u64 a, u64 b) {
    asm("fma.rn.f32x2 %0, %1, %2, %0;" : "+l"(d) : "l"(a), "l"(b));
}
__device__ __forceinline__ u64 mul2(u64 a, u64 b) {
    u64 d; asm("mul.rn.f32x2 %0, %1, %2;" : "=l"(d) : "l"(a), "l"(b)); return d;
}
__device__ __forceinline__ float2 unp2(u64 v) {
    float lo, hi; asm("mov.b64 {%0, %1}, %2;" : "=f"(lo), "=f"(hi) : "l"(v));
    return make_float2(lo, hi);
}

// Scratch
__device__ float g_Q[Bc*Hc*Tc*DKc];
__device__ float g_K[Bc*Hc*Tc*DKc];
__device__ float g_V[Bc*Hc*Tc*DKc];
__device__ float g_CTX[Bc*Tc*Fc];

// ---------------------------------------------------------------------------
// Tiled SGEMM (FFMA2): C = A @ W^T + bias.  BM=BN=128, BK=16, 256 thr, 8x8.
// ---------------------------------------------------------------------------
template<bool SCATTER>
__global__ __launch_bounds__(256, 2)
void gemm128_kernel(const float* __restrict__ A, const float* __restrict__ W,
                    const float* __restrict__ bias, float* __restrict__ C)
{
    __shared__ float As[16][132];
    __shared__ float Bs[16][132];

    const int tid = threadIdx.x;
    const int tx = tid & 15;
    const int ty = tid >> 4;
    const int bm = blockIdx.y * 128;
    const int bn = blockIdx.x * 128;

    const int lr = tid >> 2;          // 0..63
    const int lc = (tid & 3) << 2;    // 0,4,8,12

    const float* Ap = A + (size_t)(bm + lr) * Kdim + lc;
    const float* Wp = W + (size_t)(bn + lr) * Kdim + lc;

    u64 acc2[8][4];
    #pragma unroll
    for (int i = 0; i < 8; i++)
        #pragma unroll
        for (int j = 0; j < 4; j++) acc2[i][j] = 0ull;

    for (int k0 = 0; k0 < Kdim; k0 += 16) {
        float4 a0 = *(const float4*)(Ap + k0);
        float4 a1 = *(const float4*)(Ap + k0 + 64 * Kdim);
        float4 w0 = *(const float4*)(Wp + k0);
        float4 w1 = *(const float4*)(Wp + k0 + 64 * Kdim);

        __syncthreads();
        As[lc+0][lr]    = a0.x; As[lc+1][lr]    = a0.y; As[lc+2][lr]    = a0.z; As[lc+3][lr]    = a0.w;
        As[lc+0][lr+64] = a1.x; As[lc+1][lr+64] = a1.y; As[lc+2][lr+64] = a1.z; As[lc+3][lr+64] = a1.w;
        Bs[lc+0][lr]    = w0.x; Bs[lc+1][lr]    = w0.y; Bs[lc+2][lr]    = w0.z; Bs[lc+3][lr]    = w0.w;
        Bs[lc+0][lr+64] = w1.x; Bs[lc+1][lr+64] = w1.y; Bs[lc+2][lr+64] = w1.z; Bs[lc+3][lr+64] = w1.w;
        __syncthreads();

        #pragma unroll
        for (int kk = 0; kk < 16; kk++) {
            float a[8];
            *(float4*)(a)     = *(float4*)&As[kk][ty*8];
            *(float4*)(a + 4) = *(float4*)&As[kk][ty*8 + 4];
            ulonglong2 bA = *(const ulonglong2*)&Bs[kk][tx*8];
            ulonglong2 bB = *(const ulonglong2*)&Bs[kk][tx*8 + 4];
            #pragma unroll
            for (int i = 0; i < 8; i++) {
                u64 ad = dup2(a[i]);
                ffma2(acc2[i][0], ad, bA.x);
                ffma2(acc2[i][1], ad, bA.y);
                ffma2(acc2[i][2], ad, bB.x);
                ffma2(acc2[i][3], ad, bB.y);
            }
        }
    }

    float bb[8];
    #pragma unroll
    for (int j = 0; j < 8; j++) bb[j] = bias[bn + tx*8 + j];

    #pragma unroll
    for (int i = 0; i < 8; i++) {
        const int m = bm + ty*8 + i;
        #pragma unroll
        for (int jj = 0; jj < 2; jj++) {
            const int n = bn + tx*8 + jj*4;
            float2 e0 = unp2(acc2[i][jj*2]);
            float2 e1 = unp2(acc2[i][jj*2+1]);
            float4 r;
            r.x = e0.x + bb[jj*4+0];
            r.y = e0.y + bb[jj*4+1];
            r.z = e1.x + bb[jj*4+2];
            r.w = e1.y + bb[jj*4+3];
            if (!SCATTER) {
                *(float4*)(C + (size_t)m * Ndim + n) = r;
            } else {
                const int b_ = m >> 11;
                const int t  = m & 2047;
                const int h  = n >> 6;
                const int dk = n & 63;
                *(float4*)(C + ((((size_t)b_*Hc + h)*Tc + t) * DKc) + dk) = r;
            }
        }
    }
}

// ---------------------------------------------------------------------------
// Flash attention, GEMM-structured, FFMA2.
// Block: 256 threads = 16(ty: 8 rows each) x 16(tx). Tile: 128 q-rows.
// Chunks of 128 keys. QK: 8x8 microtile (tx covers 8 keys). PV: 8x4 (tx covers
// 4 of 64 dk). K transposed into smem; Q and P natural layout (broadcast reads).
// ---------------------------------------------------------------------------
#define SQS 68     // sQ/sV row stride (floats)
#define SKS 132    // sKt/sP row stride (floats)
// floats: sQ 128*68 + sV 128*68 + union(Kt 64*132, P 128*132)
#define ATTN_SMEM_FLOATS (128*SQS + 128*SQS + 128*SKS)
#define ATTN_SMEM_BYTES  (ATTN_SMEM_FLOATS * 4)

__global__ __launch_bounds__(256, 1)
void attn_kernel(const float* __restrict__ Q, const float* __restrict__ K,
                 const float* __restrict__ V, const int* __restrict__ mask,
                 float* __restrict__ CTX)
{
    extern __shared__ float sm[];
    float* sQ  = sm;                    // [128][SQS]
    float* sV  = sQ + 128*SQS;          // [128][SQS]
    float* sKP = sV + 128*SQS;          // Kt [64][SKS] / P [128][SKS]
    __shared__ int smask[128];

    const int tid = threadIdx.x;
    const int tx = tid & 15;
    const int ty = tid >> 4;
    const int row0 = ty * 8;
    const int qt = blockIdx.x;   // 0..15
    const int h  = blockIdx.y;
    const int b  = blockIdx.z;

    const size_t head_base = (((size_t)b * Hc + h) * Tc) * DKc;
    const float* Qb = Q + head_base + (size_t)qt * 128 * DKc;
    const float* Kb = K + head_base;
    const float* Vb = V + head_base;

    // Load Q tile (128x64), natural layout, coalesced
    #pragma unroll
    for (int it = 0; it < 8; it++) {
        const int e = tid + it * 256;
        const int r = e >> 4;
        const int c = (e & 15) << 2;
        *(float4*)(sQ + r*SQS + c) = *(const float4*)(Qb + r*DKc + c);
    }

    u64 acc2[8][2];
    float mi[8], li[8];
    #pragma unroll
    for (int i = 0; i < 8; i++) {
        mi[i] = -1e30f; li[i] = 0.f;
        acc2[i][0] = 0ull; acc2[i][1] = 0ull;
    }

    for (int kc = 0; kc < Tc/128; kc++) {
        __syncthreads();   // previous PV (readers of sKP-as-P, sV) done

        // Load K chunk transposed: sKP[d][key]. Conflict-free STS (lanes vary
        // along key); gmem reads pay ~2x sectors (acceptable, L2-resident).
        const float* Kc = Kb + (size_t)kc * 128 * DKc;
        const float* Vc = Vb + (size_t)kc * 128 * DKc;
        #pragma unroll
        for (int it = 0; it < 8; it++) {
            const int e = tid + it * 256;
            const int key = e & 127;
            const int d4  = e >> 7;     // 0..15
            float4 v = *(const float4*)(Kc + key*DKc + d4*4);
            float* dst = sKP + (d4*4)*SKS + key;
            dst[0*SKS] = v.x; dst[1*SKS] = v.y; dst[2*SKS] = v.z; dst[3*SKS] = v.w;
        }
        // Load V chunk natural
        #pragma unroll
        for (int it = 0; it < 8; it++) {
            const int e = tid + it * 256;
            const int r = e >> 4;
            const int c = (e & 15) << 2;
            *(float4*)(sV + r*SQS + c) = *(const float4*)(Vc + r*DKc + c);
        }
        if (tid < 128) smask[tid] = mask[b * Tc + kc*128 + tid];
        __syncthreads();

        // ---- S = Q K^T (8 rows x 8 keys per thread), FFMA2 ----
        u64 s2[8][4];
        #pragma unroll
        for (int i = 0; i < 8; i++)
            #pragma unroll
            for (int j = 0; j < 4; j++) s2[i][j] = 0ull;

        #pragma unroll 2
        for (int k4 = 0; k4 < 16; k4++) {
            float4 aq[8];
            #pragma unroll
            for (int i = 0; i < 8; i++)
                aq[i] = *(const float4*)(sQ + (row0+i)*SQS + k4*4);
            #pragma unroll
            for (int q = 0; q < 4; q++) {
                const float* kr = sKP + (k4*4+q)*SKS + tx*8;
                ulonglong2 u0 = *(const ulonglong2*)kr;
                ulonglong2 u1 = *(const ulonglong2*)(kr + 4);
                #pragma unroll
                for (int i = 0; i < 8; i++) {
                    const float av = (q == 0) ? aq[i].x : (q == 1) ? aq[i].y
                                   : (q == 2) ? aq[i].z : aq[i].w;
                    u64 ad = dup2(av);
                    ffma2(s2[i][0], ad, u0.x);
                    ffma2(s2[i][1], ad, u0.y);
                    ffma2(s2[i][2], ad, u1.x);
                    ffma2(s2[i][3], ad, u1.y);
                }
            }
        }
        __syncthreads();   // all Kt reads done before P overwrites sKP

        // ---- online softmax (rows reduce across 16 tx lanes) ----
        int vm[8];
        #pragma unroll
        for (int j = 0; j < 8; j++) vm[j] = smask[tx*8 + j];

        #pragma unroll
        for (int i = 0; i < 8; i++) {
            float s[8];
            float2 t0 = unp2(s2[i][0]); s[0] = t0.x; s[1] = t0.y;
            float2 t1 = unp2(s2[i][1]); s[2] = t1.x; s[3] = t1.y;
            float2 t2 = unp2(s2[i][2]); s[4] = t2.x; s[5] = t2.y;
            float2 t3 = unp2(s2[i][3]); s[6] = t3.x; s[7] = t3.y;

            float mx = -1e30f;
            #pragma unroll
            for (int j = 0; j < 8; j++) {
                s[j] = vm[j] ? s[j] * 0.125f : -1e30f;
                mx = fmaxf(mx, s[j]);
            }
            #pragma unroll
            for (int off = 8; off >= 1; off >>= 1)
                mx = fmaxf(mx, __shfl_xor_sync(0xffffffffu, mx, off, 16));

            const float mnew = fmaxf(mi[i], mx);
            const float alpha = __expf(mi[i] - mnew);
            mi[i] = mnew;

            float p[8];
            float rs = 0.f;
            #pragma unroll
            for (int j = 0; j < 8; j++) {
                p[j] = vm[j] ? __expf(s[j] - mnew) : 0.f;
                rs += p[j];
            }
            #pragma unroll
            for (int off = 8; off >= 1; off >>= 1)
                rs += __shfl_xor_sync(0xffffffffu, rs, off, 16);
            li[i] = li[i] * alpha + rs;

            float4 w0 = make_float4(p[0], p[1], p[2], p[3]);
            float4 w1 = make_float4(p[4], p[5], p[6], p[7]);
            *(float4*)(sKP + (row0+i)*SKS + tx*8)     = w0;
            *(float4*)(sKP + (row0+i)*SKS + tx*8 + 4) = w1;

            u64 ad = dup2(alpha);
            acc2[i][0] = mul2(acc2[i][0], ad);
            acc2[i][1] = mul2(acc2[i][1], ad);
        }
        __syncthreads();   // P visible

        // ---- O += P @ V (8 rows x 4 dk per thread), FFMA2 ----
        #pragma unroll 2
        for (int k4 = 0; k4 < 32; k4++) {
            float4 ap[8];
            #pragma unroll
            for (int i = 0; i < 8; i++)
                ap[i] = *(const float4*)(sKP + (row0+i)*SKS + k4*4);
            #pragma unroll
            for (int q = 0; q < 4; q++) {
                const float* vr = sV + (k4*4+q)*SQS + tx*4;
                ulonglong2 vv = *(const ulonglong2*)vr;
                #pragma unroll
                for (int i = 0; i < 8; i++) {
                    const float av = (q == 0) ? ap[i].x : (q == 1) ? ap[i].y
                                   : (q == 2) ? ap[i].z : ap[i].w;
                    u64 ad = dup2(av);
                    ffma2(acc2[i][0], ad, vv.x);
                    ffma2(acc2[i][1], ad, vv.y);
                }
            }
        }
    }

    // Normalize and write context [B, T, F]
    #pragma unroll
    for (int i = 0; i < 8; i++) {
        const float inv = (li[i] > 0.f) ? (1.0f / li[i]) : 0.f;
        const int t = qt*128 + row0 + i;
        float2 lo = unp2(acc2[i][0]);
        float2 hi = unp2(acc2[i][1]);
        float4 r;
        r.x = lo.x * inv; r.y = lo.y * inv;
        r.z = hi.x * inv; r.w = hi.y * inv;
        *(float4*)(CTX + ((size_t)b * Tc + t) * Fc + h*DKc + tx*4) = r;
    }
}

// ---------------------------------------------------------------------------
// Launcher
// ---------------------------------------------------------------------------
extern "C" void kernel_launch(void* const* d_in, const int* in_sizes, int n_in,
                              void* d_out, int out_size)
{
    const float* query = (const float*)d_in[0];
    const float* key   = (const float*)d_in[1];
    const float* value = (const float*)d_in[2];
    const int*   amask = (const int*)  d_in[3];
    const float* Wq = (const float*)d_in[4];
    const float* bq = (const float*)d_in[5];
    const float* Wk = (const float*)d_in[6];
    const float* bk = (const float*)d_in[7];
    const float* Wv = (const float*)d_in[8];
    const float* bv = (const float*)d_in[9];
    const float* Wo = (const float*)d_in[10];
    const float* bo = (const float*)d_in[11];
    float* out = (float*)d_out;

    float *pQ, *pK, *pV, *pC;
    cudaGetSymbolAddress((void**)&pQ, g_Q);
    cudaGetSymbolAddress((void**)&pK, g_K);
    cudaGetSymbolAddress((void**)&pV, g_V);
    cudaGetSymbolAddress((void**)&pC, g_CTX);

    cudaFuncSetAttribute(attn_kernel,
                         cudaFuncAttributeMaxDynamicSharedMemorySize, ATTN_SMEM_BYTES);

    const dim3 gemm_grid(Ndim / 128, Mdim / 128);  // (4, 64)

    gemm128_kernel<true><<<gemm_grid, 256>>>(query, Wq, bq, pQ);
    gemm128_kernel<true><<<gemm_grid, 256>>>(key,   Wk, bk, pK);
    gemm128_kernel<true><<<gemm_grid, 256>>>(value, Wv, bv, pV);

    attn_kernel<<<dim3(Tc/128, Hc, Bc), 256, ATTN_SMEM_BYTES>>>(pQ, pK, pV, amask, pC);

    gemm128_kernel<false><<<gemm_grid, 256>>>(pC, Wo, bo, out);
}

// round 3
// speedup vs baseline: 2.2324x; 1.5439x over previous
#include <cuda_runtime.h>
#include <cuda_bf16.h>
#include <cstdint>

// Problem constants
#define Bc 4
#define Tc 2048
#define Fc 512
#define Hc 8
#define DKc 64
#define Mdim (Bc*Tc)   // 8192
#define Ndim Fc        // 512
#define Kdim Fc        // 512

typedef unsigned long long u64;

// ---- packed f32x2 helpers (FFMA2) ----
__device__ __forceinline__ u64 dup2(float x) {
    u64 r; asm("mov.b64 %0, {%1, %1};" : "=l"(r) : "f"(x)); return r;
}
__device__ __forceinline__ void ffma2(u64& d, u64 a, u64 b) {
    asm("fma.rn.f32x2 %0, %1, %2, %0;" : "+l"(d) : "l"(a), "l"(b));
}
__device__ __forceinline__ float2 unp2(u64 v) {
    float lo, hi; asm("mov.b64 {%0, %1}, %2;" : "=f"(lo), "=f"(hi) : "l"(v));
    return make_float2(lo, hi);
}

// ---- tf32 helpers ----
__device__ __forceinline__ uint32_t f2tf32(float x) {
    uint32_t r; asm("cvt.rna.tf32.f32 %0, %1;" : "=r"(r) : "f"(x)); return r;
}
__device__ __forceinline__ void mma_tf32(float& c0, float& c1, float& c2, float& c3,
                                         uint32_t a0, uint32_t a1, uint32_t a2, uint32_t a3,
                                         uint32_t b0, uint32_t b1) {
    asm volatile("mma.sync.aligned.m16n8k8.row.col.f32.tf32.tf32.f32 "
                 "{%0,%1,%2,%3}, {%4,%5,%6,%7}, {%8,%9}, {%0,%1,%2,%3};"
                 : "+f"(c0), "+f"(c1), "+f"(c2), "+f"(c3)
                 : "r"(a0), "r"(a1), "r"(a2), "r"(a3), "r"(b0), "r"(b1));
}

// Scratch
__device__ float g_Q[Bc*Hc*Tc*DKc];
__device__ float g_K[Bc*Hc*Tc*DKc];
__device__ float g_V[Bc*Hc*Tc*DKc];
__device__ float g_CTX[Bc*Tc*Fc];

// ---------------------------------------------------------------------------
// Tiled SGEMM (FFMA2): C = A @ W^T + bias.  BM=BN=128, BK=16, 256 thr, 8x8.
// ---------------------------------------------------------------------------
template<bool SCATTER>
__global__ __launch_bounds__(256, 2)
void gemm128_kernel(const float* __restrict__ A, const float* __restrict__ W,
                    const float* __restrict__ bias, float* __restrict__ C)
{
    __shared__ float As[16][132];
    __shared__ float Bs[16][132];

    const int tid = threadIdx.x;
    const int tx = tid & 15;
    const int ty = tid >> 4;
    const int bm = blockIdx.y * 128;
    const int bn = blockIdx.x * 128;

    const int lr = tid >> 2;
    const int lc = (tid & 3) << 2;

    const float* Ap = A + (size_t)(bm + lr) * Kdim + lc;
    const float* Wp = W + (size_t)(bn + lr) * Kdim + lc;

    u64 acc2[8][4];
    #pragma unroll
    for (int i = 0; i < 8; i++)
        #pragma unroll
        for (int j = 0; j < 4; j++) acc2[i][j] = 0ull;

    for (int k0 = 0; k0 < Kdim; k0 += 16) {
        float4 a0 = *(const float4*)(Ap + k0);
        float4 a1 = *(const float4*)(Ap + k0 + 64 * Kdim);
        float4 w0 = *(const float4*)(Wp + k0);
        float4 w1 = *(const float4*)(Wp + k0 + 64 * Kdim);

        __syncthreads();
        As[lc+0][lr]    = a0.x; As[lc+1][lr]    = a0.y; As[lc+2][lr]    = a0.z; As[lc+3][lr]    = a0.w;
        As[lc+0][lr+64] = a1.x; As[lc+1][lr+64] = a1.y; As[lc+2][lr+64] = a1.z; As[lc+3][lr+64] = a1.w;
        Bs[lc+0][lr]    = w0.x; Bs[lc+1][lr]    = w0.y; Bs[lc+2][lr]    = w0.z; Bs[lc+3][lr]    = w0.w;
        Bs[lc+0][lr+64] = w1.x; Bs[lc+1][lr+64] = w1.y; Bs[lc+2][lr+64] = w1.z; Bs[lc+3][lr+64] = w1.w;
        __syncthreads();

        #pragma unroll
        for (int kk = 0; kk < 16; kk++) {
            float a[8];
            *(float4*)(a)     = *(float4*)&As[kk][ty*8];
            *(float4*)(a + 4) = *(float4*)&As[kk][ty*8 + 4];
            ulonglong2 bA = *(const ulonglong2*)&Bs[kk][tx*8];
            ulonglong2 bB = *(const ulonglong2*)&Bs[kk][tx*8 + 4];
            #pragma unroll
            for (int i = 0; i < 8; i++) {
                u64 ad = dup2(a[i]);
                ffma2(acc2[i][0], ad, bA.x);
                ffma2(acc2[i][1], ad, bA.y);
                ffma2(acc2[i][2], ad, bB.x);
                ffma2(acc2[i][3], ad, bB.y);
            }
        }
    }

    float bb[8];
    #pragma unroll
    for (int j = 0; j < 8; j++) bb[j] = bias[bn + tx*8 + j];

    #pragma unroll
    for (int i = 0; i < 8; i++) {
        const int m = bm + ty*8 + i;
        #pragma unroll
        for (int jj = 0; jj < 2; jj++) {
            const int n = bn + tx*8 + jj*4;
            float2 e0 = unp2(acc2[i][jj*2]);
            float2 e1 = unp2(acc2[i][jj*2+1]);
            float4 r;
            r.x = e0.x + bb[jj*4+0];
            r.y = e0.y + bb[jj*4+1];
            r.z = e1.x + bb[jj*4+2];
            r.w = e1.y + bb[jj*4+3];
            if (!SCATTER) {
                *(float4*)(C + (size_t)m * Ndim + n) = r;
            } else {
                const int b_ = m >> 11;
                const int t  = m & 2047;
                const int h  = n >> 6;
                const int dk = n & 63;
                *(float4*)(C + ((((size_t)b_*Hc + h)*Tc + t) * DKc) + dk) = r;
            }
        }
    }
}

// ---------------------------------------------------------------------------
// Flash attention on tf32 tensor cores (mma.sync m16n8k8).
// CTA: 256 thr = 8 warps; q-tile 128 rows (warp w owns rows w*16..w*16+15).
// Chunks of 128 keys. QK: warp m16 x n128 (16 n-tiles) x k64 (8 k-tiles).
// PV: warp m16 x n64 (8 n-tiles) x k128 (16 k-tiles). P round-trips smem.
// Q pre-scaled by 1/8 (exact). All operands cvt.rna tf32; fp32 accum.
// ---------------------------------------------------------------------------
#define AT_SQS 68     // sQ/sK/sV stride (floats)
#define AT_SPS 136    // sP stride (floats)
#define AT_SMEM_FLOATS (3*128*AT_SQS + 128*AT_SPS)
#define AT_SMEM_BYTES  (AT_SMEM_FLOATS * 4)   // 174080

__global__ __launch_bounds__(256, 1)
void attn_kernel(const float* __restrict__ Q, const float* __restrict__ K,
                 const float* __restrict__ V, const int* __restrict__ mask,
                 float* __restrict__ CTX)
{
    extern __shared__ float smf[];
    uint32_t* sQ = (uint32_t*)smf;              // [128][AT_SQS] tf32
    uint32_t* sK = sQ + 128*AT_SQS;             // [128][AT_SQS] tf32 ([key][d])
    uint32_t* sV = sK + 128*AT_SQS;             // [128][AT_SQS] tf32 ([key][d])
    uint32_t* sP = sV + 128*AT_SQS;             // [128][AT_SPS] tf32
    __shared__ int smask[128];

    const int tid  = threadIdx.x;
    const int lane = tid & 31;
    const int w    = tid >> 5;
    const int g    = lane >> 2;    // 0..7
    const int t    = lane & 3;     // 0..3
    const int r0   = w * 16;
    const int qt = blockIdx.x;
    const int h  = blockIdx.y;
    const int b  = blockIdx.z;

    const size_t head_base = (((size_t)b * Hc + h) * Tc) * DKc;
    const float* Qb = Q + head_base + (size_t)qt * 128 * DKc;
    const float* Kb = K + head_base;
    const float* Vb = V + head_base;

    // Load Q tile (128x64), scale by 1/8, convert to tf32
    #pragma unroll
    for (int it = 0; it < 8; it++) {
        const int e = tid + it * 256;
        const int r = e >> 4;
        const int c = (e & 15) << 2;
        float4 v = *(const float4*)(Qb + r*DKc + c);
        uint4 o;
        o.x = f2tf32(v.x * 0.125f); o.y = f2tf32(v.y * 0.125f);
        o.z = f2tf32(v.z * 0.125f); o.w = f2tf32(v.w * 0.125f);
        *(uint4*)(sQ + r*AT_SQS + c) = o;
    }

    float of[8][4];
    float mi0 = -1e30f, mi1 = -1e30f, li0 = 0.f, li1 = 0.f;
    #pragma unroll
    for (int nt = 0; nt < 8; nt++)
        #pragma unroll
        for (int j = 0; j < 4; j++) of[nt][j] = 0.f;

    for (int kc = 0; kc < Tc/128; kc++) {
        __syncthreads();   // prev chunk's sK/sV/smask readers done

        const float* Kc = Kb + (size_t)kc * 128 * DKc;
        const float* Vc = Vb + (size_t)kc * 128 * DKc;
        #pragma unroll
        for (int it = 0; it < 8; it++) {
            const int e = tid + it * 256;
            const int r = e >> 4;
            const int c = (e & 15) << 2;
            float4 kv = *(const float4*)(Kc + r*DKc + c);
            float4 vv = *(const float4*)(Vc + r*DKc + c);
            uint4 ko, vo;
            ko.x = f2tf32(kv.x); ko.y = f2tf32(kv.y); ko.z = f2tf32(kv.z); ko.w = f2tf32(kv.w);
            vo.x = f2tf32(vv.x); vo.y = f2tf32(vv.y); vo.z = f2tf32(vv.z); vo.w = f2tf32(vv.w);
            *(uint4*)(sK + r*AT_SQS + c) = ko;
            *(uint4*)(sV + r*AT_SQS + c) = vo;
        }
        if (tid < 128) smask[tid] = mask[b * Tc + kc*128 + tid];
        __syncthreads();

        // ---- S = Q K^T : 16 n-tiles of 8 keys, 8 k-tiles of 8 dims ----
        float sf[16][4];
        #pragma unroll
        for (int nt = 0; nt < 16; nt++)
            #pragma unroll
            for (int j = 0; j < 4; j++) sf[nt][j] = 0.f;

        #pragma unroll
        for (int kt = 0; kt < 8; kt++) {
            const uint32_t a0 = sQ[(r0+g  )*AT_SQS + kt*8 + t    ];
            const uint32_t a1 = sQ[(r0+g+8)*AT_SQS + kt*8 + t    ];
            const uint32_t a2 = sQ[(r0+g  )*AT_SQS + kt*8 + t + 4];
            const uint32_t a3 = sQ[(r0+g+8)*AT_SQS + kt*8 + t + 4];
            #pragma unroll
            for (int nt = 0; nt < 16; nt++) {
                const uint32_t b0 = sK[(nt*8+g)*AT_SQS + kt*8 + t    ];
                const uint32_t b1 = sK[(nt*8+g)*AT_SQS + kt*8 + t + 4];
                mma_tf32(sf[nt][0], sf[nt][1], sf[nt][2], sf[nt][3],
                         a0, a1, a2, a3, b0, b1);
            }
        }

        // ---- online softmax (rows r0+g and r0+g+8; cols nt*8+2t, +1) ----
        float mx0 = -1e30f, mx1 = -1e30f;
        #pragma unroll
        for (int nt = 0; nt < 16; nt++) {
            const int m0 = smask[nt*8 + 2*t];
            const int m1 = smask[nt*8 + 2*t + 1];
            sf[nt][0] = m0 ? sf[nt][0] : -1e30f;
            sf[nt][1] = m1 ? sf[nt][1] : -1e30f;
            sf[nt][2] = m0 ? sf[nt][2] : -1e30f;
            sf[nt][3] = m1 ? sf[nt][3] : -1e30f;
            mx0 = fmaxf(mx0, fmaxf(sf[nt][0], sf[nt][1]));
            mx1 = fmaxf(mx1, fmaxf(sf[nt][2], sf[nt][3]));
        }
        mx0 = fmaxf(mx0, __shfl_xor_sync(0xffffffffu, mx0, 1));
        mx0 = fmaxf(mx0, __shfl_xor_sync(0xffffffffu, mx0, 2));
        mx1 = fmaxf(mx1, __shfl_xor_sync(0xffffffffu, mx1, 1));
        mx1 = fmaxf(mx1, __shfl_xor_sync(0xffffffffu, mx1, 2));

        const float mn0 = fmaxf(mi0, mx0);
        const float mn1 = fmaxf(mi1, mx1);
        const float al0 = __expf(mi0 - mn0);
        const float al1 = __expf(mi1 - mn1);
        mi0 = mn0; mi1 = mn1;

        float rs0 = 0.f, rs1 = 0.f;
        #pragma unroll
        for (int nt = 0; nt < 16; nt++) {
            const int m0 = smask[nt*8 + 2*t];
            const int m1 = smask[nt*8 + 2*t + 1];
            const float p00 = m0 ? __expf(sf[nt][0] - mn0) : 0.f;
            const float p01 = m1 ? __expf(sf[nt][1] - mn0) : 0.f;
            const float p10 = m0 ? __expf(sf[nt][2] - mn1) : 0.f;
            const float p11 = m1 ? __expf(sf[nt][3] - mn1) : 0.f;
            rs0 += p00 + p01;
            rs1 += p10 + p11;
            uint2 w0; w0.x = f2tf32(p00); w0.y = f2tf32(p01);
            uint2 w1; w1.x = f2tf32(p10); w1.y = f2tf32(p11);
            *(uint2*)(sP + (r0+g  )*AT_SPS + nt*8 + 2*t) = w0;
            *(uint2*)(sP + (r0+g+8)*AT_SPS + nt*8 + 2*t) = w1;
        }
        rs0 += __shfl_xor_sync(0xffffffffu, rs0, 1);
        rs0 += __shfl_xor_sync(0xffffffffu, rs0, 2);
        rs1 += __shfl_xor_sync(0xffffffffu, rs1, 1);
        rs1 += __shfl_xor_sync(0xffffffffu, rs1, 2);
        li0 = li0 * al0 + rs0;
        li1 = li1 * al1 + rs1;

        #pragma unroll
        for (int nt = 0; nt < 8; nt++) {
            of[nt][0] *= al0; of[nt][1] *= al0;
            of[nt][2] *= al1; of[nt][3] *= al1;
        }

        __syncwarp();   // P rows are private to this warp; make STS visible

        // ---- O += P @ V : 8 n-tiles of 8 dk, 16 k-tiles of 8 keys ----
        #pragma unroll
        for (int kt = 0; kt < 16; kt++) {
            const uint32_t a0 = sP[(r0+g  )*AT_SPS + kt*8 + t    ];
            const uint32_t a1 = sP[(r0+g+8)*AT_SPS + kt*8 + t    ];
            const uint32_t a2 = sP[(r0+g  )*AT_SPS + kt*8 + t + 4];
            const uint32_t a3 = sP[(r0+g+8)*AT_SPS + kt*8 + t + 4];
            #pragma unroll
            for (int nt = 0; nt < 8; nt++) {
                const uint32_t b0 = sV[(kt*8 + t    )*AT_SQS + nt*8 + g];
                const uint32_t b1 = sV[(kt*8 + t + 4)*AT_SQS + nt*8 + g];
                mma_tf32(of[nt][0], of[nt][1], of[nt][2], of[nt][3],
                         a0, a1, a2, a3, b0, b1);
            }
        }
    }

    // Normalize and write context [B, T, F]
    const float inv0 = (li0 > 0.f) ? (1.0f / li0) : 0.f;
    const float inv1 = (li1 > 0.f) ? (1.0f / li1) : 0.f;
    const int t0 = qt*128 + r0 + g;
    const int t1 = t0 + 8;
    #pragma unroll
    for (int nt = 0; nt < 8; nt++) {
        const int dk = nt*8 + 2*t;
        float2 w0; w0.x = of[nt][0] * inv0; w0.y = of[nt][1] * inv0;
        float2 w1; w1.x = of[nt][2] * inv1; w1.y = of[nt][3] * inv1;
        *(float2*)(CTX + ((size_t)b * Tc + t0) * Fc + h*DKc + dk) = w0;
        *(float2*)(CTX + ((size_t)b * Tc + t1) * Fc + h*DKc + dk) = w1;
    }
}

// ---------------------------------------------------------------------------
// Launcher
// ---------------------------------------------------------------------------
extern "C" void kernel_launch(void* const* d_in, const int* in_sizes, int n_in,
                              void* d_out, int out_size)
{
    const float* query = (const float*)d_in[0];
    const float* key   = (const float*)d_in[1];
    const float* value = (const float*)d_in[2];
    const int*   amask = (const int*)  d_in[3];
    const float* Wq = (const float*)d_in[4];
    const float* bq = (const float*)d_in[5];
    const float* Wk = (const float*)d_in[6];
    const float* bk = (const float*)d_in[7];
    const float* Wv = (const float*)d_in[8];
    const float* bv = (const float*)d_in[9];
    const float* Wo = (const float*)d_in[10];
    const float* bo = (const float*)d_in[11];
    float* out = (float*)d_out;

    float *pQ, *pK, *pV, *pC;
    cudaGetSymbolAddress((void**)&pQ, g_Q);
    cudaGetSymbolAddress((void**)&pK, g_K);
    cudaGetSymbolAddress((void**)&pV, g_V);
    cudaGetSymbolAddress((void**)&pC, g_CTX);

    cudaFuncSetAttribute(attn_kernel,
                         cudaFuncAttributeMaxDynamicSharedMemorySize, AT_SMEM_BYTES);

    const dim3 gemm_grid(Ndim / 128, Mdim / 128);  // (4, 64)

    gemm128_kernel<true><<<gemm_grid, 256>>>(query, Wq, bq, pQ);
    gemm128_kernel<true><<<gemm_grid, 256>>>(key,   Wk, bk, pK);
    gemm128_kernel<true><<<gemm_grid, 256>>>(value, Wv, bv, pV);

    attn_kernel<<<dim3(Tc/128, Hc, Bc), 256, AT_SMEM_BYTES>>>(pQ, pK, pV, amask, pC);

    gemm128_kernel<false><<<gemm_grid, 256>>>(pC, Wo, bo, out);
}

// round 4
// speedup vs baseline: 3.8901x; 1.7426x over previous
#include <cuda_runtime.h>
#include <cuda_bf16.h>
#include <cstdint>

// Problem constants
#define Bc 4
#define Tc 2048
#define Fc 512
#define Hc 8
#define DKc 64
#define Mdim (Bc*Tc)   // 8192
#define Ndim Fc        // 512
#define Kdim Fc        // 512

// ---- tf32 helpers ----
__device__ __forceinline__ uint32_t f2tf32(float x) {
    uint32_t r; asm("cvt.rna.tf32.f32 %0, %1;" : "=r"(r) : "f"(x)); return r;
}
__device__ __forceinline__ void mma_tf32(float* c,
                                         uint32_t a0, uint32_t a1, uint32_t a2, uint32_t a3,
                                         uint32_t b0, uint32_t b1) {
    asm volatile("mma.sync.aligned.m16n8k8.row.col.f32.tf32.tf32.f32 "
                 "{%0,%1,%2,%3}, {%4,%5,%6,%7}, {%8,%9}, {%0,%1,%2,%3};"
                 : "+f"(c[0]), "+f"(c[1]), "+f"(c[2]), "+f"(c[3])
                 : "r"(a0), "r"(a1), "r"(a2), "r"(a3), "r"(b0), "r"(b1));
}

// Scratch
__device__ float g_Q[Bc*Hc*Tc*DKc];
__device__ float g_K[Bc*Hc*Tc*DKc];
__device__ float g_V[Bc*Hc*Tc*DKc];
__device__ float g_CTX[Bc*Tc*Fc];

// ---------------------------------------------------------------------------
// tf32 tensor-core GEMM: C = A @ W^T + bias.
// CTA tile 128x128, BK=16, 256 thr = 8 warps (4 m-warps x 2 n-warps),
// warp tile m32 x n64. Double-buffered smem, register prefetch.
// ---------------------------------------------------------------------------
#define GS 20   // smem row stride (uints); bank = row*20+col % 32, conflict-free

template<bool SCATTER>
__global__ __launch_bounds__(256, 2)
void gemm_tf32_kernel(const float* __restrict__ A, const float* __restrict__ W,
                      const float* __restrict__ bias, float* __restrict__ C)
{
    __shared__ uint32_t sA[2][128*GS];
    __shared__ uint32_t sW[2][128*GS];

    const int tid  = threadIdx.x;
    const int lane = tid & 31;
    const int w    = tid >> 5;
    const int g    = lane >> 2;
    const int t    = lane & 3;
    const int wm   = w & 3;          // m-warp: rows wm*32..wm*32+31
    const int wn   = w >> 2;         // n-warp: cols wn*64..wn*64+63
    const int bm = blockIdx.y * 128;
    const int bn = blockIdx.x * 128;

    const int lrow = tid >> 2;          // 0..63 (x2 iters -> 128)
    const int lcol = (tid & 3) << 2;    // 0,4,8,12

    float acc[2][8][4];
    #pragma unroll
    for (int mt = 0; mt < 2; mt++)
        #pragma unroll
        for (int nt = 0; nt < 8; nt++)
            #pragma unroll
            for (int j = 0; j < 4; j++) acc[mt][nt][j] = 0.f;

    float4 ra[2], rw[2];

    // prefetch k0=0
    #pragma unroll
    for (int it = 0; it < 2; it++) {
        const int row = lrow + it * 64;
        ra[it] = *(const float4*)(A + (size_t)(bm + row) * Kdim + lcol);
        rw[it] = *(const float4*)(W + (size_t)(bn + row) * Kdim + lcol);
    }
    // store buf 0
    #pragma unroll
    for (int it = 0; it < 2; it++) {
        const int row = lrow + it * 64;
        uint4 ua, uw;
        ua.x = f2tf32(ra[it].x); ua.y = f2tf32(ra[it].y); ua.z = f2tf32(ra[it].z); ua.w = f2tf32(ra[it].w);
        uw.x = f2tf32(rw[it].x); uw.y = f2tf32(rw[it].y); uw.z = f2tf32(rw[it].z); uw.w = f2tf32(rw[it].w);
        *(uint4*)&sA[0][row*GS + lcol] = ua;
        *(uint4*)&sW[0][row*GS + lcol] = uw;
    }
    __syncthreads();

    const int NIT = Kdim / 16;   // 32
    for (int i = 0; i < NIT; i++) {
        const int buf = i & 1;
        if (i + 1 < NIT) {
            const int k0 = (i + 1) * 16;
            #pragma unroll
            for (int it = 0; it < 2; it++) {
                const int row = lrow + it * 64;
                ra[it] = *(const float4*)(A + (size_t)(bm + row) * Kdim + k0 + lcol);
                rw[it] = *(const float4*)(W + (size_t)(bn + row) * Kdim + k0 + lcol);
            }
        }

        const uint32_t* Ab = sA[buf];
        const uint32_t* Wb = sW[buf];
        #pragma unroll
        for (int k8 = 0; k8 < 2; k8++) {
            uint32_t a[2][4];
            #pragma unroll
            for (int mt = 0; mt < 2; mt++) {
                const int r0 = wm*32 + mt*16;
                a[mt][0] = Ab[(r0+g  )*GS + k8*8 + t    ];
                a[mt][1] = Ab[(r0+g+8)*GS + k8*8 + t    ];
                a[mt][2] = Ab[(r0+g  )*GS + k8*8 + t + 4];
                a[mt][3] = Ab[(r0+g+8)*GS + k8*8 + t + 4];
            }
            #pragma unroll
            for (int nt = 0; nt < 8; nt++) {
                const int c0 = wn*64 + nt*8;
                const uint32_t b0 = Wb[(c0+g)*GS + k8*8 + t    ];
                const uint32_t b1 = Wb[(c0+g)*GS + k8*8 + t + 4];
                mma_tf32(acc[0][nt], a[0][0], a[0][1], a[0][2], a[0][3], b0, b1);
                mma_tf32(acc[1][nt], a[1][0], a[1][1], a[1][2], a[1][3], b0, b1);
            }
        }
        __syncthreads();
        if (i + 1 < NIT) {
            const int nb = buf ^ 1;
            #pragma unroll
            for (int it = 0; it < 2; it++) {
                const int row = lrow + it * 64;
                uint4 ua, uw;
                ua.x = f2tf32(ra[it].x); ua.y = f2tf32(ra[it].y); ua.z = f2tf32(ra[it].z); ua.w = f2tf32(ra[it].w);
                uw.x = f2tf32(rw[it].x); uw.y = f2tf32(rw[it].y); uw.z = f2tf32(rw[it].z); uw.w = f2tf32(rw[it].w);
                *(uint4*)&sA[nb][row*GS + lcol] = ua;
                *(uint4*)&sW[nb][row*GS + lcol] = uw;
            }
            __syncthreads();
        }
    }

    // Epilogue: bias add + store (float2 per fragment row)
    #pragma unroll
    for (int nt = 0; nt < 8; nt++) {
        const int col = bn + wn*64 + nt*8 + 2*t;
        const float2 bb = *(const float2*)(bias + col);
        #pragma unroll
        for (int mt = 0; mt < 2; mt++) {
            const int row0 = bm + wm*32 + mt*16 + g;
            const int row1 = row0 + 8;
            float2 v0, v1;
            v0.x = acc[mt][nt][0] + bb.x; v0.y = acc[mt][nt][1] + bb.y;
            v1.x = acc[mt][nt][2] + bb.x; v1.y = acc[mt][nt][3] + bb.y;
            if (!SCATTER) {
                *(float2*)(C + (size_t)row0 * Ndim + col) = v0;
                *(float2*)(C + (size_t)row1 * Ndim + col) = v1;
            } else {
                const int h  = col >> 6;
                const int dk = col & 63;
                const int b0_ = row0 >> 11, t0_ = row0 & 2047;
                const int b1_ = row1 >> 11, t1_ = row1 & 2047;
                *(float2*)(C + ((((size_t)b0_*Hc + h)*Tc + t0_) * DKc) + dk) = v0;
                *(float2*)(C + ((((size_t)b1_*Hc + h)*Tc + t1_) * DKc) + dk) = v1;
            }
        }
    }
}

// ---------------------------------------------------------------------------
// Flash attention, tf32 mma, 64-key chunks, 2 CTAs/SM.
// CTA: 256 thr = 8 warps; q-tile 128 rows (warp w owns rows w*16..w*16+15).
// QK: warp m16 x n64 x k64.  PV: warp m16 x n64 x k64. P via smem (own rows).
// ---------------------------------------------------------------------------
#define AQS 68    // sQ/sK/sP stride
#define AVS 72    // sV stride (bank = t*8+g, conflict-free for PV B-frags)
#define AT_U32 (128*AQS + 64*AQS + 64*AVS + 128*AQS)
#define AT_SMEM_BYTES (AT_U32 * 4)   // 105,472

__global__ __launch_bounds__(256, 2)
void attn_kernel(const float* __restrict__ Q, const float* __restrict__ K,
                 const float* __restrict__ V, const int* __restrict__ mask,
                 float* __restrict__ CTX)
{
    extern __shared__ uint32_t usm[];
    uint32_t* sQ = usm;                  // [128][AQS]
    uint32_t* sK = sQ + 128*AQS;         // [64][AQS]  ([key][d])
    uint32_t* sV = sK + 64*AQS;          // [64][AVS]  ([key][d])
    uint32_t* sP = sV + 64*AVS;          // [128][AQS]
    __shared__ int smask[64];

    const int tid  = threadIdx.x;
    const int lane = tid & 31;
    const int w    = tid >> 5;
    const int g    = lane >> 2;
    const int t    = lane & 3;
    const int r0   = w * 16;
    const int qt = blockIdx.x;
    const int h  = blockIdx.y;
    const int b  = blockIdx.z;

    const size_t head_base = (((size_t)b * Hc + h) * Tc) * DKc;
    const float* Qb = Q + head_base + (size_t)qt * 128 * DKc;
    const float* Kb = K + head_base;
    const float* Vb = V + head_base;

    // Load Q tile (128x64), scale by 1/8 (exact), convert to tf32
    #pragma unroll
    for (int it = 0; it < 8; it++) {
        const int e = tid + it * 256;
        const int r = e >> 4;
        const int c = (e & 15) << 2;
        float4 v = *(const float4*)(Qb + r*DKc + c);
        uint4 o;
        o.x = f2tf32(v.x * 0.125f); o.y = f2tf32(v.y * 0.125f);
        o.z = f2tf32(v.z * 0.125f); o.w = f2tf32(v.w * 0.125f);
        *(uint4*)(sQ + r*AQS + c) = o;
    }

    float of[8][4];
    float mi0 = -1e30f, mi1 = -1e30f, li0 = 0.f, li1 = 0.f;
    #pragma unroll
    for (int nt = 0; nt < 8; nt++)
        #pragma unroll
        for (int j = 0; j < 4; j++) of[nt][j] = 0.f;

    for (int kc = 0; kc < Tc/64; kc++) {
        __syncthreads();   // prev chunk's sK/sV readers done (covers Q init too)

        const float* Kc = Kb + (size_t)kc * 64 * DKc;
        const float* Vc = Vb + (size_t)kc * 64 * DKc;
        #pragma unroll
        for (int it = 0; it < 4; it++) {
            const int e = tid + it * 256;
            const int r = e >> 4;        // 0..63
            const int c = (e & 15) << 2;
            float4 kv = *(const float4*)(Kc + r*DKc + c);
            float4 vv = *(const float4*)(Vc + r*DKc + c);
            uint4 ko, vo;
            ko.x = f2tf32(kv.x); ko.y = f2tf32(kv.y); ko.z = f2tf32(kv.z); ko.w = f2tf32(kv.w);
            vo.x = f2tf32(vv.x); vo.y = f2tf32(vv.y); vo.z = f2tf32(vv.z); vo.w = f2tf32(vv.w);
            *(uint4*)(sK + r*AQS + c) = ko;
            *(uint4*)(sV + r*AVS + c) = vo;
        }
        if (tid < 64) smask[tid] = mask[b * Tc + kc*64 + tid];
        __syncthreads();

        // ---- S = Q K^T : 8 n-tiles x 8 k-tiles ----
        float sf[8][4];
        #pragma unroll
        for (int nt = 0; nt < 8; nt++)
            #pragma unroll
            for (int j = 0; j < 4; j++) sf[nt][j] = 0.f;

        #pragma unroll
        for (int kt = 0; kt < 8; kt++) {
            const uint32_t a0 = sQ[(r0+g  )*AQS + kt*8 + t    ];
            const uint32_t a1 = sQ[(r0+g+8)*AQS + kt*8 + t    ];
            const uint32_t a2 = sQ[(r0+g  )*AQS + kt*8 + t + 4];
            const uint32_t a3 = sQ[(r0+g+8)*AQS + kt*8 + t + 4];
            #pragma unroll
            for (int nt = 0; nt < 8; nt++) {
                const uint32_t b0 = sK[(nt*8+g)*AQS + kt*8 + t    ];
                const uint32_t b1 = sK[(nt*8+g)*AQS + kt*8 + t + 4];
                mma_tf32(sf[nt], a0, a1, a2, a3, b0, b1);
            }
        }

        // ---- online softmax ----
        float mx0 = -1e30f, mx1 = -1e30f;
        int m8[8][2];
        #pragma unroll
        for (int nt = 0; nt < 8; nt++) {
            m8[nt][0] = smask[nt*8 + 2*t];
            m8[nt][1] = smask[nt*8 + 2*t + 1];
            sf[nt][0] = m8[nt][0] ? sf[nt][0] : -1e30f;
            sf[nt][1] = m8[nt][1] ? sf[nt][1] : -1e30f;
            sf[nt][2] = m8[nt][0] ? sf[nt][2] : -1e30f;
            sf[nt][3] = m8[nt][1] ? sf[nt][3] : -1e30f;
            mx0 = fmaxf(mx0, fmaxf(sf[nt][0], sf[nt][1]));
            mx1 = fmaxf(mx1, fmaxf(sf[nt][2], sf[nt][3]));
        }
        mx0 = fmaxf(mx0, __shfl_xor_sync(0xffffffffu, mx0, 1));
        mx0 = fmaxf(mx0, __shfl_xor_sync(0xffffffffu, mx0, 2));
        mx1 = fmaxf(mx1, __shfl_xor_sync(0xffffffffu, mx1, 1));
        mx1 = fmaxf(mx1, __shfl_xor_sync(0xffffffffu, mx1, 2));

        const float mn0 = fmaxf(mi0, mx0);
        const float mn1 = fmaxf(mi1, mx1);
        const float al0 = __expf(mi0 - mn0);
        const float al1 = __expf(mi1 - mn1);
        mi0 = mn0; mi1 = mn1;

        float rs0 = 0.f, rs1 = 0.f;
        #pragma unroll
        for (int nt = 0; nt < 8; nt++) {
            const float p00 = m8[nt][0] ? __expf(sf[nt][0] - mn0) : 0.f;
            const float p01 = m8[nt][1] ? __expf(sf[nt][1] - mn0) : 0.f;
            const float p10 = m8[nt][0] ? __expf(sf[nt][2] - mn1) : 0.f;
            const float p11 = m8[nt][1] ? __expf(sf[nt][3] - mn1) : 0.f;
            rs0 += p00 + p01;
            rs1 += p10 + p11;
            uint2 w0; w0.x = f2tf32(p00); w0.y = f2tf32(p01);
            uint2 w1; w1.x = f2tf32(p10); w1.y = f2tf32(p11);
            *(uint2*)(sP + (r0+g  )*AQS + nt*8 + 2*t) = w0;
            *(uint2*)(sP + (r0+g+8)*AQS + nt*8 + 2*t) = w1;
        }
        rs0 += __shfl_xor_sync(0xffffffffu, rs0, 1);
        rs0 += __shfl_xor_sync(0xffffffffu, rs0, 2);
        rs1 += __shfl_xor_sync(0xffffffffu, rs1, 1);
        rs1 += __shfl_xor_sync(0xffffffffu, rs1, 2);
        li0 = li0 * al0 + rs0;
        li1 = li1 * al1 + rs1;

        #pragma unroll
        for (int nt = 0; nt < 8; nt++) {
            of[nt][0] *= al0; of[nt][1] *= al0;
            of[nt][2] *= al1; of[nt][3] *= al1;
        }

        __syncwarp();   // P rows are private to this warp

        // ---- O += P @ V : 8 n-tiles (dk) x 8 k-tiles (keys) ----
        #pragma unroll
        for (int kt = 0; kt < 8; kt++) {
            const uint32_t a0 = sP[(r0+g  )*AQS + kt*8 + t    ];
            const uint32_t a1 = sP[(r0+g+8)*AQS + kt*8 + t    ];
            const uint32_t a2 = sP[(r0+g  )*AQS + kt*8 + t + 4];
            const uint32_t a3 = sP[(r0+g+8)*AQS + kt*8 + t + 4];
            #pragma unroll
            for (int nt = 0; nt < 8; nt++) {
                const uint32_t b0 = sV[(kt*8 + t    )*AVS + nt*8 + g];
                const uint32_t b1 = sV[(kt*8 + t + 4)*AVS + nt*8 + g];
                mma_tf32(of[nt], a0, a1, a2, a3, b0, b1);
            }
        }
    }

    // Normalize and write context [B, T, F]
    const float inv0 = (li0 > 0.f) ? (1.0f / li0) : 0.f;
    const float inv1 = (li1 > 0.f) ? (1.0f / li1) : 0.f;
    const int t0 = qt*128 + r0 + g;
    const int t1 = t0 + 8;
    #pragma unroll
    for (int nt = 0; nt < 8; nt++) {
        const int dk = nt*8 + 2*t;
        float2 w0; w0.x = of[nt][0] * inv0; w0.y = of[nt][1] * inv0;
        float2 w1; w1.x = of[nt][2] * inv1; w1.y = of[nt][3] * inv1;
        *(float2*)(CTX + ((size_t)b * Tc + t0) * Fc + h*DKc + dk) = w0;
        *(float2*)(CTX + ((size_t)b * Tc + t1) * Fc + h*DKc + dk) = w1;
    }
}

// ---------------------------------------------------------------------------
// Launcher
// ---------------------------------------------------------------------------
extern "C" void kernel_launch(void* const* d_in, const int* in_sizes, int n_in,
                              void* d_out, int out_size)
{
    const float* query = (const float*)d_in[0];
    const float* key   = (const float*)d_in[1];
    const float* value = (const float*)d_in[2];
    const int*   amask = (const int*)  d_in[3];
    const float* Wq = (const float*)d_in[4];
    const float* bq = (const float*)d_in[5];
    const float* Wk = (const float*)d_in[6];
    const float* bk = (const float*)d_in[7];
    const float* Wv = (const float*)d_in[8];
    const float* bv = (const float*)d_in[9];
    const float* Wo = (const float*)d_in[10];
    const float* bo = (const float*)d_in[11];
    float* out = (float*)d_out;

    float *pQ, *pK, *pV, *pC;
    cudaGetSymbolAddress((void**)&pQ, g_Q);
    cudaGetSymbolAddress((void**)&pK, g_K);
    cudaGetSymbolAddress((void**)&pV, g_V);
    cudaGetSymbolAddress((void**)&pC, g_CTX);

    cudaFuncSetAttribute(attn_kernel,
                         cudaFuncAttributeMaxDynamicSharedMemorySize, AT_SMEM_BYTES);

    const dim3 gemm_grid(Ndim / 128, Mdim / 128);  // (4, 64)

    gemm_tf32_kernel<true><<<gemm_grid, 256>>>(query, Wq, bq, pQ);
    gemm_tf32_kernel<true><<<gemm_grid, 256>>>(key,   Wk, bk, pK);
    gemm_tf32_kernel<true><<<gemm_grid, 256>>>(value, Wv, bv, pV);

    attn_kernel<<<dim3(Tc/128, Hc, Bc), 256, AT_SMEM_BYTES>>>(pQ, pK, pV, amask, pC);

    gemm_tf32_kernel<false><<<gemm_grid, 256>>>(pC, Wo, bo, out);
}

// round 5
// speedup vs baseline: 5.6043x; 1.4407x over previous
#include <cuda_runtime.h>
#include <cuda_bf16.h>
#include <cuda_fp16.h>
#include <cstdint>

// Problem constants
#define Bc 4
#define Tc 2048
#define Fc 512
#define Hc 8
#define DKc 64
#define Mdim (Bc*Tc)   // 8192
#define Ndim Fc        // 512
#define Kdim Fc        // 512

// ---- tf32 helpers (projection GEMMs) ----
__device__ __forceinline__ uint32_t f2tf32(float x) {
    uint32_t r; asm("cvt.rna.tf32.f32 %0, %1;" : "=r"(r) : "f"(x)); return r;
}
__device__ __forceinline__ void mma_tf32(float* c,
                                         uint32_t a0, uint32_t a1, uint32_t a2, uint32_t a3,
                                         uint32_t b0, uint32_t b1) {
    asm volatile("mma.sync.aligned.m16n8k8.row.col.f32.tf32.tf32.f32 "
                 "{%0,%1,%2,%3}, {%4,%5,%6,%7}, {%8,%9}, {%0,%1,%2,%3};"
                 : "+f"(c[0]), "+f"(c[1]), "+f"(c[2]), "+f"(c[3])
                 : "r"(a0), "r"(a1), "r"(a2), "r"(a3), "r"(b0), "r"(b1));
}

// ---- fp16 mma (attention) ----
__device__ __forceinline__ void mma_f16(float* c,
                                        uint32_t a0, uint32_t a1, uint32_t a2, uint32_t a3,
                                        uint32_t b0, uint32_t b1) {
    asm volatile("mma.sync.aligned.m16n8k16.row.col.f32.f16.f16.f32 "
                 "{%0,%1,%2,%3}, {%4,%5,%6,%7}, {%8,%9}, {%0,%1,%2,%3};"
                 : "+f"(c[0]), "+f"(c[1]), "+f"(c[2]), "+f"(c[3])
                 : "r"(a0), "r"(a1), "r"(a2), "r"(a3), "r"(b0), "r"(b1));
}

__device__ __forceinline__ uint32_t smem_u32(const void* p) {
    return (uint32_t)__cvta_generic_to_shared(p);
}
__device__ __forceinline__ void cp_async16(uint32_t dst, const void* src) {
    asm volatile("cp.async.cg.shared.global [%0], [%1], 16;" :: "r"(dst), "l"(src));
}
__device__ __forceinline__ void cp_async4(uint32_t dst, const void* src) {
    asm volatile("cp.async.ca.shared.global [%0], [%1], 4;" :: "r"(dst), "l"(src));
}
__device__ __forceinline__ void cp_commit() {
    asm volatile("cp.async.commit_group;");
}

// Scratch: Q/K/V in fp16 (written by projection epilogues), CTX fp32
__device__ __half g_Qh[Bc*Hc*Tc*DKc];
__device__ __half g_Kh[Bc*Hc*Tc*DKc];
__device__ __half g_Vh[Bc*Hc*Tc*DKc];
__device__ float  g_CTX[Bc*Tc*Fc];

struct QKVPtrs {
    const float* A[3];
    const float* W[3];
    const float* bias[3];
    __half* C[3];
};

// ---------------------------------------------------------------------------
// Fused QKV projection GEMM (tf32 mma): C_z = A_z @ W_z^T + b_z, z=blockIdx.z.
// Output fp16, scattered to [B,H,T,DK]; z==0 (Q) additionally scaled by 1/8.
// CTA tile 128x128, BK=16, 8 warps (4m x 2n), warp m32 x n64, double-buffered.
// ---------------------------------------------------------------------------
#define GS 20   // smem row stride (uints)

__global__ __launch_bounds__(256, 2)
void gemm_qkv_kernel(QKVPtrs P)
{
    __shared__ uint32_t sA[2][128*GS];
    __shared__ uint32_t sW[2][128*GS];

    const int z = blockIdx.z;
    const float* A = P.A[z];
    const float* W = P.W[z];
    const float* bias = P.bias[z];
    __half* C = P.C[z];
    const float scale = (z == 0) ? 0.125f : 1.0f;

    const int tid  = threadIdx.x;
    const int lane = tid & 31;
    const int w    = tid >> 5;
    const int g    = lane >> 2;
    const int t    = lane & 3;
    const int wm   = w & 3;
    const int wn   = w >> 2;
    const int bm = blockIdx.y * 128;
    const int bn = blockIdx.x * 128;

    const int lrow = tid >> 2;
    const int lcol = (tid & 3) << 2;

    float acc[2][8][4];
    #pragma unroll
    for (int mt = 0; mt < 2; mt++)
        #pragma unroll
        for (int nt = 0; nt < 8; nt++)
            #pragma unroll
            for (int j = 0; j < 4; j++) acc[mt][nt][j] = 0.f;

    float4 ra[2], rw[2];
    #pragma unroll
    for (int it = 0; it < 2; it++) {
        const int row = lrow + it * 64;
        ra[it] = *(const float4*)(A + (size_t)(bm + row) * Kdim + lcol);
        rw[it] = *(const float4*)(W + (size_t)(bn + row) * Kdim + lcol);
    }
    #pragma unroll
    for (int it = 0; it < 2; it++) {
        const int row = lrow + it * 64;
        uint4 ua, uw;
        ua.x = f2tf32(ra[it].x); ua.y = f2tf32(ra[it].y); ua.z = f2tf32(ra[it].z); ua.w = f2tf32(ra[it].w);
        uw.x = f2tf32(rw[it].x); uw.y = f2tf32(rw[it].y); uw.z = f2tf32(rw[it].z); uw.w = f2tf32(rw[it].w);
        *(uint4*)&sA[0][row*GS + lcol] = ua;
        *(uint4*)&sW[0][row*GS + lcol] = uw;
    }
    __syncthreads();

    const int NIT = Kdim / 16;
    for (int i = 0; i < NIT; i++) {
        const int buf = i & 1;
        if (i + 1 < NIT) {
            const int k0 = (i + 1) * 16;
            #pragma unroll
            for (int it = 0; it < 2; it++) {
                const int row = lrow + it * 64;
                ra[it] = *(const float4*)(A + (size_t)(bm + row) * Kdim + k0 + lcol);
                rw[it] = *(const float4*)(W + (size_t)(bn + row) * Kdim + k0 + lcol);
            }
        }

        const uint32_t* Ab = sA[buf];
        const uint32_t* Wb = sW[buf];
        #pragma unroll
        for (int k8 = 0; k8 < 2; k8++) {
            uint32_t a[2][4];
            #pragma unroll
            for (int mt = 0; mt < 2; mt++) {
                const int r0 = wm*32 + mt*16;
                a[mt][0] = Ab[(r0+g  )*GS + k8*8 + t    ];
                a[mt][1] = Ab[(r0+g+8)*GS + k8*8 + t    ];
                a[mt][2] = Ab[(r0+g  )*GS + k8*8 + t + 4];
                a[mt][3] = Ab[(r0+g+8)*GS + k8*8 + t + 4];
            }
            #pragma unroll
            for (int nt = 0; nt < 8; nt++) {
                const int c0 = wn*64 + nt*8;
                const uint32_t b0 = Wb[(c0+g)*GS + k8*8 + t    ];
                const uint32_t b1 = Wb[(c0+g)*GS + k8*8 + t + 4];
                mma_tf32(acc[0][nt], a[0][0], a[0][1], a[0][2], a[0][3], b0, b1);
                mma_tf32(acc[1][nt], a[1][0], a[1][1], a[1][2], a[1][3], b0, b1);
            }
        }
        __syncthreads();
        if (i + 1 < NIT) {
            const int nb = buf ^ 1;
            #pragma unroll
            for (int it = 0; it < 2; it++) {
                const int row = lrow + it * 64;
                uint4 ua, uw;
                ua.x = f2tf32(ra[it].x); ua.y = f2tf32(ra[it].y); ua.z = f2tf32(ra[it].z); ua.w = f2tf32(ra[it].w);
                uw.x = f2tf32(rw[it].x); uw.y = f2tf32(rw[it].y); uw.z = f2tf32(rw[it].z); uw.w = f2tf32(rw[it].w);
                *(uint4*)&sA[nb][row*GS + lcol] = ua;
                *(uint4*)&sW[nb][row*GS + lcol] = uw;
            }
            __syncthreads();
        }
    }

    // Epilogue: bias, scale, fp16 convert, scatter to [B,H,T,DK]
    #pragma unroll
    for (int nt = 0; nt < 8; nt++) {
        const int col = bn + wn*64 + nt*8 + 2*t;
        const float2 bb = *(const float2*)(bias + col);
        const int h  = col >> 6;
        const int dk = col & 63;
        #pragma unroll
        for (int mt = 0; mt < 2; mt++) {
            const int row0 = bm + wm*32 + mt*16 + g;
            const int row1 = row0 + 8;
            float2 v0, v1;
            v0.x = (acc[mt][nt][0] + bb.x) * scale; v0.y = (acc[mt][nt][1] + bb.y) * scale;
            v1.x = (acc[mt][nt][2] + bb.x) * scale; v1.y = (acc[mt][nt][3] + bb.y) * scale;
            const int b0_ = row0 >> 11, t0_ = row0 & 2047;
            const int b1_ = row1 >> 11, t1_ = row1 & 2047;
            *(__half2*)(C + ((((size_t)b0_*Hc + h)*Tc + t0_) * DKc) + dk) = __float22half2_rn(v0);
            *(__half2*)(C + ((((size_t)b1_*Hc + h)*Tc + t1_) * DKc) + dk) = __float22half2_rn(v1);
        }
    }
}

// ---------------------------------------------------------------------------
// Output-projection GEMM (tf32): out = CTX @ Wo^T + bo, fp32 in/out.
// ---------------------------------------------------------------------------
__global__ __launch_bounds__(256, 2)
void gemm_o_kernel(const float* __restrict__ A, const float* __restrict__ W,
                   const float* __restrict__ bias, float* __restrict__ C)
{
    __shared__ uint32_t sA[2][128*GS];
    __shared__ uint32_t sW[2][128*GS];

    const int tid  = threadIdx.x;
    const int lane = tid & 31;
    const int w    = tid >> 5;
    const int g    = lane >> 2;
    const int t    = lane & 3;
    const int wm   = w & 3;
    const int wn   = w >> 2;
    const int bm = blockIdx.y * 128;
    const int bn = blockIdx.x * 128;

    const int lrow = tid >> 2;
    const int lcol = (tid & 3) << 2;

    float acc[2][8][4];
    #pragma unroll
    for (int mt = 0; mt < 2; mt++)
        #pragma unroll
        for (int nt = 0; nt < 8; nt++)
            #pragma unroll
            for (int j = 0; j < 4; j++) acc[mt][nt][j] = 0.f;

    float4 ra[2], rw[2];
    #pragma unroll
    for (int it = 0; it < 2; it++) {
        const int row = lrow + it * 64;
        ra[it] = *(const float4*)(A + (size_t)(bm + row) * Kdim + lcol);
        rw[it] = *(const float4*)(W + (size_t)(bn + row) * Kdim + lcol);
    }
    #pragma unroll
    for (int it = 0; it < 2; it++) {
        const int row = lrow + it * 64;
        uint4 ua, uw;
        ua.x = f2tf32(ra[it].x); ua.y = f2tf32(ra[it].y); ua.z = f2tf32(ra[it].z); ua.w = f2tf32(ra[it].w);
        uw.x = f2tf32(rw[it].x); uw.y = f2tf32(rw[it].y); uw.z = f2tf32(rw[it].z); uw.w = f2tf32(rw[it].w);
        *(uint4*)&sA[0][row*GS + lcol] = ua;
        *(uint4*)&sW[0][row*GS + lcol] = uw;
    }
    __syncthreads();

    const int NIT = Kdim / 16;
    for (int i = 0; i < NIT; i++) {
        const int buf = i & 1;
        if (i + 1 < NIT) {
            const int k0 = (i + 1) * 16;
            #pragma unroll
            for (int it = 0; it < 2; it++) {
                const int row = lrow + it * 64;
                ra[it] = *(const float4*)(A + (size_t)(bm + row) * Kdim + k0 + lcol);
                rw[it] = *(const float4*)(W + (size_t)(bn + row) * Kdim + k0 + lcol);
            }
        }
        const uint32_t* Ab = sA[buf];
        const uint32_t* Wb = sW[buf];
        #pragma unroll
        for (int k8 = 0; k8 < 2; k8++) {
            uint32_t a[2][4];
            #pragma unroll
            for (int mt = 0; mt < 2; mt++) {
                const int r0 = wm*32 + mt*16;
                a[mt][0] = Ab[(r0+g  )*GS + k8*8 + t    ];
                a[mt][1] = Ab[(r0+g+8)*GS + k8*8 + t    ];
                a[mt][2] = Ab[(r0+g  )*GS + k8*8 + t + 4];
                a[mt][3] = Ab[(r0+g+8)*GS + k8*8 + t + 4];
            }
            #pragma unroll
            for (int nt = 0; nt < 8; nt++) {
                const int c0 = wn*64 + nt*8;
                const uint32_t b0 = Wb[(c0+g)*GS + k8*8 + t    ];
                const uint32_t b1 = Wb[(c0+g)*GS + k8*8 + t + 4];
                mma_tf32(acc[0][nt], a[0][0], a[0][1], a[0][2], a[0][3], b0, b1);
                mma_tf32(acc[1][nt], a[1][0], a[1][1], a[1][2], a[1][3], b0, b1);
            }
        }
        __syncthreads();
        if (i + 1 < NIT) {
            const int nb = buf ^ 1;
            #pragma unroll
            for (int it = 0; it < 2; it++) {
                const int row = lrow + it * 64;
                uint4 ua, uw;
                ua.x = f2tf32(ra[it].x); ua.y = f2tf32(ra[it].y); ua.z = f2tf32(ra[it].z); ua.w = f2tf32(ra[it].w);
                uw.x = f2tf32(rw[it].x); uw.y = f2tf32(rw[it].y); uw.z = f2tf32(rw[it].z); uw.w = f2tf32(rw[it].w);
                *(uint4*)&sA[nb][row*GS + lcol] = ua;
                *(uint4*)&sW[nb][row*GS + lcol] = uw;
            }
            __syncthreads();
        }
    }

    #pragma unroll
    for (int nt = 0; nt < 8; nt++) {
        const int col = bn + wn*64 + nt*8 + 2*t;
        const float2 bb = *(const float2*)(bias + col);
        #pragma unroll
        for (int mt = 0; mt < 2; mt++) {
            const int row0 = bm + wm*32 + mt*16 + g;
            const int row1 = row0 + 8;
            float2 v0, v1;
            v0.x = acc[mt][nt][0] + bb.x; v0.y = acc[mt][nt][1] + bb.y;
            v1.x = acc[mt][nt][2] + bb.x; v1.y = acc[mt][nt][3] + bb.y;
            *(float2*)(C + (size_t)row0 * Ndim + col) = v0;
            *(float2*)(C + (size_t)row1 * Ndim + col) = v1;
        }
    }
}

// ---------------------------------------------------------------------------
// Flash attention, fp16 mma m16n8k16, cp.async double-buffered K/V.
// CTA: 256 thr = 8 warps; q-tile 128 rows (warp w: rows w*16..+15).
// 64-key chunks. QK: m16 x n64 x k64 (kt=4). PV: m16 x n64 x k64 (kt=4),
// V^T fragments via ldmatrix.x2.trans. Q pre-scaled by 1/8 in projection.
// ---------------------------------------------------------------------------
#define HS 72                      // halves per smem row (144 B, 16B-aligned)
#define HS2 (HS/2)                 // 36 u32 per row
#define SQ_OFF 0                   // halves
#define SK_OFF (128*HS)            // 9216
#define SV_OFF (SK_OFF + 2*64*HS)  // 18432
#define SP_OFF (SV_OFF + 2*64*HS)  // 27648
#define AT_HALVES (SP_OFF + 128*HS)
#define AT_SMEM_BYTES (AT_HALVES * 2)   // 73728

__global__ __launch_bounds__(256, 2)
void attn_kernel(const __half* __restrict__ Q, const __half* __restrict__ K,
                 const __half* __restrict__ V, const int* __restrict__ mask,
                 float* __restrict__ CTX)
{
    extern __shared__ __half hsm[];
    __half* sQ = hsm + SQ_OFF;              // [128][HS]
    __half* sK = hsm + SK_OFF;              // [2][64][HS]  ([key][dk])
    __half* sV = hsm + SV_OFF;              // [2][64][HS]  ([key][dk])
    __half* sP = hsm + SP_OFF;              // [128][HS]    ([row][key])
    __shared__ int smask[2][64];

    const uint32_t sQb = smem_u32(sQ);
    const uint32_t sKb = smem_u32(sK);
    const uint32_t sVb = smem_u32(sV);
    const uint32_t sMb = smem_u32(&smask[0][0]);

    const int tid  = threadIdx.x;
    const int lane = tid & 31;
    const int w    = tid >> 5;
    const int g    = lane >> 2;
    const int t    = lane & 3;
    const int r0   = w * 16;
    const int qt = blockIdx.x;
    const int h  = blockIdx.y;
    const int b  = blockIdx.z;

    const size_t head_base = (((size_t)b * Hc + h) * Tc) * DKc;
    const __half* Qb = Q + head_base + (size_t)qt * 128 * DKc;
    const __half* Kb = K + head_base;
    const __half* Vb = V + head_base;
    const int* Mb = mask + b * Tc;

    // Q tile via cp.async: 128 rows x 64 halves (128 B = 8 segs of 16 B)
    #pragma unroll
    for (int it = 0; it < 4; it++) {
        const int e = tid + it * 256;
        const int r = e >> 3, s = e & 7;
        cp_async16(sQb + (r*HS + s*8)*2, Qb + r*DKc + s*8);
    }

    // chunk loader: K/V 64x64 halves each (2x 16B per thread), + mask
    auto issue_chunk = [&](int kc) {
        const int buf = kc & 1;
        const __half* Kc = Kb + (size_t)kc * 64 * DKc;
        const __half* Vc = Vb + (size_t)kc * 64 * DKc;
        #pragma unroll
        for (int it = 0; it < 2; it++) {
            const int e = tid + it * 256;
            const int r = e >> 3, s = e & 7;
            cp_async16(sKb + ((buf*64 + r)*HS + s*8)*2, Kc + r*DKc + s*8);
            cp_async16(sVb + ((buf*64 + r)*HS + s*8)*2, Vc + r*DKc + s*8);
        }
        if (tid < 64) cp_async4(sMb + (buf*64 + tid)*4, Mb + kc*64 + tid);
    };

    issue_chunk(0);
    cp_commit();

    float of[8][4];
    float mi0 = -1e30f, mi1 = -1e30f, li0 = 0.f, li1 = 0.f;
    #pragma unroll
    for (int nt = 0; nt < 8; nt++)
        #pragma unroll
        for (int j = 0; j < 4; j++) of[nt][j] = 0.f;

    const uint32_t* sQ32 = (const uint32_t*)sQ;
    const uint32_t* sK32 = (const uint32_t*)sK;
    uint32_t* sP32 = (uint32_t*)sP;

    const int NC = Tc / 64;   // 32
    for (int kc = 0; kc < NC; kc++) {
        const int buf = kc & 1;
        if (kc + 1 < NC) { issue_chunk(kc + 1); cp_commit(); }
        if (kc + 1 < NC) asm volatile("cp.async.wait_group 1;");
        else             asm volatile("cp.async.wait_group 0;");
        __syncthreads();

        const uint32_t* Kbuf = sK32 + buf * 64 * HS2;
        const __half*   Vbuf = sV + buf * 64 * HS;
        const int*      mbuf = smask[buf];

        // ---- S = Q K^T : kt=4 (k16), nt=8 (n8) ----
        float sf[8][4];
        #pragma unroll
        for (int nt = 0; nt < 8; nt++)
            #pragma unroll
            for (int j = 0; j < 4; j++) sf[nt][j] = 0.f;

        #pragma unroll
        for (int kt = 0; kt < 4; kt++) {
            const uint32_t a0 = sQ32[(r0+g  )*HS2 + kt*8 + t    ];
            const uint32_t a1 = sQ32[(r0+g+8)*HS2 + kt*8 + t    ];
            const uint32_t a2 = sQ32[(r0+g  )*HS2 + kt*8 + t + 4];
            const uint32_t a3 = sQ32[(r0+g+8)*HS2 + kt*8 + t + 4];
            #pragma unroll
            for (int nt = 0; nt < 8; nt++) {
                const uint32_t b0 = Kbuf[(nt*8+g)*HS2 + kt*8 + t    ];
                const uint32_t b1 = Kbuf[(nt*8+g)*HS2 + kt*8 + t + 4];
                mma_f16(sf[nt], a0, a1, a2, a3, b0, b1);
            }
        }

        // ---- online softmax ----
        float mx0 = -1e30f, mx1 = -1e30f;
        int m0r[8], m1r[8];
        #pragma unroll
        for (int nt = 0; nt < 8; nt++) {
            m0r[nt] = mbuf[nt*8 + 2*t];
            m1r[nt] = mbuf[nt*8 + 2*t + 1];
            sf[nt][0] = m0r[nt] ? sf[nt][0] : -1e30f;
            sf[nt][1] = m1r[nt] ? sf[nt][1] : -1e30f;
            sf[nt][2] = m0r[nt] ? sf[nt][2] : -1e30f;
            sf[nt][3] = m1r[nt] ? sf[nt][3] : -1e30f;
            mx0 = fmaxf(mx0, fmaxf(sf[nt][0], sf[nt][1]));
            mx1 = fmaxf(mx1, fmaxf(sf[nt][2], sf[nt][3]));
        }
        mx0 = fmaxf(mx0, __shfl_xor_sync(0xffffffffu, mx0, 1));
        mx0 = fmaxf(mx0, __shfl_xor_sync(0xffffffffu, mx0, 2));
        mx1 = fmaxf(mx1, __shfl_xor_sync(0xffffffffu, mx1, 1));
        mx1 = fmaxf(mx1, __shfl_xor_sync(0xffffffffu, mx1, 2));

        const float mn0 = fmaxf(mi0, mx0);
        const float mn1 = fmaxf(mi1, mx1);
        const float al0 = __expf(mi0 - mn0);
        const float al1 = __expf(mi1 - mn1);
        mi0 = mn0; mi1 = mn1;

        float rs0 = 0.f, rs1 = 0.f;
        #pragma unroll
        for (int nt = 0; nt < 8; nt++) {
            const float p00 = m0r[nt] ? __expf(sf[nt][0] - mn0) : 0.f;
            const float p01 = m1r[nt] ? __expf(sf[nt][1] - mn0) : 0.f;
            const float p10 = m0r[nt] ? __expf(sf[nt][2] - mn1) : 0.f;
            const float p11 = m1r[nt] ? __expf(sf[nt][3] - mn1) : 0.f;
            rs0 += p00 + p01;
            rs1 += p10 + p11;
            __half2 h0 = __float22half2_rn(make_float2(p00, p01));
            __half2 h1 = __float22half2_rn(make_float2(p10, p11));
            sP32[(r0+g  )*HS2 + nt*4 + t] = *(uint32_t*)&h0;
            sP32[(r0+g+8)*HS2 + nt*4 + t] = *(uint32_t*)&h1;
        }
        rs0 += __shfl_xor_sync(0xffffffffu, rs0, 1);
        rs0 += __shfl_xor_sync(0xffffffffu, rs0, 2);
        rs1 += __shfl_xor_sync(0xffffffffu, rs1, 1);
        rs1 += __shfl_xor_sync(0xffffffffu, rs1, 2);
        li0 = li0 * al0 + rs0;
        li1 = li1 * al1 + rs1;

        #pragma unroll
        for (int nt = 0; nt < 8; nt++) {
            of[nt][0] *= al0; of[nt][1] *= al0;
            of[nt][2] *= al1; of[nt][3] *= al1;
        }

        __syncwarp();   // P rows are warp-private

        // ---- O += P @ V : kt=4 key 16-blocks, nt=8 dk 8-blocks ----
        #pragma unroll
        for (int kt = 0; kt < 4; kt++) {
            const uint32_t a0 = sP32[(r0+g  )*HS2 + kt*8 + t    ];
            const uint32_t a1 = sP32[(r0+g+8)*HS2 + kt*8 + t    ];
            const uint32_t a2 = sP32[(r0+g  )*HS2 + kt*8 + t + 4];
            const uint32_t a3 = sP32[(r0+g+8)*HS2 + kt*8 + t + 4];
            const uint32_t rowaddr = smem_u32(Vbuf + (kt*16 + (lane & 15))*HS);
            #pragma unroll
            for (int nt = 0; nt < 8; nt++) {
                uint32_t b0, b1;
                asm volatile("ldmatrix.sync.aligned.m8n8.x2.trans.shared.b16 {%0,%1}, [%2];"
                             : "=r"(b0), "=r"(b1) : "r"(rowaddr + nt*16));
                mma_f16(of[nt], a0, a1, a2, a3, b0, b1);
            }
        }
        __syncthreads();   // buf will be overwritten by issue at next iter
    }

    // Normalize and write context [B, T, F]
    const float inv0 = (li0 > 0.f) ? (1.0f / li0) : 0.f;
    const float inv1 = (li1 > 0.f) ? (1.0f / li1) : 0.f;
    const int t0 = qt*128 + r0 + g;
    const int t1 = t0 + 8;
    #pragma unroll
    for (int nt = 0; nt < 8; nt++) {
        const int dk = nt*8 + 2*t;
        float2 w0; w0.x = of[nt][0] * inv0; w0.y = of[nt][1] * inv0;
        float2 w1; w1.x = of[nt][2] * inv1; w1.y = of[nt][3] * inv1;
        *(float2*)(CTX + ((size_t)b * Tc + t0) * Fc + h*DKc + dk) = w0;
        *(float2*)(CTX + ((size_t)b * Tc + t1) * Fc + h*DKc + dk) = w1;
    }
}

// ---------------------------------------------------------------------------
// Launcher
// ---------------------------------------------------------------------------
extern "C" void kernel_launch(void* const* d_in, const int* in_sizes, int n_in,
                              void* d_out, int out_size)
{
    const float* query = (const float*)d_in[0];
    const float* key   = (const float*)d_in[1];
    const float* value = (const float*)d_in[2];
    const int*   amask = (const int*)  d_in[3];
    const float* Wq = (const float*)d_in[4];
    const float* bq = (const float*)d_in[5];
    const float* Wk = (const float*)d_in[6];
    const float* bk = (const float*)d_in[7];
    const float* Wv = (const float*)d_in[8];
    const float* bv = (const float*)d_in[9];
    const float* Wo = (const float*)d_in[10];
    const float* bo = (const float*)d_in[11];
    float* out = (float*)d_out;

    __half *pQ, *pK, *pV;
    float *pC;
    cudaGetSymbolAddress((void**)&pQ, g_Qh);
    cudaGetSymbolAddress((void**)&pK, g_Kh);
    cudaGetSymbolAddress((void**)&pV, g_Vh);
    cudaGetSymbolAddress((void**)&pC, g_CTX);

    cudaFuncSetAttribute(attn_kernel,
                         cudaFuncAttributeMaxDynamicSharedMemorySize, AT_SMEM_BYTES);

    QKVPtrs P;
    P.A[0] = query; P.A[1] = key; P.A[2] = value;
    P.W[0] = Wq;    P.W[1] = Wk;  P.W[2] = Wv;
    P.bias[0] = bq; P.bias[1] = bk; P.bias[2] = bv;
    P.C[0] = pQ;    P.C[1] = pK;  P.C[2] = pV;

    gemm_qkv_kernel<<<dim3(Ndim/128, Mdim/128, 3), 256>>>(P);

    attn_kernel<<<dim3(Tc/128, Hc, Bc), 256, AT_SMEM_BYTES>>>(pQ, pK, pV, amask, pC);

    gemm_o_kernel<<<dim3(Ndim/128, Mdim/128), 256>>>(pC, Wo, bo, out);
}

// round 6
// speedup vs baseline: 6.4959x; 1.1591x over previous
#include <cuda_runtime.h>
#include <cuda_bf16.h>
#include <cuda_fp16.h>
#include <cstdint>

// Problem constants
#define Bc 4
#define Tc 2048
#define Fc 512
#define Hc 8
#define DKc 64
#define Mdim (Bc*Tc)   // 8192
#define Ndim Fc        // 512
#define Kdim Fc        // 512

// ---- fp16 mma m16n8k16, fp32 accumulate ----
__device__ __forceinline__ void mma_f16(float* c,
                                        uint32_t a0, uint32_t a1, uint32_t a2, uint32_t a3,
                                        uint32_t b0, uint32_t b1) {
    asm volatile("mma.sync.aligned.m16n8k16.row.col.f32.f16.f16.f32 "
                 "{%0,%1,%2,%3}, {%4,%5,%6,%7}, {%8,%9}, {%0,%1,%2,%3};"
                 : "+f"(c[0]), "+f"(c[1]), "+f"(c[2]), "+f"(c[3])
                 : "r"(a0), "r"(a1), "r"(a2), "r"(a3), "r"(b0), "r"(b1));
}
__device__ __forceinline__ uint32_t smem_u32(const void* p) {
    return (uint32_t)__cvta_generic_to_shared(p);
}
__device__ __forceinline__ void cp_async16(uint32_t dst, const void* src) {
    asm volatile("cp.async.cg.shared.global [%0], [%1], 16;" :: "r"(dst), "l"(src));
}
__device__ __forceinline__ void cp_async4(uint32_t dst, const void* src) {
    asm volatile("cp.async.ca.shared.global [%0], [%1], 4;" :: "r"(dst), "l"(src));
}
__device__ __forceinline__ void cp_commit() {
    asm volatile("cp.async.commit_group;");
}
__device__ __forceinline__ void ldm_x4(uint32_t& r0, uint32_t& r1, uint32_t& r2, uint32_t& r3,
                                       uint32_t addr) {
    asm volatile("ldmatrix.sync.aligned.m8n8.x4.shared.b16 {%0,%1,%2,%3}, [%4];"
                 : "=r"(r0), "=r"(r1), "=r"(r2), "=r"(r3) : "r"(addr));
}
__device__ __forceinline__ void ldm_x2(uint32_t& r0, uint32_t& r1, uint32_t addr) {
    asm volatile("ldmatrix.sync.aligned.m8n8.x2.shared.b16 {%0,%1}, [%2];"
                 : "=r"(r0), "=r"(r1) : "r"(addr));
}

// Scratch (fp16 everywhere between stages)
__device__ __half g_Xh[3][(size_t)Mdim*Fc];   // converted inputs q,k,v
__device__ __half g_Wh[4][(size_t)Fc*Fc];     // converted Wq,Wk,Wv,Wo
__device__ __half g_Qh[(size_t)Bc*Hc*Tc*DKc];
__device__ __half g_Kh[(size_t)Bc*Hc*Tc*DKc];
__device__ __half g_Vh[(size_t)Bc*Hc*Tc*DKc];
__device__ __half g_CTXh[(size_t)Mdim*Fc];

// ---------------------------------------------------------------------------
// fp32 -> fp16 convert (blockIdx.y selects job)
// ---------------------------------------------------------------------------
struct CvtJobs { const float* src[4]; __half* dst[4]; };

__global__ __launch_bounds__(256)
void cvt_kernel(CvtJobs J)
{
    const float* s = J.src[blockIdx.y];
    __half* d = J.dst[blockIdx.y];
    const size_t i = ((size_t)blockIdx.x * 256 + threadIdx.x) * 4;
    float4 v = *(const float4*)(s + i);
    __half2 h0 = __float22half2_rn(make_float2(v.x, v.y));
    __half2 h1 = __float22half2_rn(make_float2(v.z, v.w));
    uint2 o; o.x = *(uint32_t*)&h0; o.y = *(uint32_t*)&h1;
    *(uint2*)(d + i) = o;
}

// ---------------------------------------------------------------------------
// fp16 tensor-core GEMM: C = A @ W^T + bias (A,W fp16; bias fp32).
// CTA 128x128, BK=32, 256 thr = 8 warps (4m x 2n), warp m32 x n64.
// cp.async double-buffered; ldmatrix operand loads.
// MODE 0: C fp32 row-major. MODE 1: C fp16 scatter to [B,H,T,DK], scale(z==0).
// ---------------------------------------------------------------------------
#define HAS 40   // halves per smem row (80 B): ldmatrix conflict-free

struct QKVJobs {
    const __half* A[3];
    const __half* W[3];
    const float* bias[3];
    __half* C[3];
};

template<int MODE>
__global__ __launch_bounds__(256, 2)
void gemm_h_kernel(QKVJobs P, const __half* Ao, const __half* Wo,
                   const float* biaso, float* Co)
{
    __shared__ __half sA[2][128*HAS];
    __shared__ __half sW[2][128*HAS];

    const int z = (MODE == 1) ? blockIdx.z : 0;
    const __half* A  = (MODE == 1) ? P.A[z] : Ao;
    const __half* W  = (MODE == 1) ? P.W[z] : Wo;
    const float* bias = (MODE == 1) ? P.bias[z] : biaso;
    const float scale = (MODE == 1 && z == 0) ? 0.125f : 1.0f;

    const int tid  = threadIdx.x;
    const int lane = tid & 31;
    const int w    = tid >> 5;
    const int g    = lane >> 2;
    const int t    = lane & 3;
    const int wm   = w & 3;
    const int wn   = w >> 2;
    const int bm = blockIdx.y * 128;
    const int bn = blockIdx.x * 128;

    const uint32_t sAb = smem_u32(sA);
    const uint32_t sWb = smem_u32(sW);

    // cp.async tile loader: 128 rows x 32 halves (4 segs of 16B) per matrix
    auto issue = [&](int i) {
        const int buf = i & 1;
        const int k0 = i * 32;
        #pragma unroll
        for (int it = 0; it < 2; it++) {
            const int e = tid + it * 256;
            const int r = e >> 2, s = e & 3;
            cp_async16(sAb + ((buf*128 + r)*HAS + s*8)*2,
                       A + (size_t)(bm + r) * Kdim + k0 + s*8);
            cp_async16(sWb + ((buf*128 + r)*HAS + s*8)*2,
                       W + (size_t)(bn + r) * Kdim + k0 + s*8);
        }
    };

    float acc[2][8][4];
    #pragma unroll
    for (int mt = 0; mt < 2; mt++)
        #pragma unroll
        for (int nt = 0; nt < 8; nt++)
            #pragma unroll
            for (int j = 0; j < 4; j++) acc[mt][nt][j] = 0.f;

    issue(0);
    cp_commit();

    const int NIT = Kdim / 32;   // 16
    for (int i = 0; i < NIT; i++) {
        const int buf = i & 1;
        if (i + 1 < NIT) { issue(i + 1); cp_commit(); }
        if (i + 1 < NIT) asm volatile("cp.async.wait_group 1;");
        else             asm volatile("cp.async.wait_group 0;");
        __syncthreads();

        const uint32_t Ab = sAb + (buf*128*HAS)*2;
        const uint32_t Wb = sWb + (buf*128*HAS)*2;

        #pragma unroll
        for (int kt = 0; kt < 2; kt++) {
            uint32_t a[2][4];
            #pragma unroll
            for (int mt = 0; mt < 2; mt++) {
                const int row = wm*32 + mt*16 + (lane & 15);
                const int col = kt*16 + (lane >> 4) * 8;
                ldm_x4(a[mt][0], a[mt][1], a[mt][2], a[mt][3],
                       Ab + (row*HAS + col)*2);
            }
            #pragma unroll
            for (int nt = 0; nt < 8; nt++) {
                const int row = wn*64 + nt*8 + (lane & 7);
                const int col = kt*16 + ((lane >> 3) & 1) * 8;
                uint32_t b0, b1;
                ldm_x2(b0, b1, Wb + (row*HAS + col)*2);
                mma_f16(acc[0][nt], a[0][0], a[0][1], a[0][2], a[0][3], b0, b1);
                mma_f16(acc[1][nt], a[1][0], a[1][1], a[1][2], a[1][3], b0, b1);
            }
        }
        __syncthreads();   // all reads of buf done before issue(i+2) overwrites
    }

    // Epilogue
    #pragma unroll
    for (int nt = 0; nt < 8; nt++) {
        const int col = bn + wn*64 + nt*8 + 2*t;
        const float2 bb = *(const float2*)(bias + col);
        #pragma unroll
        for (int mt = 0; mt < 2; mt++) {
            const int row0 = bm + wm*32 + mt*16 + g;
            const int row1 = row0 + 8;
            float2 v0, v1;
            v0.x = (acc[mt][nt][0] + bb.x) * scale; v0.y = (acc[mt][nt][1] + bb.y) * scale;
            v1.x = (acc[mt][nt][2] + bb.x) * scale; v1.y = (acc[mt][nt][3] + bb.y) * scale;
            if (MODE == 0) {
                *(float2*)(Co + (size_t)row0 * Ndim + col) = v0;
                *(float2*)(Co + (size_t)row1 * Ndim + col) = v1;
            } else {
                const int h  = col >> 6;
                const int dk = col & 63;
                const int b0_ = row0 >> 11, t0_ = row0 & 2047;
                const int b1_ = row1 >> 11, t1_ = row1 & 2047;
                __half2 h0 = __float22half2_rn(v0);
                __half2 h1 = __float22half2_rn(v1);
                *(__half2*)(P.C[z] + ((((size_t)b0_*Hc + h)*Tc + t0_) * DKc) + dk) = h0;
                *(__half2*)(P.C[z] + ((((size_t)b1_*Hc + h)*Tc + t1_) * DKc) + dk) = h1;
            }
        }
    }
}

// ---------------------------------------------------------------------------
// Flash attention, fp16 mma m16n8k16, cp.async double-buffered K/V.
// CTA: 256 thr = 8 warps; q-tile 128 rows (warp w: rows w*16..+15).
// 64-key chunks. Q pre-scaled by 1/8 in projection. CTX written fp16.
// ---------------------------------------------------------------------------
#define HS 72                      // halves per smem row
#define HS2 (HS/2)
#define SQ_OFF 0
#define SK_OFF (128*HS)
#define SV_OFF (SK_OFF + 2*64*HS)
#define SP_OFF (SV_OFF + 2*64*HS)
#define AT_HALVES (SP_OFF + 128*HS)
#define AT_SMEM_BYTES (AT_HALVES * 2)   // 73728

__global__ __launch_bounds__(256, 2)
void attn_kernel(const __half* __restrict__ Q, const __half* __restrict__ K,
                 const __half* __restrict__ V, const int* __restrict__ mask,
                 __half* __restrict__ CTX)
{
    extern __shared__ __half hsm[];
    __half* sQ = hsm + SQ_OFF;
    __half* sK = hsm + SK_OFF;
    __half* sV = hsm + SV_OFF;
    __half* sP = hsm + SP_OFF;
    __shared__ int smask[2][64];

    const uint32_t sQb = smem_u32(sQ);
    const uint32_t sKb = smem_u32(sK);
    const uint32_t sVb = smem_u32(sV);
    const uint32_t sMb = smem_u32(&smask[0][0]);

    const int tid  = threadIdx.x;
    const int lane = tid & 31;
    const int w    = tid >> 5;
    const int g    = lane >> 2;
    const int t    = lane & 3;
    const int r0   = w * 16;
    const int qt = blockIdx.x;
    const int h  = blockIdx.y;
    const int b  = blockIdx.z;

    const size_t head_base = (((size_t)b * Hc + h) * Tc) * DKc;
    const __half* Qb = Q + head_base + (size_t)qt * 128 * DKc;
    const __half* Kb = K + head_base;
    const __half* Vb = V + head_base;
    const int* Mb = mask + b * Tc;

    #pragma unroll
    for (int it = 0; it < 4; it++) {
        const int e = tid + it * 256;
        const int r = e >> 3, s = e & 7;
        cp_async16(sQb + (r*HS + s*8)*2, Qb + r*DKc + s*8);
    }

    auto issue_chunk = [&](int kc) {
        const int buf = kc & 1;
        const __half* Kc = Kb + (size_t)kc * 64 * DKc;
        const __half* Vc = Vb + (size_t)kc * 64 * DKc;
        #pragma unroll
        for (int it = 0; it < 2; it++) {
            const int e = tid + it * 256;
            const int r = e >> 3, s = e & 7;
            cp_async16(sKb + ((buf*64 + r)*HS + s*8)*2, Kc + r*DKc + s*8);
            cp_async16(sVb + ((buf*64 + r)*HS + s*8)*2, Vc + r*DKc + s*8);
        }
        if (tid < 64) cp_async4(sMb + (buf*64 + tid)*4, Mb + kc*64 + tid);
    };

    issue_chunk(0);
    cp_commit();

    float of[8][4];
    float mi0 = -1e30f, mi1 = -1e30f, li0 = 0.f, li1 = 0.f;
    #pragma unroll
    for (int nt = 0; nt < 8; nt++)
        #pragma unroll
        for (int j = 0; j < 4; j++) of[nt][j] = 0.f;

    const uint32_t* sQ32 = (const uint32_t*)sQ;
    const uint32_t* sK32 = (const uint32_t*)sK;
    uint32_t* sP32 = (uint32_t*)sP;

    const int NC = Tc / 64;
    for (int kc = 0; kc < NC; kc++) {
        const int buf = kc & 1;
        if (kc + 1 < NC) { issue_chunk(kc + 1); cp_commit(); }
        if (kc + 1 < NC) asm volatile("cp.async.wait_group 1;");
        else             asm volatile("cp.async.wait_group 0;");
        __syncthreads();

        const uint32_t* Kbuf = sK32 + buf * 64 * HS2;
        const __half*   Vbuf = sV + buf * 64 * HS;
        const int*      mbuf = smask[buf];

        float sf[8][4];
        #pragma unroll
        for (int nt = 0; nt < 8; nt++)
            #pragma unroll
            for (int j = 0; j < 4; j++) sf[nt][j] = 0.f;

        #pragma unroll
        for (int kt = 0; kt < 4; kt++) {
            const uint32_t a0 = sQ32[(r0+g  )*HS2 + kt*8 + t    ];
            const uint32_t a1 = sQ32[(r0+g+8)*HS2 + kt*8 + t    ];
            const uint32_t a2 = sQ32[(r0+g  )*HS2 + kt*8 + t + 4];
            const uint32_t a3 = sQ32[(r0+g+8)*HS2 + kt*8 + t + 4];
            #pragma unroll
            for (int nt = 0; nt < 8; nt++) {
                const uint32_t b0 = Kbuf[(nt*8+g)*HS2 + kt*8 + t    ];
                const uint32_t b1 = Kbuf[(nt*8+g)*HS2 + kt*8 + t + 4];
                mma_f16(sf[nt], a0, a1, a2, a3, b0, b1);
            }
        }

        float mx0 = -1e30f, mx1 = -1e30f;
        int m0r[8], m1r[8];
        #pragma unroll
        for (int nt = 0; nt < 8; nt++) {
            m0r[nt] = mbuf[nt*8 + 2*t];
            m1r[nt] = mbuf[nt*8 + 2*t + 1];
            sf[nt][0] = m0r[nt] ? sf[nt][0] : -1e30f;
            sf[nt][1] = m1r[nt] ? sf[nt][1] : -1e30f;
            sf[nt][2] = m0r[nt] ? sf[nt][2] : -1e30f;
            sf[nt][3] = m1r[nt] ? sf[nt][3] : -1e30f;
            mx0 = fmaxf(mx0, fmaxf(sf[nt][0], sf[nt][1]));
            mx1 = fmaxf(mx1, fmaxf(sf[nt][2], sf[nt][3]));
        }
        mx0 = fmaxf(mx0, __shfl_xor_sync(0xffffffffu, mx0, 1));
        mx0 = fmaxf(mx0, __shfl_xor_sync(0xffffffffu, mx0, 2));
        mx1 = fmaxf(mx1, __shfl_xor_sync(0xffffffffu, mx1, 1));
        mx1 = fmaxf(mx1, __shfl_xor_sync(0xffffffffu, mx1, 2));

        const float mn0 = fmaxf(mi0, mx0);
        const float mn1 = fmaxf(mi1, mx1);
        const float al0 = __expf(mi0 - mn0);
        const float al1 = __expf(mi1 - mn1);
        mi0 = mn0; mi1 = mn1;

        float rs0 = 0.f, rs1 = 0.f;
        #pragma unroll
        for (int nt = 0; nt < 8; nt++) {
            const float p00 = m0r[nt] ? __expf(sf[nt][0] - mn0) : 0.f;
            const float p01 = m1r[nt] ? __expf(sf[nt][1] - mn0) : 0.f;
            const float p10 = m0r[nt] ? __expf(sf[nt][2] - mn1) : 0.f;
            const float p11 = m1r[nt] ? __expf(sf[nt][3] - mn1) : 0.f;
            rs0 += p00 + p01;
            rs1 += p10 + p11;
            __half2 h0 = __float22half2_rn(make_float2(p00, p01));
            __half2 h1 = __float22half2_rn(make_float2(p10, p11));
            sP32[(r0+g  )*HS2 + nt*4 + t] = *(uint32_t*)&h0;
            sP32[(r0+g+8)*HS2 + nt*4 + t] = *(uint32_t*)&h1;
        }
        rs0 += __shfl_xor_sync(0xffffffffu, rs0, 1);
        rs0 += __shfl_xor_sync(0xffffffffu, rs0, 2);
        rs1 += __shfl_xor_sync(0xffffffffu, rs1, 1);
        rs1 += __shfl_xor_sync(0xffffffffu, rs1, 2);
        li0 = li0 * al0 + rs0;
        li1 = li1 * al1 + rs1;

        #pragma unroll
        for (int nt = 0; nt < 8; nt++) {
            of[nt][0] *= al0; of[nt][1] *= al0;
            of[nt][2] *= al1; of[nt][3] *= al1;
        }

        __syncwarp();

        #pragma unroll
        for (int kt = 0; kt < 4; kt++) {
            const uint32_t a0 = sP32[(r0+g  )*HS2 + kt*8 + t    ];
            const uint32_t a1 = sP32[(r0+g+8)*HS2 + kt*8 + t    ];
            const uint32_t a2 = sP32[(r0+g  )*HS2 + kt*8 + t + 4];
            const uint32_t a3 = sP32[(r0+g+8)*HS2 + kt*8 + t + 4];
            const uint32_t rowaddr = smem_u32(Vbuf + (kt*16 + (lane & 15))*HS);
            #pragma unroll
            for (int nt = 0; nt < 8; nt++) {
                uint32_t b0, b1;
                asm volatile("ldmatrix.sync.aligned.m8n8.x2.trans.shared.b16 {%0,%1}, [%2];"
                             : "=r"(b0), "=r"(b1) : "r"(rowaddr + nt*16));
                mma_f16(of[nt], a0, a1, a2, a3, b0, b1);
            }
        }
        __syncthreads();
    }

    // Normalize and write context [B, T, F] in fp16
    const float inv0 = (li0 > 0.f) ? (1.0f / li0) : 0.f;
    const float inv1 = (li1 > 0.f) ? (1.0f / li1) : 0.f;
    const int t0 = qt*128 + r0 + g;
    const int t1 = t0 + 8;
    #pragma unroll
    for (int nt = 0; nt < 8; nt++) {
        const int dk = nt*8 + 2*t;
        __half2 w0 = __float22half2_rn(make_float2(of[nt][0] * inv0, of[nt][1] * inv0));
        __half2 w1 = __float22half2_rn(make_float2(of[nt][2] * inv1, of[nt][3] * inv1));
        *(__half2*)(CTX + ((size_t)b * Tc + t0) * Fc + h*DKc + dk) = w0;
        *(__half2*)(CTX + ((size_t)b * Tc + t1) * Fc + h*DKc + dk) = w1;
    }
}

// ---------------------------------------------------------------------------
// Launcher
// ---------------------------------------------------------------------------
extern "C" void kernel_launch(void* const* d_in, const int* in_sizes, int n_in,
                              void* d_out, int out_size)
{
    const float* query = (const float*)d_in[0];
    const float* key   = (const float*)d_in[1];
    const float* value = (const float*)d_in[2];
    const int*   amask = (const int*)  d_in[3];
    const float* Wq = (const float*)d_in[4];
    const float* bq = (const float*)d_in[5];
    const float* Wk = (const float*)d_in[6];
    const float* bk = (const float*)d_in[7];
    const float* Wv = (const float*)d_in[8];
    const float* bv = (const float*)d_in[9];
    const float* Wo = (const float*)d_in[10];
    const float* bo = (const float*)d_in[11];
    float* out = (float*)d_out;

    __half *pXh, *pWh, *pQ, *pK, *pV, *pCTX;
    cudaGetSymbolAddress((void**)&pXh, g_Xh);
    cudaGetSymbolAddress((void**)&pWh, g_Wh);
    cudaGetSymbolAddress((void**)&pQ,  g_Qh);
    cudaGetSymbolAddress((void**)&pK,  g_Kh);
    cudaGetSymbolAddress((void**)&pV,  g_Vh);
    cudaGetSymbolAddress((void**)&pCTX, g_CTXh);

    __half* xh[3] = { pXh, pXh + (size_t)Mdim*Fc, pXh + 2*(size_t)Mdim*Fc };
    __half* wh[4] = { pWh, pWh + (size_t)Fc*Fc, pWh + 2*(size_t)Fc*Fc, pWh + 3*(size_t)Fc*Fc };

    cudaFuncSetAttribute(attn_kernel,
                         cudaFuncAttributeMaxDynamicSharedMemorySize, AT_SMEM_BYTES);

    // 1) convert inputs + weights to fp16
    CvtJobs JI;
    JI.src[0] = query; JI.src[1] = key; JI.src[2] = value; JI.src[3] = query;
    JI.dst[0] = xh[0]; JI.dst[1] = xh[1]; JI.dst[2] = xh[2]; JI.dst[3] = xh[0];
    cvt_kernel<<<dim3((Mdim*Fc)/(256*4), 3), 256>>>(JI);

    CvtJobs JW;
    JW.src[0] = Wq; JW.src[1] = Wk; JW.src[2] = Wv; JW.src[3] = Wo;
    JW.dst[0] = wh[0]; JW.dst[1] = wh[1]; JW.dst[2] = wh[2]; JW.dst[3] = wh[3];
    cvt_kernel<<<dim3((Fc*Fc)/(256*4), 4), 256>>>(JW);

    // 2) fused QKV projections (fp16 mma), scatter fp16 [B,H,T,DK]
    QKVJobs P;
    P.A[0] = xh[0]; P.A[1] = xh[1]; P.A[2] = xh[2];
    P.W[0] = wh[0]; P.W[1] = wh[1]; P.W[2] = wh[2];
    P.bias[0] = bq; P.bias[1] = bk; P.bias[2] = bv;
    P.C[0] = pQ;    P.C[1] = pK;   P.C[2] = pV;
    gemm_h_kernel<1><<<dim3(Ndim/128, Mdim/128, 3), 256>>>(P, nullptr, nullptr, nullptr, nullptr);

    // 3) attention (fp16 mma), CTX fp16
    attn_kernel<<<dim3(Tc/128, Hc, Bc), 256, AT_SMEM_BYTES>>>(pQ, pK, pV, amask, pCTX);

    // 4) output projection (fp16 mma), fp32 out
    QKVJobs PD = {};
    gemm_h_kernel<0><<<dim3(Ndim/128, Mdim/128), 256>>>(PD, pCTX, wh[3], bo, out);
}

// round 7
// speedup vs baseline: 7.3927x; 1.1381x over previous
#include <cuda_runtime.h>
#include <cuda_bf16.h>
#include <cuda_fp16.h>
#include <cstdint>

// Problem constants
#define Bc 4
#define Tc 2048
#define Fc 512
#define Hc 8
#define DKc 64
#define Mdim (Bc*Tc)   // 8192
#define Ndim Fc        // 512
#define Kdim Fc        // 512

#define LOG2E 1.44269504088896340736f

// ---- fp16 mma m16n8k16, fp32 accumulate ----
__device__ __forceinline__ void mma_f16(float* c,
                                        uint32_t a0, uint32_t a1, uint32_t a2, uint32_t a3,
                                        uint32_t b0, uint32_t b1) {
    asm volatile("mma.sync.aligned.m16n8k16.row.col.f32.f16.f16.f32 "
                 "{%0,%1,%2,%3}, {%4,%5,%6,%7}, {%8,%9}, {%0,%1,%2,%3};"
                 : "+f"(c[0]), "+f"(c[1]), "+f"(c[2]), "+f"(c[3])
                 : "r"(a0), "r"(a1), "r"(a2), "r"(a3), "r"(b0), "r"(b1));
}
__device__ __forceinline__ uint32_t smem_u32(const void* p) {
    return (uint32_t)__cvta_generic_to_shared(p);
}
__device__ __forceinline__ void cp_async16(uint32_t dst, const void* src) {
    asm volatile("cp.async.cg.shared.global [%0], [%1], 16;" :: "r"(dst), "l"(src));
}
__device__ __forceinline__ void cp_commit() {
    asm volatile("cp.async.commit_group;");
}
__device__ __forceinline__ void ldm_x4(uint32_t& r0, uint32_t& r1, uint32_t& r2, uint32_t& r3,
                                       uint32_t addr) {
    asm volatile("ldmatrix.sync.aligned.m8n8.x4.shared.b16 {%0,%1,%2,%3}, [%4];"
                 : "=r"(r0), "=r"(r1), "=r"(r2), "=r"(r3) : "r"(addr));
}
__device__ __forceinline__ void ldm_x4t(uint32_t& r0, uint32_t& r1, uint32_t& r2, uint32_t& r3,
                                        uint32_t addr) {
    asm volatile("ldmatrix.sync.aligned.m8n8.x4.trans.shared.b16 {%0,%1,%2,%3}, [%4];"
                 : "=r"(r0), "=r"(r1), "=r"(r2), "=r"(r3) : "r"(addr));
}
__device__ __forceinline__ void ldm_x2(uint32_t& r0, uint32_t& r1, uint32_t addr) {
    asm volatile("ldmatrix.sync.aligned.m8n8.x2.shared.b16 {%0,%1}, [%2];"
                 : "=r"(r0), "=r"(r1) : "r"(addr));
}
__device__ __forceinline__ float ex2(float x) {
    float y; asm("ex2.approx.f32 %0, %1;" : "=f"(y) : "f"(x)); return y;
}

// Scratch
__device__ __half g_Xh[3][(size_t)Mdim*Fc];
__device__ __half g_Wh[4][(size_t)Fc*Fc];
__device__ __half g_Qh[(size_t)Bc*Hc*Tc*DKc];
__device__ __half g_Kh[(size_t)Bc*Hc*Tc*DKc];
__device__ __half g_Vh[(size_t)Bc*Hc*Tc*DKc];
__device__ __half g_CTXh[(size_t)Mdim*Fc];
__device__ float  g_MB[(size_t)Bc*Tc];        // mask bias: 0 or -1e30

// ---------------------------------------------------------------------------
// fp32 -> fp16 convert (blockIdx.y selects job)
// ---------------------------------------------------------------------------
struct CvtJobs { const float* src[4]; __half* dst[4]; };

__global__ __launch_bounds__(256)
void cvt_kernel(CvtJobs J)
{
    const float* s = J.src[blockIdx.y];
    __half* d = J.dst[blockIdx.y];
    const size_t i = ((size_t)blockIdx.x * 256 + threadIdx.x) * 4;
    float4 v = *(const float4*)(s + i);
    __half2 h0 = __float22half2_rn(make_float2(v.x, v.y));
    __half2 h1 = __float22half2_rn(make_float2(v.z, v.w));
    uint2 o; o.x = *(uint32_t*)&h0; o.y = *(uint32_t*)&h1;
    *(uint2*)(d + i) = o;
}

__global__ __launch_bounds__(256)
void maskbias_kernel(const int* __restrict__ m, float* __restrict__ mb)
{
    const int i = blockIdx.x * 256 + threadIdx.x;
    mb[i] = m[i] ? 0.f : -1e30f;
}

// ---------------------------------------------------------------------------
// fp16 tensor-core GEMM (as R5, validated): C = A @ W^T + bias.
// MODE 0: C fp32 row-major. MODE 1: C fp16 scatter to [B,H,T,DK], scale(z==0).
// ---------------------------------------------------------------------------
#define HAS 40

struct QKVJobs {
    const __half* A[3];
    const __half* W[3];
    const float* bias[3];
    __half* C[3];
};

template<int MODE>
__global__ __launch_bounds__(256, 2)
void gemm_h_kernel(QKVJobs P, const __half* Ao, const __half* Wo,
                   const float* biaso, float* Co)
{
    __shared__ __half sA[2][128*HAS];
    __shared__ __half sW[2][128*HAS];

    const int z = (MODE == 1) ? blockIdx.z : 0;
    const __half* A  = (MODE == 1) ? P.A[z] : Ao;
    const __half* W  = (MODE == 1) ? P.W[z] : Wo;
    const float* bias = (MODE == 1) ? P.bias[z] : biaso;
    const float scale = (MODE == 1 && z == 0) ? 0.125f * LOG2E : 1.0f;

    const int tid  = threadIdx.x;
    const int lane = tid & 31;
    const int w    = tid >> 5;
    const int g    = lane >> 2;
    const int t    = lane & 3;
    const int wm   = w & 3;
    const int wn   = w >> 2;
    const int bm = blockIdx.y * 128;
    const int bn = blockIdx.x * 128;

    const uint32_t sAb = smem_u32(sA);
    const uint32_t sWb = smem_u32(sW);

    auto issue = [&](int i) {
        const int buf = i & 1;
        const int k0 = i * 32;
        #pragma unroll
        for (int it = 0; it < 2; it++) {
            const int e = tid + it * 256;
            const int r = e >> 2, s = e & 3;
            cp_async16(sAb + ((buf*128 + r)*HAS + s*8)*2,
                       A + (size_t)(bm + r) * Kdim + k0 + s*8);
            cp_async16(sWb + ((buf*128 + r)*HAS + s*8)*2,
                       W + (size_t)(bn + r) * Kdim + k0 + s*8);
        }
    };

    float acc[2][8][4];
    #pragma unroll
    for (int mt = 0; mt < 2; mt++)
        #pragma unroll
        for (int nt = 0; nt < 8; nt++)
            #pragma unroll
            for (int j = 0; j < 4; j++) acc[mt][nt][j] = 0.f;

    issue(0);
    cp_commit();

    const int NIT = Kdim / 32;
    for (int i = 0; i < NIT; i++) {
        const int buf = i & 1;
        if (i + 1 < NIT) { issue(i + 1); cp_commit(); }
        if (i + 1 < NIT) asm volatile("cp.async.wait_group 1;");
        else             asm volatile("cp.async.wait_group 0;");
        __syncthreads();

        const uint32_t Ab = sAb + (buf*128*HAS)*2;
        const uint32_t Wb = sWb + (buf*128*HAS)*2;

        #pragma unroll
        for (int kt = 0; kt < 2; kt++) {
            uint32_t a[2][4];
            #pragma unroll
            for (int mt = 0; mt < 2; mt++) {
                const int row = wm*32 + mt*16 + (lane & 15);
                const int col = kt*16 + (lane >> 4) * 8;
                ldm_x4(a[mt][0], a[mt][1], a[mt][2], a[mt][3],
                       Ab + (row*HAS + col)*2);
            }
            #pragma unroll
            for (int nt = 0; nt < 8; nt++) {
                const int row = wn*64 + nt*8 + (lane & 7);
                const int col = kt*16 + ((lane >> 3) & 1) * 8;
                uint32_t b0, b1;
                ldm_x2(b0, b1, Wb + (row*HAS + col)*2);
                mma_f16(acc[0][nt], a[0][0], a[0][1], a[0][2], a[0][3], b0, b1);
                mma_f16(acc[1][nt], a[1][0], a[1][1], a[1][2], a[1][3], b0, b1);
            }
        }
        __syncthreads();
    }

    #pragma unroll
    for (int nt = 0; nt < 8; nt++) {
        const int col = bn + wn*64 + nt*8 + 2*t;
        const float2 bb = *(const float2*)(bias + col);
        #pragma unroll
        for (int mt = 0; mt < 2; mt++) {
            const int row0 = bm + wm*32 + mt*16 + g;
            const int row1 = row0 + 8;
            float2 v0, v1;
            v0.x = (acc[mt][nt][0] + bb.x) * scale; v0.y = (acc[mt][nt][1] + bb.y) * scale;
            v1.x = (acc[mt][nt][2] + bb.x) * scale; v1.y = (acc[mt][nt][3] + bb.y) * scale;
            if (MODE == 0) {
                *(float2*)(Co + (size_t)row0 * Ndim + col) = v0;
                *(float2*)(Co + (size_t)row1 * Ndim + col) = v1;
            } else {
                const int h  = col >> 6;
                const int dk = col & 63;
                const int b0_ = row0 >> 11, t0_ = row0 & 2047;
                const int b1_ = row1 >> 11, t1_ = row1 & 2047;
                __half2 h0 = __float22half2_rn(v0);
                __half2 h1 = __float22half2_rn(v1);
                *(__half2*)(P.C[z] + ((((size_t)b0_*Hc + h)*Tc + t0_) * DKc) + dk) = h0;
                *(__half2*)(P.C[z] + ((((size_t)b1_*Hc + h)*Tc + t1_) * DKc) + dk) = h1;
            }
        }
    }
}

// ---------------------------------------------------------------------------
// Flash attention, fp16 mma, ldmatrix operands, additive mask bias, exp2 domain.
// Q pre-scaled by 0.125*log2e in projection. CTX fp16.
// ---------------------------------------------------------------------------
#define HS 72
#define HS2 (HS/2)
#define SQ_OFF 0
#define SK_OFF (128*HS)
#define SV_OFF (SK_OFF + 2*64*HS)
#define SP_OFF (SV_OFF + 2*64*HS)
#define AT_HALVES (SP_OFF + 128*HS)
#define AT_SMEM_BYTES (AT_HALVES * 2)   // 73728

__global__ __launch_bounds__(256, 2)
void attn_kernel(const __half* __restrict__ Q, const __half* __restrict__ K,
                 const __half* __restrict__ V, const float* __restrict__ maskb,
                 __half* __restrict__ CTX)
{
    extern __shared__ __half hsm[];
    __half* sQ = hsm + SQ_OFF;
    __half* sK = hsm + SK_OFF;
    __half* sV = hsm + SV_OFF;
    __half* sP = hsm + SP_OFF;
    __shared__ float sMB[2][64];

    const uint32_t sQb = smem_u32(sQ);
    const uint32_t sKb = smem_u32(sK);
    const uint32_t sVb = smem_u32(sV);
    const uint32_t sPb = smem_u32(sP);
    const uint32_t sMBb = smem_u32(&sMB[0][0]);

    const int tid  = threadIdx.x;
    const int lane = tid & 31;
    const int w    = tid >> 5;
    const int g    = lane >> 2;
    const int t    = lane & 3;
    const int r0   = w * 16;
    const int qt = blockIdx.x;
    const int h  = blockIdx.y;
    const int b  = blockIdx.z;

    const size_t head_base = (((size_t)b * Hc + h) * Tc) * DKc;
    const __half* Qb = Q + head_base + (size_t)qt * 128 * DKc;
    const __half* Kb = K + head_base;
    const __half* Vb = V + head_base;
    const float* MBp = maskb + b * Tc;

    // ldmatrix source addresses (bytes)
    const int l15 = lane & 15;
    const int lhi = lane >> 4;          // 0/1
    const int l7  = lane & 7;
    const int lb8 = (lane >> 3) & 1;    // 0/1
    // A-frag rows (sQ / sP): row = r0 + l15, col-half = lhi*8
    const uint32_t aQaddr = sQb + ((r0 + l15)*HS + lhi*8)*2;
    const uint32_t aPaddr = sPb + ((r0 + l15)*HS + lhi*8)*2;
    // K B-frag (pair of n-tiles): row = nt*8 + l7 + lhi*8, col-half = lb8*8
    const uint32_t bKoff = ((l7 + lhi*8)*HS + lb8*8)*2;
    // V B-frag trans (pair of n-tiles): row = kt*16 + l15, col = nt*8 + lhi*8
    const uint32_t bVoff = (l15*HS + lhi*8)*2;

    #pragma unroll
    for (int it = 0; it < 4; it++) {
        const int e = tid + it * 256;
        const int r = e >> 3, s = e & 7;
        cp_async16(sQb + (r*HS + s*8)*2, Qb + r*DKc + s*8);
    }

    auto issue_chunk = [&](int kc) {
        const int buf = kc & 1;
        const __half* Kc = Kb + (size_t)kc * 64 * DKc;
        const __half* Vc = Vb + (size_t)kc * 64 * DKc;
        #pragma unroll
        for (int it = 0; it < 2; it++) {
            const int e = tid + it * 256;
            const int r = e >> 3, s = e & 7;
            cp_async16(sKb + ((buf*64 + r)*HS + s*8)*2, Kc + r*DKc + s*8);
            cp_async16(sVb + ((buf*64 + r)*HS + s*8)*2, Vc + r*DKc + s*8);
        }
        if (tid < 16) cp_async16(sMBb + (buf*64 + tid*4)*4, MBp + kc*64 + tid*4);
    };

    issue_chunk(0);
    cp_commit();

    float of[8][4];
    float mi0 = -1e30f, mi1 = -1e30f, li0 = 0.f, li1 = 0.f;
    #pragma unroll
    for (int nt = 0; nt < 8; nt++)
        #pragma unroll
        for (int j = 0; j < 4; j++) of[nt][j] = 0.f;

    uint32_t* sP32 = (uint32_t*)sP;

    const int NC = Tc / 64;
    for (int kc = 0; kc < NC; kc++) {
        const int buf = kc & 1;
        if (kc + 1 < NC) { issue_chunk(kc + 1); cp_commit(); }
        if (kc + 1 < NC) asm volatile("cp.async.wait_group 1;");
        else             asm volatile("cp.async.wait_group 0;");
        __syncthreads();

        const uint32_t Kbuf = sKb + (buf*64*HS)*2;
        const uint32_t Vbuf = sVb + (buf*64*HS)*2;
        const float*   mbuf = sMB[buf];

        // ---- S = Q K^T : 4 kt x 8 nt (nt paired via ldmatrix.x4) ----
        float sf[8][4];
        #pragma unroll
        for (int nt = 0; nt < 8; nt++)
            #pragma unroll
            for (int j = 0; j < 4; j++) sf[nt][j] = 0.f;

        #pragma unroll
        for (int kt = 0; kt < 4; kt++) {
            uint32_t a0, a1, a2, a3;
            ldm_x4(a0, a1, a2, a3, aQaddr + kt*32);
            #pragma unroll
            for (int nt = 0; nt < 8; nt += 2) {
                uint32_t b0, b1, b2, b3;
                ldm_x4(b0, b1, b2, b3, Kbuf + (nt*8*HS)*2 + kt*32 + bKoff);
                mma_f16(sf[nt],   a0, a1, a2, a3, b0, b1);
                mma_f16(sf[nt+1], a0, a1, a2, a3, b2, b3);
            }
        }

        // ---- softmax (log2 domain, additive mask bias) ----
        float mx0 = -1e30f, mx1 = -1e30f;
        float mb0[8], mb1[8];
        #pragma unroll
        for (int nt = 0; nt < 8; nt++) {
            const float2 m2 = *(const float2*)(mbuf + nt*8 + 2*t);
            mb0[nt] = m2.x; mb1[nt] = m2.y;
            sf[nt][0] += m2.x; sf[nt][1] += m2.y;
            sf[nt][2] += m2.x; sf[nt][3] += m2.y;
            mx0 = fmaxf(mx0, fmaxf(sf[nt][0], sf[nt][1]));
            mx1 = fmaxf(mx1, fmaxf(sf[nt][2], sf[nt][3]));
        }
        mx0 = fmaxf(mx0, __shfl_xor_sync(0xffffffffu, mx0, 1));
        mx0 = fmaxf(mx0, __shfl_xor_sync(0xffffffffu, mx0, 2));
        mx1 = fmaxf(mx1, __shfl_xor_sync(0xffffffffu, mx1, 1));
        mx1 = fmaxf(mx1, __shfl_xor_sync(0xffffffffu, mx1, 2));

        // clamp keeps all-masked rows at p==0 (softmax is shift-invariant)
        const float mn0 = fmaxf(fmaxf(mi0, mx0), -60.f);
        const float mn1 = fmaxf(fmaxf(mi1, mx1), -60.f);
        const float al0 = ex2(mi0 - mn0);
        const float al1 = ex2(mi1 - mn1);
        mi0 = mn0; mi1 = mn1;

        float rs0 = 0.f, rs1 = 0.f;
        #pragma unroll
        for (int nt = 0; nt < 8; nt++) {
            const float p00 = ex2(sf[nt][0] - mn0);
            const float p01 = ex2(sf[nt][1] - mn0);
            const float p10 = ex2(sf[nt][2] - mn1);
            const float p11 = ex2(sf[nt][3] - mn1);
            rs0 += p00 + p01;
            rs1 += p10 + p11;
            __half2 h0 = __float22half2_rn(make_float2(p00, p01));
            __half2 h1 = __float22half2_rn(make_float2(p10, p11));
            sP32[(r0+g  )*HS2 + nt*4 + t] = *(uint32_t*)&h0;
            sP32[(r0+g+8)*HS2 + nt*4 + t] = *(uint32_t*)&h1;
        }
        rs0 += __shfl_xor_sync(0xffffffffu, rs0, 1);
        rs0 += __shfl_xor_sync(0xffffffffu, rs0, 2);
        rs1 += __shfl_xor_sync(0xffffffffu, rs1, 1);
        rs1 += __shfl_xor_sync(0xffffffffu, rs1, 2);
        li0 = li0 * al0 + rs0;
        li1 = li1 * al1 + rs1;

        #pragma unroll
        for (int nt = 0; nt < 8; nt++) {
            of[nt][0] *= al0; of[nt][1] *= al0;
            of[nt][2] *= al1; of[nt][3] *= al1;
        }

        __syncwarp();   // P rows are warp-private

        // ---- O += P @ V : 4 kt x 8 nt (nt paired via ldmatrix.x4.trans) ----
        #pragma unroll
        for (int kt = 0; kt < 4; kt++) {
            uint32_t a0, a1, a2, a3;
            ldm_x4(a0, a1, a2, a3, aPaddr + kt*32);
            #pragma unroll
            for (int nt = 0; nt < 8; nt += 2) {
                uint32_t b0, b1, b2, b3;
                ldm_x4t(b0, b1, b2, b3, Vbuf + (kt*16*HS + nt*8)*2 + bVoff);
                mma_f16(of[nt],   a0, a1, a2, a3, b0, b1);
                mma_f16(of[nt+1], a0, a1, a2, a3, b2, b3);
            }
        }
        __syncthreads();
    }

    // Normalize and write context [B, T, F] in fp16
    const float inv0 = (li0 > 0.f) ? (1.0f / li0) : 0.f;
    const float inv1 = (li1 > 0.f) ? (1.0f / li1) : 0.f;
    const int t0 = qt*128 + r0 + g;
    const int t1 = t0 + 8;
    #pragma unroll
    for (int nt = 0; nt < 8; nt++) {
        const int dk = nt*8 + 2*t;
        __half2 w0 = __float22half2_rn(make_float2(of[nt][0] * inv0, of[nt][1] * inv0));
        __half2 w1 = __float22half2_rn(make_float2(of[nt][2] * inv1, of[nt][3] * inv1));
        *(__half2*)(CTX + ((size_t)b * Tc + t0) * Fc + h*DKc + dk) = w0;
        *(__half2*)(CTX + ((size_t)b * Tc + t1) * Fc + h*DKc + dk) = w1;
    }
}

// ---------------------------------------------------------------------------
// Launcher
// ---------------------------------------------------------------------------
extern "C" void kernel_launch(void* const* d_in, const int* in_sizes, int n_in,
                              void* d_out, int out_size)
{
    const float* query = (const float*)d_in[0];
    const float* key   = (const float*)d_in[1];
    const float* value = (const float*)d_in[2];
    const int*   amask = (const int*)  d_in[3];
    const float* Wq = (const float*)d_in[4];
    const float* bq = (const float*)d_in[5];
    const float* Wk = (const float*)d_in[6];
    const float* bk = (const float*)d_in[7];
    const float* Wv = (const float*)d_in[8];
    const float* bv = (const float*)d_in[9];
    const float* Wo = (const float*)d_in[10];
    const float* bo = (const float*)d_in[11];
    float* out = (float*)d_out;

    __half *pXh, *pWh, *pQ, *pK, *pV, *pCTX;
    float *pMB;
    cudaGetSymbolAddress((void**)&pXh, g_Xh);
    cudaGetSymbolAddress((void**)&pWh, g_Wh);
    cudaGetSymbolAddress((void**)&pQ,  g_Qh);
    cudaGetSymbolAddress((void**)&pK,  g_Kh);
    cudaGetSymbolAddress((void**)&pV,  g_Vh);
    cudaGetSymbolAddress((void**)&pCTX, g_CTXh);
    cudaGetSymbolAddress((void**)&pMB, g_MB);

    __half* xh[3] = { pXh, pXh + (size_t)Mdim*Fc, pXh + 2*(size_t)Mdim*Fc };
    __half* wh[4] = { pWh, pWh + (size_t)Fc*Fc, pWh + 2*(size_t)Fc*Fc, pWh + 3*(size_t)Fc*Fc };

    cudaFuncSetAttribute(attn_kernel,
                         cudaFuncAttributeMaxDynamicSharedMemorySize, AT_SMEM_BYTES);

    // 1) convert inputs + weights to fp16, mask -> float bias
    CvtJobs JI;
    JI.src[0] = query; JI.src[1] = key; JI.src[2] = value; JI.src[3] = query;
    JI.dst[0] = xh[0]; JI.dst[1] = xh[1]; JI.dst[2] = xh[2]; JI.dst[3] = xh[0];
    cvt_kernel<<<dim3((Mdim*Fc)/(256*4), 3), 256>>>(JI);

    CvtJobs JW;
    JW.src[0] = Wq; JW.src[1] = Wk; JW.src[2] = Wv; JW.src[3] = Wo;
    JW.dst[0] = wh[0]; JW.dst[1] = wh[1]; JW.dst[2] = wh[2]; JW.dst[3] = wh[3];
    cvt_kernel<<<dim3((Fc*Fc)/(256*4), 4), 256>>>(JW);

    maskbias_kernel<<<(Bc*Tc)/256, 256>>>(amask, pMB);

    // 2) fused QKV projections (Q scaled by 0.125*log2e)
    QKVJobs P;
    P.A[0] = xh[0]; P.A[1] = xh[1]; P.A[2] = xh[2];
    P.W[0] = wh[0]; P.W[1] = wh[1]; P.W[2] = wh[2];
    P.bias[0] = bq; P.bias[1] = bk; P.bias[2] = bv;
    P.C[0] = pQ;    P.C[1] = pK;   P.C[2] = pV;
    gemm_h_kernel<1><<<dim3(Ndim/128, Mdim/128, 3), 256>>>(P, nullptr, nullptr, nullptr, nullptr);

    // 3) attention
    attn_kernel<<<dim3(Tc/128, Hc, Bc), 256, AT_SMEM_BYTES>>>(pQ, pK, pV, pMB, pCTX);

    // 4) output projection
    QKVJobs PD = {};
    gemm_h_kernel<0><<<dim3(Ndim/128, Mdim/128), 256>>>(PD, pCTX, wh[3], bo, out);
}

// round 8
// speedup vs baseline: 8.0813x; 1.0931x over previous
#include <cuda_runtime.h>
#include <cuda_bf16.h>
#include <cuda_fp16.h>
#include <cstdint>

// Problem constants
#define Bc 4
#define Tc 2048
#define Fc 512
#define Hc 8
#define DKc 64
#define Mdim (Bc*Tc)   // 8192
#define Ndim Fc        // 512
#define Kdim Fc        // 512

#define LOG2E 1.44269504088896340736f

// ---- fp16 mma m16n8k16, fp32 accumulate ----
__device__ __forceinline__ void mma_f16(float* c,
                                        uint32_t a0, uint32_t a1, uint32_t a2, uint32_t a3,
                                        uint32_t b0, uint32_t b1) {
    asm volatile("mma.sync.aligned.m16n8k16.row.col.f32.f16.f16.f32 "
                 "{%0,%1,%2,%3}, {%4,%5,%6,%7}, {%8,%9}, {%0,%1,%2,%3};"
                 : "+f"(c[0]), "+f"(c[1]), "+f"(c[2]), "+f"(c[3])
                 : "r"(a0), "r"(a1), "r"(a2), "r"(a3), "r"(b0), "r"(b1));
}
__device__ __forceinline__ uint32_t smem_u32(const void* p) {
    return (uint32_t)__cvta_generic_to_shared(p);
}
__device__ __forceinline__ void cp_async16(uint32_t dst, const void* src) {
    asm volatile("cp.async.cg.shared.global [%0], [%1], 16;" :: "r"(dst), "l"(src));
}
__device__ __forceinline__ void cp_commit() {
    asm volatile("cp.async.commit_group;");
}
__device__ __forceinline__ void ldm_x4(uint32_t& r0, uint32_t& r1, uint32_t& r2, uint32_t& r3,
                                       uint32_t addr) {
    asm volatile("ldmatrix.sync.aligned.m8n8.x4.shared.b16 {%0,%1,%2,%3}, [%4];"
                 : "=r"(r0), "=r"(r1), "=r"(r2), "=r"(r3) : "r"(addr));
}
__device__ __forceinline__ void ldm_x4t(uint32_t& r0, uint32_t& r1, uint32_t& r2, uint32_t& r3,
                                        uint32_t addr) {
    asm volatile("ldmatrix.sync.aligned.m8n8.x4.trans.shared.b16 {%0,%1,%2,%3}, [%4];"
                 : "=r"(r0), "=r"(r1), "=r"(r2), "=r"(r3) : "r"(addr));
}
__device__ __forceinline__ void ldm_x2(uint32_t& r0, uint32_t& r1, uint32_t addr) {
    asm volatile("ldmatrix.sync.aligned.m8n8.x2.shared.b16 {%0,%1}, [%2];"
                 : "=r"(r0), "=r"(r1) : "r"(addr));
}
__device__ __forceinline__ float ex2(float x) {
    float y; asm("ex2.approx.f32 %0, %1;" : "=f"(y) : "f"(x)); return y;
}

// Scratch
__device__ __half g_Xh[3][(size_t)Mdim*Fc];
__device__ __half g_Wh[4][(size_t)Fc*Fc];
__device__ __half g_Qh[(size_t)Bc*Hc*Tc*DKc];
__device__ __half g_Kh[(size_t)Bc*Hc*Tc*DKc];
__device__ __half g_Vh[(size_t)Bc*Hc*Tc*DKc];
__device__ __half g_CTXh[(size_t)Mdim*Fc];
__device__ float  g_MB[(size_t)Bc*Tc];

// ---------------------------------------------------------------------------
// fp32 -> fp16 convert (blockIdx.y selects job)
// ---------------------------------------------------------------------------
struct CvtJobs { const float* src[4]; __half* dst[4]; };

__global__ __launch_bounds__(256)
void cvt_kernel(CvtJobs J)
{
    const float* s = J.src[blockIdx.y];
    __half* d = J.dst[blockIdx.y];
    const size_t i = ((size_t)blockIdx.x * 256 + threadIdx.x) * 4;
    float4 v = *(const float4*)(s + i);
    __half2 h0 = __float22half2_rn(make_float2(v.x, v.y));
    __half2 h1 = __float22half2_rn(make_float2(v.z, v.w));
    uint2 o; o.x = *(uint32_t*)&h0; o.y = *(uint32_t*)&h1;
    *(uint2*)(d + i) = o;
}

__global__ __launch_bounds__(256)
void maskbias_kernel(const int* __restrict__ m, float* __restrict__ mb)
{
    const int i = blockIdx.x * 256 + threadIdx.x;
    mb[i] = m[i] ? 0.f : -1e30f;
}

// ---------------------------------------------------------------------------
// fp16 GEMM, 3-stage cp.async pipeline, one barrier per K-iter.
// C = A @ W^T + bias. CTA 128x128, BK=32, 8 warps (4m x 2n), warp m32 x n64.
// MODE 0: C fp32 row-major. MODE 1: C fp16 scatter to [B,H,T,DK], scale(z==0).
// ---------------------------------------------------------------------------
#define HAS 40
#define G_STAGE_H (128*HAS)                 // halves per stage per matrix
#define G_SMEM_BYTES (2 * 3 * G_STAGE_H * 2)  // 61440

struct QKVJobs {
    const __half* A[3];
    const __half* W[3];
    const float* bias[3];
    __half* C[3];
};

template<int MODE>
__global__ __launch_bounds__(256, 2)
void gemm_h_kernel(QKVJobs P, const __half* Ao, const __half* Wo,
                   const float* biaso, float* Co)
{
    extern __shared__ __half gsm[];
    __half* sA = gsm;                  // [3][128*HAS]
    __half* sW = gsm + 3*G_STAGE_H;    // [3][128*HAS]

    const int z = (MODE == 1) ? blockIdx.z : 0;
    const __half* A  = (MODE == 1) ? P.A[z] : Ao;
    const __half* W  = (MODE == 1) ? P.W[z] : Wo;
    const float* bias = (MODE == 1) ? P.bias[z] : biaso;
    const float scale = (MODE == 1 && z == 0) ? 0.125f * LOG2E : 1.0f;

    const int tid  = threadIdx.x;
    const int lane = tid & 31;
    const int w    = tid >> 5;
    const int g    = lane >> 2;
    const int t    = lane & 3;
    const int wm   = w & 3;
    const int wn   = w >> 2;
    const int bm = blockIdx.y * 128;
    const int bn = blockIdx.x * 128;

    const uint32_t sAb = smem_u32(sA);
    const uint32_t sWb = smem_u32(sW);

    auto issue = [&](int i) {
        const int buf = i % 3;
        const int k0 = i * 32;
        #pragma unroll
        for (int it = 0; it < 2; it++) {
            const int e = tid + it * 256;
            const int r = e >> 2, s = e & 3;
            cp_async16(sAb + (buf*G_STAGE_H + r*HAS + s*8)*2,
                       A + (size_t)(bm + r) * Kdim + k0 + s*8);
            cp_async16(sWb + (buf*G_STAGE_H + r*HAS + s*8)*2,
                       W + (size_t)(bn + r) * Kdim + k0 + s*8);
        }
    };

    float acc[2][8][4];
    #pragma unroll
    for (int mt = 0; mt < 2; mt++)
        #pragma unroll
        for (int nt = 0; nt < 8; nt++)
            #pragma unroll
            for (int j = 0; j < 4; j++) acc[mt][nt][j] = 0.f;

    issue(0); cp_commit();
    issue(1); cp_commit();

    const int NIT = Kdim / 32;   // 16
    for (int i = 0; i < NIT; i++) {
        const int buf = i % 3;
        if (i + 1 < NIT) asm volatile("cp.async.wait_group 1;");
        else             asm volatile("cp.async.wait_group 0;");
        __syncthreads();

        const uint32_t Ab = sAb + (buf*G_STAGE_H)*2;
        const uint32_t Wb = sWb + (buf*G_STAGE_H)*2;

        #pragma unroll
        for (int kt = 0; kt < 2; kt++) {
            uint32_t a[2][4];
            #pragma unroll
            for (int mt = 0; mt < 2; mt++) {
                const int row = wm*32 + mt*16 + (lane & 15);
                const int col = kt*16 + (lane >> 4) * 8;
                ldm_x4(a[mt][0], a[mt][1], a[mt][2], a[mt][3],
                       Ab + (row*HAS + col)*2);
            }
            #pragma unroll
            for (int nt = 0; nt < 8; nt++) {
                const int row = wn*64 + nt*8 + (lane & 7);
                const int col = kt*16 + ((lane >> 3) & 1) * 8;
                uint32_t b0, b1;
                ldm_x2(b0, b1, Wb + (row*HAS + col)*2);
                mma_f16(acc[0][nt], a[0][0], a[0][1], a[0][2], a[0][3], b0, b1);
                mma_f16(acc[1][nt], a[1][0], a[1][1], a[1][2], a[1][3], b0, b1);
            }
        }
        if (i + 2 < NIT) { issue(i + 2); cp_commit(); }
    }

    #pragma unroll
    for (int nt = 0; nt < 8; nt++) {
        const int col = bn + wn*64 + nt*8 + 2*t;
        const float2 bb = *(const float2*)(bias + col);
        #pragma unroll
        for (int mt = 0; mt < 2; mt++) {
            const int row0 = bm + wm*32 + mt*16 + g;
            const int row1 = row0 + 8;
            float2 v0, v1;
            v0.x = (acc[mt][nt][0] + bb.x) * scale; v0.y = (acc[mt][nt][1] + bb.y) * scale;
            v1.x = (acc[mt][nt][2] + bb.x) * scale; v1.y = (acc[mt][nt][3] + bb.y) * scale;
            if (MODE == 0) {
                *(float2*)(Co + (size_t)row0 * Ndim + col) = v0;
                *(float2*)(Co + (size_t)row1 * Ndim + col) = v1;
            } else {
                const int h  = col >> 6;
                const int dk = col & 63;
                const int b0_ = row0 >> 11, t0_ = row0 & 2047;
                const int b1_ = row1 >> 11, t1_ = row1 & 2047;
                __half2 h0 = __float22half2_rn(v0);
                __half2 h1 = __float22half2_rn(v1);
                *(__half2*)(P.C[z] + ((((size_t)b0_*Hc + h)*Tc + t0_) * DKc) + dk) = h0;
                *(__half2*)(P.C[z] + ((((size_t)b1_*Hc + h)*Tc + t1_) * DKc) + dk) = h1;
            }
        }
    }
}

// ---------------------------------------------------------------------------
// Flash attention: fp16 mma, 3-stage cp.async K/V, P kept in registers
// (QK C-frag == PV A-frag layout), additive mask bias, exp2 domain.
// Q pre-scaled by 0.125*log2e in projection. CTX fp16.
// ---------------------------------------------------------------------------
#define HS 72
#define SQ_OFF 0
#define SK_OFF (128*HS)
#define SV_OFF (SK_OFF + 3*64*HS)
#define AT_HALVES (SV_OFF + 3*64*HS)
#define AT_SMEM_BYTES (AT_HALVES * 2)   // 73728

__global__ __launch_bounds__(256, 2)
void attn_kernel(const __half* __restrict__ Q, const __half* __restrict__ K,
                 const __half* __restrict__ V, const float* __restrict__ maskb,
                 __half* __restrict__ CTX)
{
    extern __shared__ __half hsm[];
    __half* sQ = hsm + SQ_OFF;          // [128][HS]
    __half* sK = hsm + SK_OFF;          // [3][64][HS]
    __half* sV = hsm + SV_OFF;          // [3][64][HS]
    __shared__ float sMB[3][64];

    const uint32_t sQb = smem_u32(sQ);
    const uint32_t sKb = smem_u32(sK);
    const uint32_t sVb = smem_u32(sV);
    const uint32_t sMBb = smem_u32(&sMB[0][0]);

    const int tid  = threadIdx.x;
    const int lane = tid & 31;
    const int w    = tid >> 5;
    const int g    = lane >> 2;
    const int t    = lane & 3;
    const int r0   = w * 16;
    const int qt = blockIdx.x;
    const int h  = blockIdx.y;
    const int b  = blockIdx.z;

    const size_t head_base = (((size_t)b * Hc + h) * Tc) * DKc;
    const __half* Qb = Q + head_base + (size_t)qt * 128 * DKc;
    const __half* Kb = K + head_base;
    const __half* Vb = V + head_base;
    const float* MBp = maskb + b * Tc;

    const int l15 = lane & 15;
    const int lhi = lane >> 4;
    const int l7  = lane & 7;
    const int lb8 = (lane >> 3) & 1;
    const uint32_t aQaddr = sQb + ((r0 + l15)*HS + lhi*8)*2;
    const uint32_t bKoff = ((l7 + lhi*8)*HS + lb8*8)*2;
    const uint32_t bVoff = (l15*HS + lhi*8)*2;

    // Q tile (group 0)
    #pragma unroll
    for (int it = 0; it < 4; it++) {
        const int e = tid + it * 256;
        const int r = e >> 3, s = e & 7;
        cp_async16(sQb + (r*HS + s*8)*2, Qb + r*DKc + s*8);
    }

    auto issue_chunk = [&](int kc) {
        const int buf = kc % 3;
        const __half* Kc = Kb + (size_t)kc * 64 * DKc;
        const __half* Vc = Vb + (size_t)kc * 64 * DKc;
        #pragma unroll
        for (int it = 0; it < 2; it++) {
            const int e = tid + it * 256;
            const int r = e >> 3, s = e & 7;
            cp_async16(sKb + ((buf*64 + r)*HS + s*8)*2, Kc + r*DKc + s*8);
            cp_async16(sVb + ((buf*64 + r)*HS + s*8)*2, Vc + r*DKc + s*8);
        }
        if (tid < 16) cp_async16(sMBb + (buf*64 + tid*4)*4, MBp + kc*64 + tid*4);
    };

    issue_chunk(0); cp_commit();
    issue_chunk(1); cp_commit();

    float of[8][4];
    float mi0 = -1e30f, mi1 = -1e30f, li0 = 0.f, li1 = 0.f;
    #pragma unroll
    for (int nt = 0; nt < 8; nt++)
        #pragma unroll
        for (int j = 0; j < 4; j++) of[nt][j] = 0.f;

    const int NC = Tc / 64;   // 32
    for (int kc = 0; kc < NC; kc++) {
        const int buf = kc % 3;
        if (kc + 1 < NC) asm volatile("cp.async.wait_group 1;");
        else             asm volatile("cp.async.wait_group 0;");
        __syncthreads();

        const uint32_t Kbuf = sKb + (buf*64*HS)*2;
        const uint32_t Vbuf = sVb + (buf*64*HS)*2;
        const float*   mbuf = sMB[buf];

        // ---- S = Q K^T ----
        float sf[8][4];
        #pragma unroll
        for (int nt = 0; nt < 8; nt++)
            #pragma unroll
            for (int j = 0; j < 4; j++) sf[nt][j] = 0.f;

        #pragma unroll
        for (int kt = 0; kt < 4; kt++) {
            uint32_t a0, a1, a2, a3;
            ldm_x4(a0, a1, a2, a3, aQaddr + kt*32);
            #pragma unroll
            for (int nt = 0; nt < 8; nt += 2) {
                uint32_t b0, b1, b2, b3;
                ldm_x4(b0, b1, b2, b3, Kbuf + (nt*8*HS)*2 + kt*32 + bKoff);
                mma_f16(sf[nt],   a0, a1, a2, a3, b0, b1);
                mma_f16(sf[nt+1], a0, a1, a2, a3, b2, b3);
            }
        }

        // ---- softmax (log2 domain, additive mask bias) ----
        float mx0 = -1e30f, mx1 = -1e30f;
        #pragma unroll
        for (int nt = 0; nt < 8; nt++) {
            const float2 m2 = *(const float2*)(mbuf + nt*8 + 2*t);
            sf[nt][0] += m2.x; sf[nt][1] += m2.y;
            sf[nt][2] += m2.x; sf[nt][3] += m2.y;
            mx0 = fmaxf(mx0, fmaxf(sf[nt][0], sf[nt][1]));
            mx1 = fmaxf(mx1, fmaxf(sf[nt][2], sf[nt][3]));
        }
        mx0 = fmaxf(mx0, __shfl_xor_sync(0xffffffffu, mx0, 1));
        mx0 = fmaxf(mx0, __shfl_xor_sync(0xffffffffu, mx0, 2));
        mx1 = fmaxf(mx1, __shfl_xor_sync(0xffffffffu, mx1, 1));
        mx1 = fmaxf(mx1, __shfl_xor_sync(0xffffffffu, mx1, 2));

        const float mn0 = fmaxf(fmaxf(mi0, mx0), -60.f);
        const float mn1 = fmaxf(fmaxf(mi1, mx1), -60.f);
        const float al0 = ex2(mi0 - mn0);
        const float al1 = ex2(mi1 - mn1);
        mi0 = mn0; mi1 = mn1;

        // p in registers, packed directly as PV A-fragments
        uint32_t ph[8][2];
        float rs0 = 0.f, rs1 = 0.f;
        #pragma unroll
        for (int nt = 0; nt < 8; nt++) {
            const float p00 = ex2(sf[nt][0] - mn0);
            const float p01 = ex2(sf[nt][1] - mn0);
            const float p10 = ex2(sf[nt][2] - mn1);
            const float p11 = ex2(sf[nt][3] - mn1);
            rs0 += p00 + p01;
            rs1 += p10 + p11;
            __half2 h0 = __float22half2_rn(make_float2(p00, p01));
            __half2 h1 = __float22half2_rn(make_float2(p10, p11));
            ph[nt][0] = *(uint32_t*)&h0;
            ph[nt][1] = *(uint32_t*)&h1;
        }
        rs0 += __shfl_xor_sync(0xffffffffu, rs0, 1);
        rs0 += __shfl_xor_sync(0xffffffffu, rs0, 2);
        rs1 += __shfl_xor_sync(0xffffffffu, rs1, 1);
        rs1 += __shfl_xor_sync(0xffffffffu, rs1, 2);
        li0 = li0 * al0 + rs0;
        li1 = li1 * al1 + rs1;

        #pragma unroll
        for (int nt = 0; nt < 8; nt++) {
            of[nt][0] *= al0; of[nt][1] *= al0;
            of[nt][2] *= al1; of[nt][3] *= al1;
        }

        // ---- O += P @ V (A-frags from registers) ----
        #pragma unroll
        for (int kt = 0; kt < 4; kt++) {
            const uint32_t a0 = ph[2*kt][0];
            const uint32_t a1 = ph[2*kt][1];
            const uint32_t a2 = ph[2*kt+1][0];
            const uint32_t a3 = ph[2*kt+1][1];
            #pragma unroll
            for (int nt = 0; nt < 8; nt += 2) {
                uint32_t b0, b1, b2, b3;
                ldm_x4t(b0, b1, b2, b3, Vbuf + (kt*16*HS + nt*8)*2 + bVoff);
                mma_f16(of[nt],   a0, a1, a2, a3, b0, b1);
                mma_f16(of[nt+1], a0, a1, a2, a3, b2, b3);
            }
        }

        if (kc + 2 < NC) { issue_chunk(kc + 2); cp_commit(); }
    }

    // Normalize and write context [B, T, F] in fp16
    const float inv0 = (li0 > 0.f) ? (1.0f / li0) : 0.f;
    const float inv1 = (li1 > 0.f) ? (1.0f / li1) : 0.f;
    const int t0 = qt*128 + r0 + g;
    const int t1 = t0 + 8;
    #pragma unroll
    for (int nt = 0; nt < 8; nt++) {
        const int dk = nt*8 + 2*t;
        __half2 w0 = __float22half2_rn(make_float2(of[nt][0] * inv0, of[nt][1] * inv0));
        __half2 w1 = __float22half2_rn(make_float2(of[nt][2] * inv1, of[nt][3] * inv1));
        *(__half2*)(CTX + ((size_t)b * Tc + t0) * Fc + h*DKc + dk) = w0;
        *(__half2*)(CTX + ((size_t)b * Tc + t1) * Fc + h*DKc + dk) = w1;
    }
}

// ---------------------------------------------------------------------------
// Launcher
// ---------------------------------------------------------------------------
extern "C" void kernel_launch(void* const* d_in, const int* in_sizes, int n_in,
                              void* d_out, int out_size)
{
    const float* query = (const float*)d_in[0];
    const float* key   = (const float*)d_in[1];
    const float* value = (const float*)d_in[2];
    const int*   amask = (const int*)  d_in[3];
    const float* Wq = (const float*)d_in[4];
    const float* bq = (const float*)d_in[5];
    const float* Wk = (const float*)d_in[6];
    const float* bk = (const float*)d_in[7];
    const float* Wv = (const float*)d_in[8];
    const float* bv = (const float*)d_in[9];
    const float* Wo = (const float*)d_in[10];
    const float* bo = (const float*)d_in[11];
    float* out = (float*)d_out;

    __half *pXh, *pWh, *pQ, *pK, *pV, *pCTX;
    float *pMB;
    cudaGetSymbolAddress((void**)&pXh, g_Xh);
    cudaGetSymbolAddress((void**)&pWh, g_Wh);
    cudaGetSymbolAddress((void**)&pQ,  g_Qh);
    cudaGetSymbolAddress((void**)&pK,  g_Kh);
    cudaGetSymbolAddress((void**)&pV,  g_Vh);
    cudaGetSymbolAddress((void**)&pCTX, g_CTXh);
    cudaGetSymbolAddress((void**)&pMB, g_MB);

    __half* xh[3] = { pXh, pXh + (size_t)Mdim*Fc, pXh + 2*(size_t)Mdim*Fc };
    __half* wh[4] = { pWh, pWh + (size_t)Fc*Fc, pWh + 2*(size_t)Fc*Fc, pWh + 3*(size_t)Fc*Fc };

    cudaFuncSetAttribute(attn_kernel,
                         cudaFuncAttributeMaxDynamicSharedMemorySize, AT_SMEM_BYTES);
    cudaFuncSetAttribute(gemm_h_kernel<0>,
                         cudaFuncAttributeMaxDynamicSharedMemorySize, G_SMEM_BYTES);
    cudaFuncSetAttribute(gemm_h_kernel<1>,
                         cudaFuncAttributeMaxDynamicSharedMemorySize, G_SMEM_BYTES);

    // 1) converts + mask bias
    CvtJobs JI;
    JI.src[0] = query; JI.src[1] = key; JI.src[2] = value; JI.src[3] = query;
    JI.dst[0] = xh[0]; JI.dst[1] = xh[1]; JI.dst[2] = xh[2]; JI.dst[3] = xh[0];
    cvt_kernel<<<dim3((Mdim*Fc)/(256*4), 3), 256>>>(JI);

    CvtJobs JW;
    JW.src[0] = Wq; JW.src[1] = Wk; JW.src[2] = Wv; JW.src[3] = Wo;
    JW.dst[0] = wh[0]; JW.dst[1] = wh[1]; JW.dst[2] = wh[2]; JW.dst[3] = wh[3];
    cvt_kernel<<<dim3((Fc*Fc)/(256*4), 4), 256>>>(JW);

    maskbias_kernel<<<(Bc*Tc)/256, 256>>>(amask, pMB);

    // 2) fused QKV projections (Q scaled by 0.125*log2e)
    QKVJobs P;
    P.A[0] = xh[0]; P.A[1] = xh[1]; P.A[2] = xh[2];
    P.W[0] = wh[0]; P.W[1] = wh[1]; P.W[2] = wh[2];
    P.bias[0] = bq; P.bias[1] = bk; P.bias[2] = bv;
    P.C[0] = pQ;    P.C[1] = pK;   P.C[2] = pV;
    gemm_h_kernel<1><<<dim3(Ndim/128, Mdim/128, 3), 256, G_SMEM_BYTES>>>(P, nullptr, nullptr, nullptr, nullptr);

    // 3) attention
    attn_kernel<<<dim3(Tc/128, Hc, Bc), 256, AT_SMEM_BYTES>>>(pQ, pK, pV, pMB, pCTX);

    // 4) output projection
    QKVJobs PD = {};
    gemm_h_kernel<0><<<dim3(Ndim/128, Mdim/128), 256, G_SMEM_BYTES>>>(PD, pCTX, wh[3], bo, out);
}

// round 10
// speedup vs baseline: 8.4071x; 1.0403x over previous
#include <cuda_runtime.h>
#include <cuda_bf16.h>
#include <cuda_fp16.h>
#include <cstdint>

// Problem constants
#define Bc 4
#define Tc 2048
#define Fc 512
#define Hc 8
#define DKc 64
#define Mdim (Bc*Tc)   // 8192
#define Ndim Fc        // 512
#define Kdim Fc        // 512

#define LOG2E 1.44269504088896340736f

// ---- fp16 mma m16n8k16, fp32 accumulate ----
__device__ __forceinline__ void mma_f16(float* c,
                                        uint32_t a0, uint32_t a1, uint32_t a2, uint32_t a3,
                                        uint32_t b0, uint32_t b1) {
    asm volatile("mma.sync.aligned.m16n8k16.row.col.f32.f16.f16.f32 "
                 "{%0,%1,%2,%3}, {%4,%5,%6,%7}, {%8,%9}, {%0,%1,%2,%3};"
                 : "+f"(c[0]), "+f"(c[1]), "+f"(c[2]), "+f"(c[3])
                 : "r"(a0), "r"(a1), "r"(a2), "r"(a3), "r"(b0), "r"(b1));
}
__device__ __forceinline__ uint32_t smem_u32(const void* p) {
    return (uint32_t)__cvta_generic_to_shared(p);
}
__device__ __forceinline__ void cp_async16(uint32_t dst, const void* src) {
    asm volatile("cp.async.cg.shared.global [%0], [%1], 16;" :: "r"(dst), "l"(src));
}
__device__ __forceinline__ void cp_commit() {
    asm volatile("cp.async.commit_group;");
}
__device__ __forceinline__ void ldm_x4(uint32_t& r0, uint32_t& r1, uint32_t& r2, uint32_t& r3,
                                       uint32_t addr) {
    asm volatile("ldmatrix.sync.aligned.m8n8.x4.shared.b16 {%0,%1,%2,%3}, [%4];"
                 : "=r"(r0), "=r"(r1), "=r"(r2), "=r"(r3) : "r"(addr));
}
__device__ __forceinline__ void ldm_x4t(uint32_t& r0, uint32_t& r1, uint32_t& r2, uint32_t& r3,
                                        uint32_t addr) {
    asm volatile("ldmatrix.sync.aligned.m8n8.x4.trans.shared.b16 {%0,%1,%2,%3}, [%4];"
                 : "=r"(r0), "=r"(r1), "=r"(r2), "=r"(r3) : "r"(addr));
}
__device__ __forceinline__ void ldm_x2t(uint32_t& r0, uint32_t& r1, uint32_t addr) {
    asm volatile("ldmatrix.sync.aligned.m8n8.x2.trans.shared.b16 {%0,%1}, [%2];"
                 : "=r"(r0), "=r"(r1) : "r"(addr));
}
__device__ __forceinline__ void ldm_x2(uint32_t& r0, uint32_t& r1, uint32_t addr) {
    asm volatile("ldmatrix.sync.aligned.m8n8.x2.shared.b16 {%0,%1}, [%2];"
                 : "=r"(r0), "=r"(r1) : "r"(addr));
}
__device__ __forceinline__ float ex2(float x) {
    float y; asm("ex2.approx.f32 %0, %1;" : "=f"(y) : "f"(x)); return y;
}
// packed fp16 exp2 of two fp32 args (lo = a, hi = b)
__device__ __forceinline__ uint32_t ex2_h2(float a, float b) {
    uint32_t d, r;
    asm("cvt.rn.f16x2.f32 %0, %1, %2;" : "=r"(d) : "f"(b), "f"(a));  // hi=b, lo=a
    asm("ex2.approx.f16x2 %0, %1;" : "=r"(r) : "r"(d));
    return r;
}

// Scratch
__device__ __half g_Xh[3][(size_t)Mdim*Fc];
__device__ __half g_Wh[4][(size_t)Fc*Fc];
__device__ __half g_Qh[(size_t)Bc*Hc*Tc*DKc];
__device__ __half g_Kh[(size_t)Bc*Hc*Tc*DKc];
__device__ __half g_Vh[(size_t)Bc*Hc*Tc*DKc];
__device__ __half g_CTXh[(size_t)Mdim*Fc];
__device__ float  g_MB[(size_t)Bc*Tc];

// ---------------------------------------------------------------------------
// fp32 -> fp16 convert
// ---------------------------------------------------------------------------
struct CvtJobs { const float* src[4]; __half* dst[4]; };

__global__ __launch_bounds__(256)
void cvt_kernel(CvtJobs J)
{
    const float* s = J.src[blockIdx.y];
    __half* d = J.dst[blockIdx.y];
    const size_t i = ((size_t)blockIdx.x * 256 + threadIdx.x) * 4;
    float4 v = *(const float4*)(s + i);
    __half2 h0 = __float22half2_rn(make_float2(v.x, v.y));
    __half2 h1 = __float22half2_rn(make_float2(v.z, v.w));
    uint2 o; o.x = *(uint32_t*)&h0; o.y = *(uint32_t*)&h1;
    *(uint2*)(d + i) = o;
}

__global__ __launch_bounds__(256)
void maskbias_kernel(const int* __restrict__ m, float* __restrict__ mb)
{
    const int i = blockIdx.x * 256 + threadIdx.x;
    mb[i] = m[i] ? 0.f : -1e30f;
}

// ---------------------------------------------------------------------------
// fp16 GEMM, 3-stage cp.async pipeline (R7, proven).
// MODE 0: C fp32 row-major. MODE 1: C fp16 scatter to [B,H,T,DK], scale(z==0).
// ---------------------------------------------------------------------------
#define HAS 40
#define G_STAGE_H (128*HAS)
#define G_SMEM_BYTES (2 * 3 * G_STAGE_H * 2)  // 61440

struct QKVJobs {
    const __half* A[3];
    const __half* W[3];
    const float* bias[3];
    __half* C[3];
};

template<int MODE>
__global__ __launch_bounds__(256, 2)
void gemm_h_kernel(QKVJobs P, const __half* Ao, const __half* Wo,
                   const float* biaso, float* Co)
{
    extern __shared__ __half gsm[];
    __half* sA = gsm;
    __half* sW = gsm + 3*G_STAGE_H;

    const int z = (MODE == 1) ? blockIdx.z : 0;
    const __half* A  = (MODE == 1) ? P.A[z] : Ao;
    const __half* W  = (MODE == 1) ? P.W[z] : Wo;
    const float* bias = (MODE == 1) ? P.bias[z] : biaso;
    const float scale = (MODE == 1 && z == 0) ? 0.125f * LOG2E : 1.0f;

    const int tid  = threadIdx.x;
    const int lane = tid & 31;
    const int w    = tid >> 5;
    const int g    = lane >> 2;
    const int t    = lane & 3;
    const int wm   = w & 3;
    const int wn   = w >> 2;
    const int bm = blockIdx.y * 128;
    const int bn = blockIdx.x * 128;

    const uint32_t sAb = smem_u32(sA);
    const uint32_t sWb = smem_u32(sW);

    auto issue = [&](int i) {
        const int buf = i % 3;
        const int k0 = i * 32;
        #pragma unroll
        for (int it = 0; it < 2; it++) {
            const int e = tid + it * 256;
            const int r = e >> 2, s = e & 3;
            cp_async16(sAb + (buf*G_STAGE_H + r*HAS + s*8)*2,
                       A + (size_t)(bm + r) * Kdim + k0 + s*8);
            cp_async16(sWb + (buf*G_STAGE_H + r*HAS + s*8)*2,
                       W + (size_t)(bn + r) * Kdim + k0 + s*8);
        }
    };

    float acc[2][8][4];
    #pragma unroll
    for (int mt = 0; mt < 2; mt++)
        #pragma unroll
        for (int nt = 0; nt < 8; nt++)
            #pragma unroll
            for (int j = 0; j < 4; j++) acc[mt][nt][j] = 0.f;

    issue(0); cp_commit();
    issue(1); cp_commit();

    const int NIT = Kdim / 32;   // 16
    for (int i = 0; i < NIT; i++) {
        const int buf = i % 3;
        if (i + 1 < NIT) asm volatile("cp.async.wait_group 1;");
        else             asm volatile("cp.async.wait_group 0;");
        __syncthreads();

        const uint32_t Ab = sAb + (buf*G_STAGE_H)*2;
        const uint32_t Wb = sWb + (buf*G_STAGE_H)*2;

        #pragma unroll
        for (int kt = 0; kt < 2; kt++) {
            uint32_t a[2][4];
            #pragma unroll
            for (int mt = 0; mt < 2; mt++) {
                const int row = wm*32 + mt*16 + (lane & 15);
                const int col = kt*16 + (lane >> 4) * 8;
                ldm_x4(a[mt][0], a[mt][1], a[mt][2], a[mt][3],
                       Ab + (row*HAS + col)*2);
            }
            #pragma unroll
            for (int nt = 0; nt < 8; nt++) {
                const int row = wn*64 + nt*8 + (lane & 7);
                const int col = kt*16 + ((lane >> 3) & 1) * 8;
                uint32_t b0, b1;
                ldm_x2(b0, b1, Wb + (row*HAS + col)*2);
                mma_f16(acc[0][nt], a[0][0], a[0][1], a[0][2], a[0][3], b0, b1);
                mma_f16(acc[1][nt], a[1][0], a[1][1], a[1][2], a[1][3], b0, b1);
            }
        }
        if (i + 2 < NIT) { issue(i + 2); cp_commit(); }
    }

    #pragma unroll
    for (int nt = 0; nt < 8; nt++) {
        const int col = bn + wn*64 + nt*8 + 2*t;
        const float2 bb = *(const float2*)(bias + col);
        #pragma unroll
        for (int mt = 0; mt < 2; mt++) {
            const int row0 = bm + wm*32 + mt*16 + g;
            const int row1 = row0 + 8;
            float2 v0, v1;
            v0.x = (acc[mt][nt][0] + bb.x) * scale; v0.y = (acc[mt][nt][1] + bb.y) * scale;
            v1.x = (acc[mt][nt][2] + bb.x) * scale; v1.y = (acc[mt][nt][3] + bb.y) * scale;
            if (MODE == 0) {
                *(float2*)(Co + (size_t)row0 * Ndim + col) = v0;
                *(float2*)(Co + (size_t)row1 * Ndim + col) = v1;
            } else {
                const int h  = col >> 6;
                const int dk = col & 63;
                const int b0_ = row0 >> 11, t0_ = row0 & 2047;
                const int b1_ = row1 >> 11, t1_ = row1 & 2047;
                __half2 h0 = __float22half2_rn(v0);
                __half2 h1 = __float22half2_rn(v1);
                *(__half2*)(P.C[z] + ((((size_t)b0_*Hc + h)*Tc + t0_) * DKc) + dk) = h0;
                *(__half2*)(P.C[z] + ((((size_t)b1_*Hc + h)*Tc + t1_) * DKc) + dk) = h1;
            }
        }
    }
}

// ---------------------------------------------------------------------------
// Flash attention: fp16 mma, 3-stage cp.async, P in registers,
// fp16x2 packed exp2 (half the MUFU ops), li via ones-column of V (row sums
// computed by the tensor core), warp-uniform alpha-rescale skip.
// Q pre-scaled by 0.125*log2e in projection. CTX fp16.
// ---------------------------------------------------------------------------
#define HS 72
#define SQ_OFF 0
#define SK_OFF (128*HS)
#define SV_OFF (SK_OFF + 3*64*HS)
#define AT_HALVES (SV_OFF + 3*64*HS)
#define AT_SMEM_BYTES (AT_HALVES * 2)   // 73728

__global__ __launch_bounds__(256, 2)
void attn_kernel(const __half* __restrict__ Q, const __half* __restrict__ K,
                 const __half* __restrict__ V, const float* __restrict__ maskb,
                 __half* __restrict__ CTX)
{
    extern __shared__ __half hsm[];
    __half* sQ = hsm + SQ_OFF;          // [128][HS]
    __half* sK = hsm + SK_OFF;          // [3][64][HS]
    __half* sV = hsm + SV_OFF;          // [3][64][HS]; col 64 = 1.0 (ones col)
    __shared__ float sMB[3][64];

    const uint32_t sQb = smem_u32(sQ);
    const uint32_t sKb = smem_u32(sK);
    const uint32_t sVb = smem_u32(sV);
    const uint32_t sMBb = smem_u32(&sMB[0][0]);

    const int tid  = threadIdx.x;
    const int lane = tid & 31;
    const int w    = tid >> 5;
    const int g    = lane >> 2;
    const int t    = lane & 3;
    const int r0   = w * 16;
    const int qt = blockIdx.x;
    const int h  = blockIdx.y;
    const int b  = blockIdx.z;

    const size_t head_base = (((size_t)b * Hc + h) * Tc) * DKc;
    const __half* Qb = Q + head_base + (size_t)qt * 128 * DKc;
    const __half* Kb = K + head_base;
    const __half* Vb = V + head_base;
    const float* MBp = maskb + b * Tc;

    const int l15 = lane & 15;
    const int lhi = lane >> 4;
    const int l7  = lane & 7;
    const int lb8 = (lane >> 3) & 1;
    const uint32_t aQaddr = sQb + ((r0 + l15)*HS + lhi*8)*2;
    const uint32_t bKoff = ((l7 + lhi*8)*HS + lb8*8)*2;
    const uint32_t bVoff = (l15*HS + lhi*8)*2;

    // Init ones-column (col 64 = 1.0h, cols 65-71 = 0) for all 3 V buffers.
    // cp.async stages only write cols 0..63, so this persists.
    for (int idx = tid; idx < 3*64; idx += 256) {
        uint4 v; v.x = 0x00003C00u; v.y = 0; v.z = 0; v.w = 0;
        *(uint4*)(sV + idx*HS + 64) = v;
    }

    // Q tile
    #pragma unroll
    for (int it = 0; it < 4; it++) {
        const int e = tid + it * 256;
        const int r = e >> 3, s = e & 7;
        cp_async16(sQb + (r*HS + s*8)*2, Qb + r*DKc + s*8);
    }

    auto issue_chunk = [&](int kc) {
        const int buf = kc % 3;
        const __half* Kc = Kb + (size_t)kc * 64 * DKc;
        const __half* Vc = Vb + (size_t)kc * 64 * DKc;
        #pragma unroll
        for (int it = 0; it < 2; it++) {
            const int e = tid + it * 256;
            const int r = e >> 3, s = e & 7;
            cp_async16(sKb + ((buf*64 + r)*HS + s*8)*2, Kc + r*DKc + s*8);
            cp_async16(sVb + ((buf*64 + r)*HS + s*8)*2, Vc + r*DKc + s*8);
        }
        if (tid < 16) cp_async16(sMBb + (buf*64 + tid*4)*4, MBp + kc*64 + tid*4);
    };

    issue_chunk(0); cp_commit();
    issue_chunk(1); cp_commit();

    float of[8][4];
    float ofs[4];                     // ones-column accumulator -> li
    float mi0 = -1e30f, mi1 = -1e30f;
    #pragma unroll
    for (int nt = 0; nt < 8; nt++)
        #pragma unroll
        for (int j = 0; j < 4; j++) of[nt][j] = 0.f;
    ofs[0] = ofs[1] = ofs[2] = ofs[3] = 0.f;

    const int NC = Tc / 64;   // 32
    for (int kc = 0; kc < NC; kc++) {
        const int buf = kc % 3;
        if (kc + 1 < NC) asm volatile("cp.async.wait_group 1;");
        else             asm volatile("cp.async.wait_group 0;");
        __syncthreads();

        const uint32_t Kbuf = sKb + (buf*64*HS)*2;
        const uint32_t Vbuf = sVb + (buf*64*HS)*2;
        const float*   mbuf = sMB[buf];

        // ---- S = Q K^T ----
        float sf[8][4];
        #pragma unroll
        for (int nt = 0; nt < 8; nt++)
            #pragma unroll
            for (int j = 0; j < 4; j++) sf[nt][j] = 0.f;

        #pragma unroll
        for (int kt = 0; kt < 4; kt++) {
            uint32_t a0, a1, a2, a3;
            ldm_x4(a0, a1, a2, a3, aQaddr + kt*32);
            #pragma unroll
            for (int nt = 0; nt < 8; nt += 2) {
                uint32_t b0, b1, b2, b3;
                ldm_x4(b0, b1, b2, b3, Kbuf + (nt*8*HS)*2 + kt*32 + bKoff);
                mma_f16(sf[nt],   a0, a1, a2, a3, b0, b1);
                mma_f16(sf[nt+1], a0, a1, a2, a3, b2, b3);
            }
        }

        // ---- softmax: bias + row max ----
        float mx0 = -1e30f, mx1 = -1e30f;
        #pragma unroll
        for (int nt = 0; nt < 8; nt++) {
            const float2 m2 = *(const float2*)(mbuf + nt*8 + 2*t);
            sf[nt][0] += m2.x; sf[nt][1] += m2.y;
            sf[nt][2] += m2.x; sf[nt][3] += m2.y;
            mx0 = fmaxf(mx0, fmaxf(sf[nt][0], sf[nt][1]));
            mx1 = fmaxf(mx1, fmaxf(sf[nt][2], sf[nt][3]));
        }
        mx0 = fmaxf(mx0, __shfl_xor_sync(0xffffffffu, mx0, 1));
        mx0 = fmaxf(mx0, __shfl_xor_sync(0xffffffffu, mx0, 2));
        mx1 = fmaxf(mx1, __shfl_xor_sync(0xffffffffu, mx1, 1));
        mx1 = fmaxf(mx1, __shfl_xor_sync(0xffffffffu, mx1, 2));

        // warp-uniform skip: alpha == 1 exactly when mi >= max(mx, -60)
        const bool skiprow = (mx0 <= mi0) && (mx1 <= mi1) &&
                             (mi0 >= -60.f) && (mi1 >= -60.f);
        float mn0, mn1;
        if (__all_sync(0xffffffffu, skiprow)) {
            mn0 = mi0; mn1 = mi1;           // alpha == 1, no rescale
        } else {
            mn0 = fmaxf(fmaxf(mi0, mx0), -60.f);
            mn1 = fmaxf(fmaxf(mi1, mx1), -60.f);
            const float al0 = ex2(mi0 - mn0);
            const float al1 = ex2(mi1 - mn1);
            mi0 = mn0; mi1 = mn1;
            #pragma unroll
            for (int nt = 0; nt < 8; nt++) {
                of[nt][0] *= al0; of[nt][1] *= al0;
                of[nt][2] *= al1; of[nt][3] *= al1;
            }
            ofs[0] *= al0; ofs[1] *= al0;
            ofs[2] *= al1; ofs[3] *= al1;
        }

        // p = exp2(sf - mn), computed directly in packed fp16 (PV A-frags)
        uint32_t ph[8][2];
        #pragma unroll
        for (int nt = 0; nt < 8; nt++) {
            ph[nt][0] = ex2_h2(sf[nt][0] - mn0, sf[nt][1] - mn0);
            ph[nt][1] = ex2_h2(sf[nt][2] - mn1, sf[nt][3] - mn1);
        }

        // ---- O += P @ V ; ones-column accumulates li ----
        #pragma unroll
        for (int kt = 0; kt < 4; kt++) {
            const uint32_t a0 = ph[2*kt][0];
            const uint32_t a1 = ph[2*kt][1];
            const uint32_t a2 = ph[2*kt+1][0];
            const uint32_t a3 = ph[2*kt+1][1];
            #pragma unroll
            for (int nt = 0; nt < 8; nt += 2) {
                uint32_t b0, b1, b2, b3;
                ldm_x4t(b0, b1, b2, b3, Vbuf + (kt*16*HS + nt*8)*2 + bVoff);
                mma_f16(of[nt],   a0, a1, a2, a3, b0, b1);
                mma_f16(of[nt+1], a0, a1, a2, a3, b2, b3);
            }
            uint32_t s0, s1;
            ldm_x2t(s0, s1, Vbuf + ((kt*16 + l15)*HS + 64)*2);
            mma_f16(ofs, a0, a1, a2, a3, s0, s1);
        }

        if (kc + 2 < NC) { issue_chunk(kc + 2); cp_commit(); }
    }

    // li lives in ones-column accumulator at t==0 lanes; broadcast in group
    const float li0 = __shfl_sync(0xffffffffu, ofs[0], lane & 28);
    const float li1 = __shfl_sync(0xffffffffu, ofs[2], lane & 28);
    const float inv0 = (li0 > 0.f) ? (1.0f / li0) : 0.f;
    const float inv1 = (li1 > 0.f) ? (1.0f / li1) : 0.f;
    const int t0 = qt*128 + r0 + g;
    const int t1 = t0 + 8;
    #pragma unroll
    for (int nt = 0; nt < 8; nt++) {
        const int dk = nt*8 + 2*t;
        __half2 w0 = __float22half2_rn(make_float2(of[nt][0] * inv0, of[nt][1] * inv0));
        __half2 w1 = __float22half2_rn(make_float2(of[nt][2] * inv1, of[nt][3] * inv1));
        *(__half2*)(CTX + ((size_t)b * Tc + t0) * Fc + h*DKc + dk) = w0;
        *(__half2*)(CTX + ((size_t)b * Tc + t1) * Fc + h*DKc + dk) = w1;
    }
}

// ---------------------------------------------------------------------------
// Launcher
// ---------------------------------------------------------------------------
extern "C" void kernel_launch(void* const* d_in, const int* in_sizes, int n_in,
                              void* d_out, int out_size)
{
    const float* query = (const float*)d_in[0];
    const float* key   = (const float*)d_in[1];
    const float* value = (const float*)d_in[2];
    const int*   amask = (const int*)  d_in[3];
    const float* Wq = (const float*)d_in[4];
    const float* bq = (const float*)d_in[5];
    const float* Wk = (const float*)d_in[6];
    const float* bk = (const float*)d_in[7];
    const float* Wv = (const float*)d_in[8];
    const float* bv = (const float*)d_in[9];
    const float* Wo = (const float*)d_in[10];
    const float* bo = (const float*)d_in[11];
    float* out = (float*)d_out;

    __half *pXh, *pWh, *pQ, *pK, *pV, *pCTX;
    float *pMB;
    cudaGetSymbolAddress((void**)&pXh, g_Xh);
    cudaGetSymbolAddress((void**)&pWh, g_Wh);
    cudaGetSymbolAddress((void**)&pQ,  g_Qh);
    cudaGetSymbolAddress((void**)&pK,  g_Kh);
    cudaGetSymbolAddress((void**)&pV,  g_Vh);
    cudaGetSymbolAddress((void**)&pCTX, g_CTXh);
    cudaGetSymbolAddress((void**)&pMB, g_MB);

    __half* xh[3] = { pXh, pXh + (size_t)Mdim*Fc, pXh + 2*(size_t)Mdim*Fc };
    __half* wh[4] = { pWh, pWh + (size_t)Fc*Fc, pWh + 2*(size_t)Fc*Fc, pWh + 3*(size_t)Fc*Fc };

    cudaFuncSetAttribute(attn_kernel,
                         cudaFuncAttributeMaxDynamicSharedMemorySize, AT_SMEM_BYTES);
    cudaFuncSetAttribute(gemm_h_kernel<0>,
                         cudaFuncAttributeMaxDynamicSharedMemorySize, G_SMEM_BYTES);
    cudaFuncSetAttribute(gemm_h_kernel<1>,
                         cudaFuncAttributeMaxDynamicSharedMemorySize, G_SMEM_BYTES);

    // 1) converts + mask bias
    CvtJobs JI;
    JI.src[0] = query; JI.src[1] = key; JI.src[2] = value; JI.src[3] = query;
    JI.dst[0] = xh[0]; JI.dst[1] = xh[1]; JI.dst[2] = xh[2]; JI.dst[3] = xh[0];
    cvt_kernel<<<dim3((Mdim*Fc)/(256*4), 3), 256>>>(JI);

    CvtJobs JW;
    JW.src[0] = Wq; JW.src[1] = Wk; JW.src[2] = Wv; JW.src[3] = Wo;
    JW.dst[0] = wh[0]; JW.dst[1] = wh[1]; JW.dst[2] = wh[2]; JW.dst[3] = wh[3];
    cvt_kernel<<<dim3((Fc*Fc)/(256*4), 4), 256>>>(JW);

    maskbias_kernel<<<(Bc*Tc)/256, 256>>>(amask, pMB);

    // 2) fused QKV projections (Q scaled by 0.125*log2e)
    QKVJobs P;
    P.A[0] = xh[0]; P.A[1] = xh[1]; P.A[2] = xh[2];
    P.W[0] = wh[0]; P.W[1] = wh[1]; P.W[2] = wh[2];
    P.bias[0] = bq; P.bias[1] = bk; P.bias[2] = bv;
    P.C[0] = pQ;    P.C[1] = pK;   P.C[2] = pV;
    gemm_h_kernel<1><<<dim3(Ndim/128, Mdim/128, 3), 256, G_SMEM_BYTES>>>(P, nullptr, nullptr, nullptr, nullptr);

    // 3) attention
    attn_kernel<<<dim3(Tc/128, Hc, Bc), 256, AT_SMEM_BYTES>>>(pQ, pK, pV, pMB, pCTX);

    // 4) output projection
    QKVJobs PD = {};
    gemm_h_kernel<0><<<dim3(Ndim/128, Mdim/128), 256, G_SMEM_BYTES>>>(PD, pCTX, wh[3], bo, out);
}

// round 11
// speedup vs baseline: 8.5450x; 1.0164x over previous
#include <cuda_runtime.h>
#include <cuda_bf16.h>
#include <cuda_fp16.h>
#include <cstdint>

// Problem constants
#define Bc 4
#define Tc 2048
#define Fc 512
#define Hc 8
#define DKc 64
#define Mdim (Bc*Tc)   // 8192
#define Ndim Fc        // 512
#define Kdim Fc        // 512

#define LOG2E 1.44269504088896340736f

// ---- fp16 mma m16n8k16, fp32 accumulate ----
__device__ __forceinline__ void mma_f16(float* c,
                                        uint32_t a0, uint32_t a1, uint32_t a2, uint32_t a3,
                                        uint32_t b0, uint32_t b1) {
    asm volatile("mma.sync.aligned.m16n8k16.row.col.f32.f16.f16.f32 "
                 "{%0,%1,%2,%3}, {%4,%5,%6,%7}, {%8,%9}, {%0,%1,%2,%3};"
                 : "+f"(c[0]), "+f"(c[1]), "+f"(c[2]), "+f"(c[3])
                 : "r"(a0), "r"(a1), "r"(a2), "r"(a3), "r"(b0), "r"(b1));
}
__device__ __forceinline__ uint32_t smem_u32(const void* p) {
    return (uint32_t)__cvta_generic_to_shared(p);
}
__device__ __forceinline__ void cp_async16(uint32_t dst, const void* src) {
    asm volatile("cp.async.cg.shared.global [%0], [%1], 16;" :: "r"(dst), "l"(src));
}
__device__ __forceinline__ void cp_commit() {
    asm volatile("cp.async.commit_group;");
}
__device__ __forceinline__ void ldm_x4(uint32_t& r0, uint32_t& r1, uint32_t& r2, uint32_t& r3,
                                       uint32_t addr) {
    asm volatile("ldmatrix.sync.aligned.m8n8.x4.shared.b16 {%0,%1,%2,%3}, [%4];"
                 : "=r"(r0), "=r"(r1), "=r"(r2), "=r"(r3) : "r"(addr));
}
__device__ __forceinline__ void ldm_x4t(uint32_t& r0, uint32_t& r1, uint32_t& r2, uint32_t& r3,
                                        uint32_t addr) {
    asm volatile("ldmatrix.sync.aligned.m8n8.x4.trans.shared.b16 {%0,%1,%2,%3}, [%4];"
                 : "=r"(r0), "=r"(r1), "=r"(r2), "=r"(r3) : "r"(addr));
}
__device__ __forceinline__ void ldm_x2t(uint32_t& r0, uint32_t& r1, uint32_t addr) {
    asm volatile("ldmatrix.sync.aligned.m8n8.x2.trans.shared.b16 {%0,%1}, [%2];"
                 : "=r"(r0), "=r"(r1) : "r"(addr));
}
__device__ __forceinline__ void ldm_x2(uint32_t& r0, uint32_t& r1, uint32_t addr) {
    asm volatile("ldmatrix.sync.aligned.m8n8.x2.shared.b16 {%0,%1}, [%2];"
                 : "=r"(r0), "=r"(r1) : "r"(addr));
}
__device__ __forceinline__ float ex2(float x) {
    float y; asm("ex2.approx.f32 %0, %1;" : "=f"(y) : "f"(x)); return y;
}
// ---- packed f16x2 ops ----
__device__ __forceinline__ uint32_t cvt_h2(float lo, float hi) {
    uint32_t d; asm("cvt.rn.f16x2.f32 %0, %1, %2;" : "=r"(d) : "f"(hi), "f"(lo)); return d;
}
__device__ __forceinline__ uint32_t add_h2u(uint32_t a, uint32_t b) {
    uint32_t d; asm("add.f16x2 %0, %1, %2;" : "=r"(d) : "r"(a), "r"(b)); return d;
}
__device__ __forceinline__ uint32_t sub_h2u(uint32_t a, uint32_t b) {
    uint32_t d; asm("sub.f16x2 %0, %1, %2;" : "=r"(d) : "r"(a), "r"(b)); return d;
}
__device__ __forceinline__ uint32_t max_h2u(uint32_t a, uint32_t b) {
    uint32_t d; asm("max.f16x2 %0, %1, %2;" : "=r"(d) : "r"(a), "r"(b)); return d;
}
__device__ __forceinline__ uint32_t prmtu(uint32_t a, uint32_t b, uint32_t c) {
    uint32_t d; asm("prmt.b32 %0, %1, %2, %3;" : "=r"(d) : "r"(a), "r"(b), "r"(c)); return d;
}
__device__ __forceinline__ uint32_t ex2_h2u(uint32_t a) {
    uint32_t d; asm("ex2.approx.f16x2 %0, %1;" : "=r"(d) : "r"(a)); return d;
}

// Scratch
__device__ __half g_Xh[3][(size_t)Mdim*Fc];
__device__ __half g_Wh[4][(size_t)Fc*Fc];
__device__ __half g_Qh[(size_t)Bc*Hc*Tc*DKc];
__device__ __half g_Kh[(size_t)Bc*Hc*Tc*DKc];
__device__ __half g_Vh[(size_t)Bc*Hc*Tc*DKc];
__device__ __half g_CTXh[(size_t)Mdim*Fc];
__device__ __half g_MBh[(size_t)Bc*Tc];      // fp16 mask bias: 0 or -inf

// ---------------------------------------------------------------------------
// fp32 -> fp16 convert
// ---------------------------------------------------------------------------
struct CvtJobs { const float* src[4]; __half* dst[4]; };

__global__ __launch_bounds__(256)
void cvt_kernel(CvtJobs J)
{
    const float* s = J.src[blockIdx.y];
    __half* d = J.dst[blockIdx.y];
    const size_t i = ((size_t)blockIdx.x * 256 + threadIdx.x) * 4;
    float4 v = *(const float4*)(s + i);
    __half2 h0 = __float22half2_rn(make_float2(v.x, v.y));
    __half2 h1 = __float22half2_rn(make_float2(v.z, v.w));
    uint2 o; o.x = *(uint32_t*)&h0; o.y = *(uint32_t*)&h1;
    *(uint2*)(d + i) = o;
}

__global__ __launch_bounds__(256)
void maskbias_kernel(const int* __restrict__ m, __half* __restrict__ mb)
{
    const int i = blockIdx.x * 256 + threadIdx.x;
    mb[i] = __ushort_as_half(m[i] ? (unsigned short)0x0000 : (unsigned short)0xFC00);
}

// ---------------------------------------------------------------------------
// fp16 GEMM, 3-stage cp.async pipeline (proven).
// MODE 0: C fp32 row-major. MODE 1: C fp16 scatter to [B,H,T,DK], scale(z==0).
// ---------------------------------------------------------------------------
#define HAS 40
#define G_STAGE_H (128*HAS)
#define G_SMEM_BYTES (2 * 3 * G_STAGE_H * 2)  // 61440

struct QKVJobs {
    const __half* A[3];
    const __half* W[3];
    const float* bias[3];
    __half* C[3];
};

template<int MODE>
__global__ __launch_bounds__(256, 2)
void gemm_h_kernel(QKVJobs P, const __half* Ao, const __half* Wo,
                   const float* biaso, float* Co)
{
    extern __shared__ __half gsm[];
    __half* sA = gsm;
    __half* sW = gsm + 3*G_STAGE_H;

    const int z = (MODE == 1) ? blockIdx.z : 0;
    const __half* A  = (MODE == 1) ? P.A[z] : Ao;
    const __half* W  = (MODE == 1) ? P.W[z] : Wo;
    const float* bias = (MODE == 1) ? P.bias[z] : biaso;
    const float scale = (MODE == 1 && z == 0) ? 0.125f * LOG2E : 1.0f;

    const int tid  = threadIdx.x;
    const int lane = tid & 31;
    const int w    = tid >> 5;
    const int g    = lane >> 2;
    const int t    = lane & 3;
    const int wm   = w & 3;
    const int wn   = w >> 2;
    const int bm = blockIdx.y * 128;
    const int bn = blockIdx.x * 128;

    const uint32_t sAb = smem_u32(sA);
    const uint32_t sWb = smem_u32(sW);

    auto issue = [&](int i) {
        const int buf = i % 3;
        const int k0 = i * 32;
        #pragma unroll
        for (int it = 0; it < 2; it++) {
            const int e = tid + it * 256;
            const int r = e >> 2, s = e & 3;
            cp_async16(sAb + (buf*G_STAGE_H + r*HAS + s*8)*2,
                       A + (size_t)(bm + r) * Kdim + k0 + s*8);
            cp_async16(sWb + (buf*G_STAGE_H + r*HAS + s*8)*2,
                       W + (size_t)(bn + r) * Kdim + k0 + s*8);
        }
    };

    float acc[2][8][4];
    #pragma unroll
    for (int mt = 0; mt < 2; mt++)
        #pragma unroll
        for (int nt = 0; nt < 8; nt++)
            #pragma unroll
            for (int j = 0; j < 4; j++) acc[mt][nt][j] = 0.f;

    issue(0); cp_commit();
    issue(1); cp_commit();

    const int NIT = Kdim / 32;   // 16
    for (int i = 0; i < NIT; i++) {
        const int buf = i % 3;
        if (i + 1 < NIT) asm volatile("cp.async.wait_group 1;");
        else             asm volatile("cp.async.wait_group 0;");
        __syncthreads();

        const uint32_t Ab = sAb + (buf*G_STAGE_H)*2;
        const uint32_t Wb = sWb + (buf*G_STAGE_H)*2;

        #pragma unroll
        for (int kt = 0; kt < 2; kt++) {
            uint32_t a[2][4];
            #pragma unroll
            for (int mt = 0; mt < 2; mt++) {
                const int row = wm*32 + mt*16 + (lane & 15);
                const int col = kt*16 + (lane >> 4) * 8;
                ldm_x4(a[mt][0], a[mt][1], a[mt][2], a[mt][3],
                       Ab + (row*HAS + col)*2);
            }
            #pragma unroll
            for (int nt = 0; nt < 8; nt++) {
                const int row = wn*64 + nt*8 + (lane & 7);
                const int col = kt*16 + ((lane >> 3) & 1) * 8;
                uint32_t b0, b1;
                ldm_x2(b0, b1, Wb + (row*HAS + col)*2);
                mma_f16(acc[0][nt], a[0][0], a[0][1], a[0][2], a[0][3], b0, b1);
                mma_f16(acc[1][nt], a[1][0], a[1][1], a[1][2], a[1][3], b0, b1);
            }
        }
        if (i + 2 < NIT) { issue(i + 2); cp_commit(); }
    }

    #pragma unroll
    for (int nt = 0; nt < 8; nt++) {
        const int col = bn + wn*64 + nt*8 + 2*t;
        const float2 bb = *(const float2*)(bias + col);
        #pragma unroll
        for (int mt = 0; mt < 2; mt++) {
            const int row0 = bm + wm*32 + mt*16 + g;
            const int row1 = row0 + 8;
            float2 v0, v1;
            v0.x = (acc[mt][nt][0] + bb.x) * scale; v0.y = (acc[mt][nt][1] + bb.y) * scale;
            v1.x = (acc[mt][nt][2] + bb.x) * scale; v1.y = (acc[mt][nt][3] + bb.y) * scale;
            if (MODE == 0) {
                *(float2*)(Co + (size_t)row0 * Ndim + col) = v0;
                *(float2*)(Co + (size_t)row1 * Ndim + col) = v1;
            } else {
                const int h  = col >> 6;
                const int dk = col & 63;
                const int b0_ = row0 >> 11, t0_ = row0 & 2047;
                const int b1_ = row1 >> 11, t1_ = row1 & 2047;
                __half2 h0 = __float22half2_rn(v0);
                __half2 h1 = __float22half2_rn(v1);
                *(__half2*)(P.C[z] + ((((size_t)b0_*Hc + h)*Tc + t0_) * DKc) + dk) = h0;
                *(__half2*)(P.C[z] + ((((size_t)b1_*Hc + h)*Tc + t1_) * DKc) + dk) = h1;
            }
        }
    }
}

// ---------------------------------------------------------------------------
// Flash attention: fp16 mma, 3-stage cp.async, P in registers, full f16x2
// softmax (bias/max/sub/exp packed), li via ones-column mma, rescale skip.
// Q pre-scaled by 0.125*log2e in projection. CTX fp16.
// ---------------------------------------------------------------------------
#define HS 72
#define SQ_OFF 0
#define SK_OFF (128*HS)
#define SV_OFF (SK_OFF + 3*64*HS)
#define AT_HALVES (SV_OFF + 3*64*HS)
#define AT_SMEM_BYTES (AT_HALVES * 2)   // 73728

__global__ __launch_bounds__(256, 2)
void attn_kernel(const __half* __restrict__ Q, const __half* __restrict__ K,
                 const __half* __restrict__ V, const __half* __restrict__ maskb,
                 __half* __restrict__ CTX)
{
    extern __shared__ __half hsm[];
    __half* sQ = hsm + SQ_OFF;          // [128][HS]
    __half* sK = hsm + SK_OFF;          // [3][64][HS]
    __half* sV = hsm + SV_OFF;          // [3][64][HS]; col 64 = 1.0 (ones col)
    __shared__ __half sMBh[3][64];      // fp16 mask bias per key

    const uint32_t sQb = smem_u32(sQ);
    const uint32_t sKb = smem_u32(sK);
    const uint32_t sVb = smem_u32(sV);
    const uint32_t sMBb = smem_u32(&sMBh[0][0]);
    const uint32_t* sMB32 = (const uint32_t*)&sMBh[0][0];

    const int tid  = threadIdx.x;
    const int lane = tid & 31;
    const int w    = tid >> 5;
    const int g    = lane >> 2;
    const int t    = lane & 3;
    const int r0   = w * 16;
    const int qt = blockIdx.x;
    const int h  = blockIdx.y;
    const int b  = blockIdx.z;

    const size_t head_base = (((size_t)b * Hc + h) * Tc) * DKc;
    const __half* Qb = Q + head_base + (size_t)qt * 128 * DKc;
    const __half* Kb = K + head_base;
    const __half* Vb = V + head_base;
    const __half* MBp = maskb + b * Tc;

    const int l15 = lane & 15;
    const int lhi = lane >> 4;
    const int l7  = lane & 7;
    const int lb8 = (lane >> 3) & 1;
    const uint32_t aQaddr = sQb + ((r0 + l15)*HS + lhi*8)*2;
    const uint32_t bKoff = ((l7 + lhi*8)*HS + lb8*8)*2;
    const uint32_t bVoff = (l15*HS + lhi*8)*2;

    // Ones-column init (col 64 = 1.0h, 65-71 = 0) for all 3 V buffers.
    for (int idx = tid; idx < 3*64; idx += 256) {
        uint4 v; v.x = 0x00003C00u; v.y = 0; v.z = 0; v.w = 0;
        *(uint4*)(sV + idx*HS + 64) = v;
    }

    // Q tile
    #pragma unroll
    for (int it = 0; it < 4; it++) {
        const int e = tid + it * 256;
        const int r = e >> 3, s = e & 7;
        cp_async16(sQb + (r*HS + s*8)*2, Qb + r*DKc + s*8);
    }

    auto issue_chunk = [&](int kc) {
        const int buf = kc % 3;
        const __half* Kc = Kb + (size_t)kc * 64 * DKc;
        const __half* Vc = Vb + (size_t)kc * 64 * DKc;
        #pragma unroll
        for (int it = 0; it < 2; it++) {
            const int e = tid + it * 256;
            const int r = e >> 3, s = e & 7;
            cp_async16(sKb + ((buf*64 + r)*HS + s*8)*2, Kc + r*DKc + s*8);
            cp_async16(sVb + ((buf*64 + r)*HS + s*8)*2, Vc + r*DKc + s*8);
        }
        if (tid < 8) cp_async16(sMBb + (buf*64 + tid*8)*2, MBp + kc*64 + tid*8);
    };

    issue_chunk(0); cp_commit();
    issue_chunk(1); cp_commit();

    float of[8][4];
    float ofs[4];                     // ones-column accumulator -> li
    float mi0 = -1e30f, mi1 = -1e30f;
    #pragma unroll
    for (int nt = 0; nt < 8; nt++)
        #pragma unroll
        for (int j = 0; j < 4; j++) of[nt][j] = 0.f;
    ofs[0] = ofs[1] = ofs[2] = ofs[3] = 0.f;

    const int NC = Tc / 64;   // 32
    for (int kc = 0; kc < NC; kc++) {
        const int buf = kc % 3;
        if (kc + 1 < NC) asm volatile("cp.async.wait_group 1;");
        else             asm volatile("cp.async.wait_group 0;");
        __syncthreads();

        const uint32_t Kbuf = sKb + (buf*64*HS)*2;
        const uint32_t Vbuf = sVb + (buf*64*HS)*2;

        // ---- S = Q K^T ----
        float sf[8][4];
        #pragma unroll
        for (int nt = 0; nt < 8; nt++)
            #pragma unroll
            for (int j = 0; j < 4; j++) sf[nt][j] = 0.f;

        #pragma unroll
        for (int kt = 0; kt < 4; kt++) {
            uint32_t a0, a1, a2, a3;
            ldm_x4(a0, a1, a2, a3, aQaddr + kt*32);
            #pragma unroll
            for (int nt = 0; nt < 8; nt += 2) {
                uint32_t b0, b1, b2, b3;
                ldm_x4(b0, b1, b2, b3, Kbuf + (nt*8*HS)*2 + kt*32 + bKoff);
                mma_f16(sf[nt],   a0, a1, a2, a3, b0, b1);
                mma_f16(sf[nt+1], a0, a1, a2, a3, b2, b3);
            }
        }

        // ---- softmax, fully in packed f16x2 ----
        // dh[nt][0] = h2(scores row0, keys 2t/2t+1) + maskbias; dh[nt][1] row1
        uint32_t dh[8][2];
        #pragma unroll
        for (int nt = 0; nt < 8; nt++) {
            const uint32_t mb2 = sMB32[buf*32 + nt*4 + t];
            dh[nt][0] = add_h2u(cvt_h2(sf[nt][0], sf[nt][1]), mb2);
            dh[nt][1] = add_h2u(cvt_h2(sf[nt][2], sf[nt][3]), mb2);
        }
        // per-row max trees
        uint32_t m0 = dh[0][0], m1 = dh[0][1];
        #pragma unroll
        for (int nt = 1; nt < 8; nt++) {
            m0 = max_h2u(m0, dh[nt][0]);
            m1 = max_h2u(m1, dh[nt][1]);
        }
        m0 = max_h2u(m0, prmtu(m0, m0, 0x1032));   // fold halves
        m1 = max_h2u(m1, prmtu(m1, m1, 0x1032));
        uint32_t mx2 = prmtu(m0, m1, 0x5410);      // lo=row0max, hi=row1max
        mx2 = max_h2u(mx2, __shfl_xor_sync(0xffffffffu, mx2, 1));
        mx2 = max_h2u(mx2, __shfl_xor_sync(0xffffffffu, mx2, 2));
        const __half2 mxh = *(const __half2*)&mx2;
        const float mx0 = __low2float(mxh);
        const float mx1 = __high2float(mxh);

        // warp-uniform alpha==1 skip
        const bool skiprow = (mx0 <= mi0) && (mx1 <= mi1) &&
                             (mi0 >= -60.f) && (mi1 >= -60.f);
        float mn0, mn1;
        if (__all_sync(0xffffffffu, skiprow)) {
            mn0 = mi0; mn1 = mi1;
        } else {
            mn0 = fmaxf(fmaxf(mi0, mx0), -60.f);
            mn1 = fmaxf(fmaxf(mi1, mx1), -60.f);
            const float al0 = ex2(mi0 - mn0);
            const float al1 = ex2(mi1 - mn1);
            mi0 = mn0; mi1 = mn1;
            #pragma unroll
            for (int nt = 0; nt < 8; nt++) {
                of[nt][0] *= al0; of[nt][1] *= al0;
                of[nt][2] *= al1; of[nt][3] *= al1;
            }
            ofs[0] *= al0; ofs[1] *= al0;
            ofs[2] *= al1; ofs[3] *= al1;
        }

        // p = exp2(d - mn), packed; results are the PV A-fragments
        __half2 mh0 = __float2half2_rn(mn0);
        __half2 mh1 = __float2half2_rn(mn1);
        const uint32_t mn0h2 = *(uint32_t*)&mh0;
        const uint32_t mn1h2 = *(uint32_t*)&mh1;
        uint32_t ph[8][2];
        #pragma unroll
        for (int nt = 0; nt < 8; nt++) {
            ph[nt][0] = ex2_h2u(sub_h2u(dh[nt][0], mn0h2));
            ph[nt][1] = ex2_h2u(sub_h2u(dh[nt][1], mn1h2));
        }

        // ---- O += P @ V ; ones-column accumulates li ----
        #pragma unroll
        for (int kt = 0; kt < 4; kt++) {
            const uint32_t a0 = ph[2*kt][0];
            const uint32_t a1 = ph[2*kt][1];
            const uint32_t a2 = ph[2*kt+1][0];
            const uint32_t a3 = ph[2*kt+1][1];
            #pragma unroll
            for (int nt = 0; nt < 8; nt += 2) {
                uint32_t b0, b1, b2, b3;
                ldm_x4t(b0, b1, b2, b3, Vbuf + (kt*16*HS + nt*8)*2 + bVoff);
                mma_f16(of[nt],   a0, a1, a2, a3, b0, b1);
                mma_f16(of[nt+1], a0, a1, a2, a3, b2, b3);
            }
            uint32_t s0, s1;
            ldm_x2t(s0, s1, Vbuf + ((kt*16 + l15)*HS + 64)*2);
            mma_f16(ofs, a0, a1, a2, a3, s0, s1);
        }

        if (kc + 2 < NC) { issue_chunk(kc + 2); cp_commit(); }
    }

    // li lives in ones-column accumulator at t==0 lanes; broadcast in group
    const float li0 = __shfl_sync(0xffffffffu, ofs[0], lane & 28);
    const float li1 = __shfl_sync(0xffffffffu, ofs[2], lane & 28);
    const float inv0 = (li0 > 0.f) ? (1.0f / li0) : 0.f;
    const float inv1 = (li1 > 0.f) ? (1.0f / li1) : 0.f;
    const int t0 = qt*128 + r0 + g;
    const int t1 = t0 + 8;
    #pragma unroll
    for (int nt = 0; nt < 8; nt++) {
        const int dk = nt*8 + 2*t;
        __half2 w0 = __float22half2_rn(make_float2(of[nt][0] * inv0, of[nt][1] * inv0));
        __half2 w1 = __float22half2_rn(make_float2(of[nt][2] * inv1, of[nt][3] * inv1));
        *(__half2*)(CTX + ((size_t)b * Tc + t0) * Fc + h*DKc + dk) = w0;
        *(__half2*)(CTX + ((size_t)b * Tc + t1) * Fc + h*DKc + dk) = w1;
    }
}

// ---------------------------------------------------------------------------
// Launcher
// ---------------------------------------------------------------------------
extern "C" void kernel_launch(void* const* d_in, const int* in_sizes, int n_in,
                              void* d_out, int out_size)
{
    const float* query = (const float*)d_in[0];
    const float* key   = (const float*)d_in[1];
    const float* value = (const float*)d_in[2];
    const int*   amask = (const int*)  d_in[3];
    const float* Wq = (const float*)d_in[4];
    const float* bq = (const float*)d_in[5];
    const float* Wk = (const float*)d_in[6];
    const float* bk = (const float*)d_in[7];
    const float* Wv = (const float*)d_in[8];
    const float* bv = (const float*)d_in[9];
    const float* Wo = (const float*)d_in[10];
    const float* bo = (const float*)d_in[11];
    float* out = (float*)d_out;

    __half *pXh, *pWh, *pQ, *pK, *pV, *pCTX, *pMB;
    cudaGetSymbolAddress((void**)&pXh, g_Xh);
    cudaGetSymbolAddress((void**)&pWh, g_Wh);
    cudaGetSymbolAddress((void**)&pQ,  g_Qh);
    cudaGetSymbolAddress((void**)&pK,  g_Kh);
    cudaGetSymbolAddress((void**)&pV,  g_Vh);
    cudaGetSymbolAddress((void**)&pCTX, g_CTXh);
    cudaGetSymbolAddress((void**)&pMB, g_MBh);

    __half* xh[3] = { pXh, pXh + (size_t)Mdim*Fc, pXh + 2*(size_t)Mdim*Fc };
    __half* wh[4] = { pWh, pWh + (size_t)Fc*Fc, pWh + 2*(size_t)Fc*Fc, pWh + 3*(size_t)Fc*Fc };

    cudaFuncSetAttribute(attn_kernel,
                         cudaFuncAttributeMaxDynamicSharedMemorySize, AT_SMEM_BYTES);
    cudaFuncSetAttribute(gemm_h_kernel<0>,
                         cudaFuncAttributeMaxDynamicSharedMemorySize, G_SMEM_BYTES);
    cudaFuncSetAttribute(gemm_h_kernel<1>,
                         cudaFuncAttributeMaxDynamicSharedMemorySize, G_SMEM_BYTES);

    // 1) converts + mask bias (fp16)
    CvtJobs JI;
    JI.src[0] = query; JI.src[1] = key; JI.src[2] = value; JI.src[3] = query;
    JI.dst[0] = xh[0]; JI.dst[1] = xh[1]; JI.dst[2] = xh[2]; JI.dst[3] = xh[0];
    cvt_kernel<<<dim3((Mdim*Fc)/(256*4), 3), 256>>>(JI);

    CvtJobs JW;
    JW.src[0] = Wq; JW.src[1] = Wk; JW.src[2] = Wv; JW.src[3] = Wo;
    JW.dst[0] = wh[0]; JW.dst[1] = wh[1]; JW.dst[2] = wh[2]; JW.dst[3] = wh[3];
    cvt_kernel<<<dim3((Fc*Fc)/(256*4), 4), 256>>>(JW);

    maskbias_kernel<<<(Bc*Tc)/256, 256>>>(amask, pMB);

    // 2) fused QKV projections (Q scaled by 0.125*log2e)
    QKVJobs P;
    P.A[0] = xh[0]; P.A[1] = xh[1]; P.A[2] = xh[2];
    P.W[0] = wh[0]; P.W[1] = wh[1]; P.W[2] = wh[2];
    P.bias[0] = bq; P.bias[1] = bk; P.bias[2] = bv;
    P.C[0] = pQ;    P.C[1] = pK;   P.C[2] = pV;
    gemm_h_kernel<1><<<dim3(Ndim/128, Mdim/128, 3), 256, G_SMEM_BYTES>>>(P, nullptr, nullptr, nullptr, nullptr);

    // 3) attention
    attn_kernel<<<dim3(Tc/128, Hc, Bc), 256, AT_SMEM_BYTES>>>(pQ, pK, pV, pMB, pCTX);

    // 4) output projection
    QKVJobs PD = {};
    gemm_h_kernel<0><<<dim3(Ndim/128, Mdim/128), 256, G_SMEM_BYTES>>>(PD, pCTX, wh[3], bo, out);
}

// round 12
// speedup vs baseline: 10.9735x; 1.2842x over previous
#include <cuda_runtime.h>
#include <cuda_bf16.h>
#include <cuda_fp16.h>
#include <cstdint>

// Problem constants
#define Bc 4
#define Tc 2048
#define Fc 512
#define Hc 8
#define DKc 64
#define Mdim (Bc*Tc)   // 8192
#define Ndim Fc        // 512
#define Kdim Fc        // 512

#define LOG2E 1.44269504088896340736f

// ---- fp16 mma m16n8k16, fp32 accumulate ----
__device__ __forceinline__ void mma_f16(float* c,
                                        uint32_t a0, uint32_t a1, uint32_t a2, uint32_t a3,
                                        uint32_t b0, uint32_t b1) {
    asm volatile("mma.sync.aligned.m16n8k16.row.col.f32.f16.f16.f32 "
                 "{%0,%1,%2,%3}, {%4,%5,%6,%7}, {%8,%9}, {%0,%1,%2,%3};"
                 : "+f"(c[0]), "+f"(c[1]), "+f"(c[2]), "+f"(c[3])
                 : "r"(a0), "r"(a1), "r"(a2), "r"(a3), "r"(b0), "r"(b1));
}
__device__ __forceinline__ uint32_t smem_u32(const void* p) {
    return (uint32_t)__cvta_generic_to_shared(p);
}
__device__ __forceinline__ void cp_async16(uint32_t dst, const void* src) {
    asm volatile("cp.async.cg.shared.global [%0], [%1], 16;" :: "r"(dst), "l"(src));
}
__device__ __forceinline__ void cp_commit() {
    asm volatile("cp.async.commit_group;");
}
__device__ __forceinline__ void ldm_x4(uint32_t& r0, uint32_t& r1, uint32_t& r2, uint32_t& r3,
                                       uint32_t addr) {
    asm volatile("ldmatrix.sync.aligned.m8n8.x4.shared.b16 {%0,%1,%2,%3}, [%4];"
                 : "=r"(r0), "=r"(r1), "=r"(r2), "=r"(r3) : "r"(addr));
}
__device__ __forceinline__ void ldm_x4t(uint32_t& r0, uint32_t& r1, uint32_t& r2, uint32_t& r3,
                                        uint32_t addr) {
    asm volatile("ldmatrix.sync.aligned.m8n8.x4.trans.shared.b16 {%0,%1,%2,%3}, [%4];"
                 : "=r"(r0), "=r"(r1), "=r"(r2), "=r"(r3) : "r"(addr));
}
__device__ __forceinline__ void ldm_x2t(uint32_t& r0, uint32_t& r1, uint32_t addr) {
    asm volatile("ldmatrix.sync.aligned.m8n8.x2.trans.shared.b16 {%0,%1}, [%2];"
                 : "=r"(r0), "=r"(r1) : "r"(addr));
}
__device__ __forceinline__ void ldm_x2(uint32_t& r0, uint32_t& r1, uint32_t addr) {
    asm volatile("ldmatrix.sync.aligned.m8n8.x2.shared.b16 {%0,%1}, [%2];"
                 : "=r"(r0), "=r"(r1) : "r"(addr));
}
__device__ __forceinline__ float ex2(float x) {
    float y; asm("ex2.approx.f32 %0, %1;" : "=f"(y) : "f"(x)); return y;
}
// ---- packed f16x2 ops ----
__device__ __forceinline__ uint32_t cvt_h2(float lo, float hi) {
    uint32_t d; asm("cvt.rn.f16x2.f32 %0, %1, %2;" : "=r"(d) : "f"(hi), "f"(lo)); return d;
}
__device__ __forceinline__ uint32_t add_h2u(uint32_t a, uint32_t b) {
    uint32_t d; asm("add.f16x2 %0, %1, %2;" : "=r"(d) : "r"(a), "r"(b)); return d;
}
__device__ __forceinline__ uint32_t sub_h2u(uint32_t a, uint32_t b) {
    uint32_t d; asm("sub.f16x2 %0, %1, %2;" : "=r"(d) : "r"(a), "r"(b)); return d;
}
__device__ __forceinline__ uint32_t max_h2u(uint32_t a, uint32_t b) {
    uint32_t d; asm("max.f16x2 %0, %1, %2;" : "=r"(d) : "r"(a), "r"(b)); return d;
}
__device__ __forceinline__ uint32_t prmtu(uint32_t a, uint32_t b, uint32_t c) {
    uint32_t d; asm("prmt.b32 %0, %1, %2, %3;" : "=r"(d) : "r"(a), "r"(b), "r"(c)); return d;
}
__device__ __forceinline__ uint32_t ex2_h2u(uint32_t a) {
    uint32_t d; asm("ex2.approx.f16x2 %0, %1;" : "=r"(d) : "r"(a)); return d;
}

// Scratch
__device__ __half g_Xh[3][(size_t)Mdim*Fc];
__device__ __half g_Wh[4][(size_t)Fc*Fc];
__device__ __half g_Qh[(size_t)Bc*Hc*Tc*DKc];
__device__ __half g_Kh[(size_t)Bc*Hc*Tc*DKc];   // compacted per (b,h): rows 0..nv[b)
__device__ __half g_Vh[(size_t)Bc*Hc*Tc*DKc];   // compacted; rows >= nv stay 0
__device__ __half g_CTXh[(size_t)Mdim*Fc];
__device__ __half g_MBh[(size_t)Bc*Tc];         // compacted bias: 0 (j<nv) / -inf
__device__ int    g_RK[(size_t)Bc*Tc];          // rank of key t among valid, -1 if masked
__device__ int    g_NV[Bc];                     // valid-key count per batch

// ---------------------------------------------------------------------------
// fp32 -> fp16 convert
// ---------------------------------------------------------------------------
struct CvtJobs { const float* src[4]; __half* dst[4]; };

__global__ __launch_bounds__(256)
void cvt_kernel(CvtJobs J)
{
    const float* s = J.src[blockIdx.y];
    __half* d = J.dst[blockIdx.y];
    const size_t i = ((size_t)blockIdx.x * 256 + threadIdx.x) * 4;
    float4 v = *(const float4*)(s + i);
    __half2 h0 = __float22half2_rn(make_float2(v.x, v.y));
    __half2 h1 = __float22half2_rn(make_float2(v.z, v.w));
    uint2 o; o.x = *(uint32_t*)&h0; o.y = *(uint32_t*)&h1;
    *(uint2*)(d + i) = o;
}

// ---------------------------------------------------------------------------
// Mask compaction: rank (stable prefix), nv count, compacted fp16 bias array.
// One block per batch, 256 threads x 8 keys.
// ---------------------------------------------------------------------------
__global__ __launch_bounds__(256)
void compact_mask_kernel(const int* __restrict__ m, int* __restrict__ rank,
                         __half* __restrict__ mbc, int* __restrict__ nv)
{
    const int b = blockIdx.x;
    const int tid = threadIdx.x;
    const int lane = tid & 31, wid = tid >> 5;
    const int* mb_ = m + b * Tc;

    int loc[8], s = 0;
    #pragma unroll
    for (int j = 0; j < 8; j++) { loc[j] = mb_[tid*8 + j] ? 1 : 0; s += loc[j]; }

    int inc = s;
    #pragma unroll
    for (int off = 1; off < 32; off <<= 1) {
        int v = __shfl_up_sync(0xffffffffu, inc, off);
        if (lane >= off) inc += v;
    }
    __shared__ int wsum[8], wpre[8], nvsh;
    if (lane == 31) wsum[wid] = inc;
    __syncthreads();
    if (tid == 0) {
        int acc = 0;
        #pragma unroll
        for (int i = 0; i < 8; i++) { wpre[i] = acc; acc += wsum[i]; }
        nv[b] = acc; nvsh = acc;
    }
    __syncthreads();

    int ex = wpre[wid] + inc - s;   // exclusive prefix of this thread's block
    int* rk = rank + b * Tc;
    #pragma unroll
    for (int j = 0; j < 8; j++) {
        rk[tid*8 + j] = loc[j] ? ex : -1;
        ex += loc[j];
    }

    const int NV = nvsh;
    __half* mo = mbc + b * Tc;
    for (int p = tid; p < Tc; p += 256)
        mo[p] = __ushort_as_half(p < NV ? (unsigned short)0x0000
                                        : (unsigned short)0xFC00);
}

// ---------------------------------------------------------------------------
// fp16 GEMM, 3-stage cp.async pipeline (proven).
// MODE 0: C fp32 row-major.
// MODE 1: C fp16 scatter to [B,H,T,DK]; z==0 (Q): scale + identity t;
//         z==1/2 (K/V): scatter to rank[t] (compaction), skip masked rows.
// ---------------------------------------------------------------------------
#define HAS 40
#define G_STAGE_H (128*HAS)
#define G_SMEM_BYTES (2 * 3 * G_STAGE_H * 2)  // 61440

struct QKVJobs {
    const __half* A[3];
    const __half* W[3];
    const float* bias[3];
    __half* C[3];
};

template<int MODE>
__global__ __launch_bounds__(256, 2)
void gemm_h_kernel(QKVJobs P, const __half* Ao, const __half* Wo,
                   const float* biaso, float* Co, const int* __restrict__ rankArr)
{
    extern __shared__ __half gsm[];
    __half* sA = gsm;
    __half* sW = gsm + 3*G_STAGE_H;

    const int z = (MODE == 1) ? blockIdx.z : 0;
    const __half* A  = (MODE == 1) ? P.A[z] : Ao;
    const __half* W  = (MODE == 1) ? P.W[z] : Wo;
    const float* bias = (MODE == 1) ? P.bias[z] : biaso;
    const float scale = (MODE == 1 && z == 0) ? 0.125f * LOG2E : 1.0f;

    const int tid  = threadIdx.x;
    const int lane = tid & 31;
    const int w    = tid >> 5;
    const int g    = lane >> 2;
    const int t    = lane & 3;
    const int wm   = w & 3;
    const int wn   = w >> 2;
    const int bm = blockIdx.y * 128;
    const int bn = blockIdx.x * 128;

    const uint32_t sAb = smem_u32(sA);
    const uint32_t sWb = smem_u32(sW);

    auto issue = [&](int i) {
        const int buf = i % 3;
        const int k0 = i * 32;
        #pragma unroll
        for (int it = 0; it < 2; it++) {
            const int e = tid + it * 256;
            const int r = e >> 2, s = e & 3;
            cp_async16(sAb + (buf*G_STAGE_H + r*HAS + s*8)*2,
                       A + (size_t)(bm + r) * Kdim + k0 + s*8);
            cp_async16(sWb + (buf*G_STAGE_H + r*HAS + s*8)*2,
                       W + (size_t)(bn + r) * Kdim + k0 + s*8);
        }
    };

    float acc[2][8][4];
    #pragma unroll
    for (int mt = 0; mt < 2; mt++)
        #pragma unroll
        for (int nt = 0; nt < 8; nt++)
            #pragma unroll
            for (int j = 0; j < 4; j++) acc[mt][nt][j] = 0.f;

    issue(0); cp_commit();
    issue(1); cp_commit();

    const int NIT = Kdim / 32;   // 16
    for (int i = 0; i < NIT; i++) {
        const int buf = i % 3;
        if (i + 1 < NIT) asm volatile("cp.async.wait_group 1;");
        else             asm volatile("cp.async.wait_group 0;");
        __syncthreads();

        const uint32_t Ab = sAb + (buf*G_STAGE_H)*2;
        const uint32_t Wb = sWb + (buf*G_STAGE_H)*2;

        #pragma unroll
        for (int kt = 0; kt < 2; kt++) {
            uint32_t a[2][4];
            #pragma unroll
            for (int mt = 0; mt < 2; mt++) {
                const int row = wm*32 + mt*16 + (lane & 15);
                const int col = kt*16 + (lane >> 4) * 8;
                ldm_x4(a[mt][0], a[mt][1], a[mt][2], a[mt][3],
                       Ab + (row*HAS + col)*2);
            }
            #pragma unroll
            for (int nt = 0; nt < 8; nt++) {
                const int row = wn*64 + nt*8 + (lane & 7);
                const int col = kt*16 + ((lane >> 3) & 1) * 8;
                uint32_t b0, b1;
                ldm_x2(b0, b1, Wb + (row*HAS + col)*2);
                mma_f16(acc[0][nt], a[0][0], a[0][1], a[0][2], a[0][3], b0, b1);
                mma_f16(acc[1][nt], a[1][0], a[1][1], a[1][2], a[1][3], b0, b1);
            }
        }
        if (i + 2 < NIT) { issue(i + 2); cp_commit(); }
    }

    if (MODE == 0) {
        #pragma unroll
        for (int nt = 0; nt < 8; nt++) {
            const int col = bn + wn*64 + nt*8 + 2*t;
            const float2 bb = *(const float2*)(bias + col);
            #pragma unroll
            for (int mt = 0; mt < 2; mt++) {
                const int row0 = bm + wm*32 + mt*16 + g;
                const int row1 = row0 + 8;
                float2 v0, v1;
                v0.x = acc[mt][nt][0] + bb.x; v0.y = acc[mt][nt][1] + bb.y;
                v1.x = acc[mt][nt][2] + bb.x; v1.y = acc[mt][nt][3] + bb.y;
                *(float2*)(Co + (size_t)row0 * Ndim + col) = v0;
                *(float2*)(Co + (size_t)row1 * Ndim + col) = v1;
            }
        }
    } else {
        #pragma unroll
        for (int mt = 0; mt < 2; mt++) {
            const int row0 = bm + wm*32 + mt*16 + g;
            const int row1 = row0 + 8;
            const int b0_ = row0 >> 11, t0_ = row0 & 2047;
            const int b1_ = row1 >> 11, t1_ = row1 & 2047;
            int d0 = t0_, d1 = t1_;
            if (z != 0) {                       // K/V: compact to rank position
                d0 = rankArr[b0_*Tc + t0_];
                d1 = rankArr[b1_*Tc + t1_];
            }
            #pragma unroll
            for (int nt = 0; nt < 8; nt++) {
                const int col = bn + wn*64 + nt*8 + 2*t;
                const float2 bb = *(const float2*)(bias + col);
                const int h  = col >> 6;
                const int dk = col & 63;
                if (d0 >= 0) {
                    float2 v0;
                    v0.x = (acc[mt][nt][0] + bb.x) * scale;
                    v0.y = (acc[mt][nt][1] + bb.y) * scale;
                    *(__half2*)(P.C[z] + ((((size_t)b0_*Hc + h)*Tc + d0) * DKc) + dk)
                        = __float22half2_rn(v0);
                }
                if (d1 >= 0) {
                    float2 v1;
                    v1.x = (acc[mt][nt][2] + bb.x) * scale;
                    v1.y = (acc[mt][nt][3] + bb.y) * scale;
                    *(__half2*)(P.C[z] + ((((size_t)b1_*Hc + h)*Tc + d1) * DKc) + dk)
                        = __float22half2_rn(v1);
                }
            }
        }
    }
}

// ---------------------------------------------------------------------------
// Flash attention over COMPACTED keys (nv[b] valid keys; rest padded with
// zero K/V rows + -inf bias). fp16 mma, 3-stage cp.async, P in registers,
// f16x2 softmax, li via ones-column mma. Q pre-scaled. CTX fp16.
// ---------------------------------------------------------------------------
#define HS 72
#define SQ_OFF 0
#define SK_OFF (128*HS)
#define SV_OFF (SK_OFF + 3*64*HS)
#define AT_HALVES (SV_OFF + 3*64*HS)
#define AT_SMEM_BYTES (AT_HALVES * 2)   // 73728

__global__ __launch_bounds__(256, 2)
void attn_kernel(const __half* __restrict__ Q, const __half* __restrict__ K,
                 const __half* __restrict__ V, const __half* __restrict__ maskb,
                 const int* __restrict__ nv, __half* __restrict__ CTX)
{
    extern __shared__ __half hsm[];
    __half* sQ = hsm + SQ_OFF;          // [128][HS]
    __half* sK = hsm + SK_OFF;          // [3][64][HS]
    __half* sV = hsm + SV_OFF;          // [3][64][HS]; col 64 = 1.0 (ones col)
    __shared__ __half sMBh[3][64];

    const uint32_t sQb = smem_u32(sQ);
    const uint32_t sKb = smem_u32(sK);
    const uint32_t sVb = smem_u32(sV);
    const uint32_t sMBb = smem_u32(&sMBh[0][0]);
    const uint32_t* sMB32 = (const uint32_t*)&sMBh[0][0];

    const int tid  = threadIdx.x;
    const int lane = tid & 31;
    const int w    = tid >> 5;
    const int g    = lane >> 2;
    const int t    = lane & 3;
    const int r0   = w * 16;
    const int qt = blockIdx.x;
    const int h  = blockIdx.y;
    const int b  = blockIdx.z;

    const int NV = nv[b];
    const int NC = (NV + 63) >> 6;      // chunks of 64 compacted keys

    const size_t head_base = (((size_t)b * Hc + h) * Tc) * DKc;
    const __half* Qb = Q + head_base + (size_t)qt * 128 * DKc;
    const __half* Kb = K + head_base;
    const __half* Vb = V + head_base;
    const __half* MBp = maskb + b * Tc;

    const int l15 = lane & 15;
    const int lhi = lane >> 4;
    const int l7  = lane & 7;
    const int lb8 = (lane >> 3) & 1;
    const uint32_t aQaddr = sQb + ((r0 + l15)*HS + lhi*8)*2;
    const uint32_t bKoff = ((l7 + lhi*8)*HS + lb8*8)*2;
    const uint32_t bVoff = (l15*HS + lhi*8)*2;

    // Ones-column init for all 3 V buffers.
    for (int idx = tid; idx < 3*64; idx += 256) {
        uint4 v; v.x = 0x00003C00u; v.y = 0; v.z = 0; v.w = 0;
        *(uint4*)(sV + idx*HS + 64) = v;
    }

    // Q tile
    #pragma unroll
    for (int it = 0; it < 4; it++) {
        const int e = tid + it * 256;
        const int r = e >> 3, s = e & 7;
        cp_async16(sQb + (r*HS + s*8)*2, Qb + r*DKc + s*8);
    }

    auto issue_chunk = [&](int kc) {
        const int buf = kc % 3;
        const __half* Kc = Kb + (size_t)kc * 64 * DKc;
        const __half* Vc = Vb + (size_t)kc * 64 * DKc;
        #pragma unroll
        for (int it = 0; it < 2; it++) {
            const int e = tid + it * 256;
            const int r = e >> 3, s = e & 7;
            cp_async16(sKb + ((buf*64 + r)*HS + s*8)*2, Kc + r*DKc + s*8);
            cp_async16(sVb + ((buf*64 + r)*HS + s*8)*2, Vc + r*DKc + s*8);
        }
        if (tid < 8) cp_async16(sMBb + (buf*64 + tid*8)*2, MBp + kc*64 + tid*8);
    };

    if (NC > 0) issue_chunk(0);
    cp_commit();
    if (NC > 1) { issue_chunk(1); cp_commit(); }

    float of[8][4];
    float ofs[4];
    float mi0 = -1e30f, mi1 = -1e30f;
    #pragma unroll
    for (int nt = 0; nt < 8; nt++)
        #pragma unroll
        for (int j = 0; j < 4; j++) of[nt][j] = 0.f;
    ofs[0] = ofs[1] = ofs[2] = ofs[3] = 0.f;

    for (int kc = 0; kc < NC; kc++) {
        const int buf = kc % 3;
        if (kc + 1 < NC) asm volatile("cp.async.wait_group 1;");
        else             asm volatile("cp.async.wait_group 0;");
        __syncthreads();

        const uint32_t Kbuf = sKb + (buf*64*HS)*2;
        const uint32_t Vbuf = sVb + (buf*64*HS)*2;

        // ---- S = Q K^T ----
        float sf[8][4];
        #pragma unroll
        for (int nt = 0; nt < 8; nt++)
            #pragma unroll
            for (int j = 0; j < 4; j++) sf[nt][j] = 0.f;

        #pragma unroll
        for (int kt = 0; kt < 4; kt++) {
            uint32_t a0, a1, a2, a3;
            ldm_x4(a0, a1, a2, a3, aQaddr + kt*32);
            #pragma unroll
            for (int nt = 0; nt < 8; nt += 2) {
                uint32_t b0, b1, b2, b3;
                ldm_x4(b0, b1, b2, b3, Kbuf + (nt*8*HS)*2 + kt*32 + bKoff);
                mma_f16(sf[nt],   a0, a1, a2, a3, b0, b1);
                mma_f16(sf[nt+1], a0, a1, a2, a3, b2, b3);
            }
        }

        // ---- softmax, packed f16x2 ----
        uint32_t dh[8][2];
        #pragma unroll
        for (int nt = 0; nt < 8; nt++) {
            const uint32_t mb2 = sMB32[buf*32 + nt*4 + t];
            dh[nt][0] = add_h2u(cvt_h2(sf[nt][0], sf[nt][1]), mb2);
            dh[nt][1] = add_h2u(cvt_h2(sf[nt][2], sf[nt][3]), mb2);
        }
        uint32_t m0 = dh[0][0], m1 = dh[0][1];
        #pragma unroll
        for (int nt = 1; nt < 8; nt++) {
            m0 = max_h2u(m0, dh[nt][0]);
            m1 = max_h2u(m1, dh[nt][1]);
        }
        m0 = max_h2u(m0, prmtu(m0, m0, 0x1032));
        m1 = max_h2u(m1, prmtu(m1, m1, 0x1032));
        uint32_t mx2 = prmtu(m0, m1, 0x5410);
        mx2 = max_h2u(mx2, __shfl_xor_sync(0xffffffffu, mx2, 1));
        mx2 = max_h2u(mx2, __shfl_xor_sync(0xffffffffu, mx2, 2));
        const __half2 mxh = *(const __half2*)&mx2;
        const float mx0 = __low2float(mxh);
        const float mx1 = __high2float(mxh);

        const bool skiprow = (mx0 <= mi0) && (mx1 <= mi1) &&
                             (mi0 >= -60.f) && (mi1 >= -60.f);
        float mn0, mn1;
        if (__all_sync(0xffffffffu, skiprow)) {
            mn0 = mi0; mn1 = mi1;
        } else {
            mn0 = fmaxf(fmaxf(mi0, mx0), -60.f);
            mn1 = fmaxf(fmaxf(mi1, mx1), -60.f);
            const float al0 = ex2(mi0 - mn0);
            const float al1 = ex2(mi1 - mn1);
            mi0 = mn0; mi1 = mn1;
            #pragma unroll
            for (int nt = 0; nt < 8; nt++) {
                of[nt][0] *= al0; of[nt][1] *= al0;
                of[nt][2] *= al1; of[nt][3] *= al1;
            }
            ofs[0] *= al0; ofs[1] *= al0;
            ofs[2] *= al1; ofs[3] *= al1;
        }

        __half2 mh0 = __float2half2_rn(mn0);
        __half2 mh1 = __float2half2_rn(mn1);
        const uint32_t mn0h2 = *(uint32_t*)&mh0;
        const uint32_t mn1h2 = *(uint32_t*)&mh1;
        uint32_t ph[8][2];
        #pragma unroll
        for (int nt = 0; nt < 8; nt++) {
            ph[nt][0] = ex2_h2u(sub_h2u(dh[nt][0], mn0h2));
            ph[nt][1] = ex2_h2u(sub_h2u(dh[nt][1], mn1h2));
        }

        // ---- O += P @ V ; ones-column accumulates li ----
        #pragma unroll
        for (int kt = 0; kt < 4; kt++) {
            const uint32_t a0 = ph[2*kt][0];
            const uint32_t a1 = ph[2*kt][1];
            const uint32_t a2 = ph[2*kt+1][0];
            const uint32_t a3 = ph[2*kt+1][1];
            #pragma unroll
            for (int nt = 0; nt < 8; nt += 2) {
                uint32_t b0, b1, b2, b3;
                ldm_x4t(b0, b1, b2, b3, Vbuf + (kt*16*HS + nt*8)*2 + bVoff);
                mma_f16(of[nt],   a0, a1, a2, a3, b0, b1);
                mma_f16(of[nt+1], a0, a1, a2, a3, b2, b3);
            }
            uint32_t s0, s1;
            ldm_x2t(s0, s1, Vbuf + ((kt*16 + l15)*HS + 64)*2);
            mma_f16(ofs, a0, a1, a2, a3, s0, s1);
        }

        if (kc + 2 < NC) { issue_chunk(kc + 2); cp_commit(); }
    }
    if (NC == 0) asm volatile("cp.async.wait_group 0;");

    const float li0 = __shfl_sync(0xffffffffu, ofs[0], lane & 28);
    const float li1 = __shfl_sync(0xffffffffu, ofs[2], lane & 28);
    const float inv0 = (li0 > 0.f) ? (1.0f / li0) : 0.f;
    const float inv1 = (li1 > 0.f) ? (1.0f / li1) : 0.f;
    const int t0 = qt*128 + r0 + g;
    const int t1 = t0 + 8;
    #pragma unroll
    for (int nt = 0; nt < 8; nt++) {
        const int dk = nt*8 + 2*t;
        __half2 w0 = __float22half2_rn(make_float2(of[nt][0] * inv0, of[nt][1] * inv0));
        __half2 w1 = __float22half2_rn(make_float2(of[nt][2] * inv1, of[nt][3] * inv1));
        *(__half2*)(CTX + ((size_t)b * Tc + t0) * Fc + h*DKc + dk) = w0;
        *(__half2*)(CTX + ((size_t)b * Tc + t1) * Fc + h*DKc + dk) = w1;
    }
}

// ---------------------------------------------------------------------------
// Launcher
// ---------------------------------------------------------------------------
extern "C" void kernel_launch(void* const* d_in, const int* in_sizes, int n_in,
                              void* d_out, int out_size)
{
    const float* query = (const float*)d_in[0];
    const float* key   = (const float*)d_in[1];
    const float* value = (const float*)d_in[2];
    const int*   amask = (const int*)  d_in[3];
    const float* Wq = (const float*)d_in[4];
    const float* bq = (const float*)d_in[5];
    const float* Wk = (const float*)d_in[6];
    const float* bk = (const float*)d_in[7];
    const float* Wv = (const float*)d_in[8];
    const float* bv = (const float*)d_in[9];
    const float* Wo = (const float*)d_in[10];
    const float* bo = (const float*)d_in[11];
    float* out = (float*)d_out;

    __half *pXh, *pWh, *pQ, *pK, *pV, *pCTX, *pMB;
    int *pRK, *pNV;
    cudaGetSymbolAddress((void**)&pXh, g_Xh);
    cudaGetSymbolAddress((void**)&pWh, g_Wh);
    cudaGetSymbolAddress((void**)&pQ,  g_Qh);
    cudaGetSymbolAddress((void**)&pK,  g_Kh);
    cudaGetSymbolAddress((void**)&pV,  g_Vh);
    cudaGetSymbolAddress((void**)&pCTX, g_CTXh);
    cudaGetSymbolAddress((void**)&pMB, g_MBh);
    cudaGetSymbolAddress((void**)&pRK, g_RK);
    cudaGetSymbolAddress((void**)&pNV, g_NV);

    __half* xh[3] = { pXh, pXh + (size_t)Mdim*Fc, pXh + 2*(size_t)Mdim*Fc };
    __half* wh[4] = { pWh, pWh + (size_t)Fc*Fc, pWh + 2*(size_t)Fc*Fc, pWh + 3*(size_t)Fc*Fc };

    cudaFuncSetAttribute(attn_kernel,
                         cudaFuncAttributeMaxDynamicSharedMemorySize, AT_SMEM_BYTES);
    cudaFuncSetAttribute(gemm_h_kernel<0>,
                         cudaFuncAttributeMaxDynamicSharedMemorySize, G_SMEM_BYTES);
    cudaFuncSetAttribute(gemm_h_kernel<1>,
                         cudaFuncAttributeMaxDynamicSharedMemorySize, G_SMEM_BYTES);

    // 1) converts + mask compaction
    CvtJobs JI;
    JI.src[0] = query; JI.src[1] = key; JI.src[2] = value; JI.src[3] = query;
    JI.dst[0] = xh[0]; JI.dst[1] = xh[1]; JI.dst[2] = xh[2]; JI.dst[3] = xh[0];
    cvt_kernel<<<dim3((Mdim*Fc)/(256*4), 3), 256>>>(JI);

    CvtJobs JW;
    JW.src[0] = Wq; JW.src[1] = Wk; JW.src[2] = Wv; JW.src[3] = Wo;
    JW.dst[0] = wh[0]; JW.dst[1] = wh[1]; JW.dst[2] = wh[2]; JW.dst[3] = wh[3];
    cvt_kernel<<<dim3((Fc*Fc)/(256*4), 4), 256>>>(JW);

    compact_mask_kernel<<<Bc, 256>>>(amask, pRK, pMB, pNV);

    // 2) fused QKV projections; K/V scattered compacted via rank
    QKVJobs P;
    P.A[0] = xh[0]; P.A[1] = xh[1]; P.A[2] = xh[2];
    P.W[0] = wh[0]; P.W[1] = wh[1]; P.W[2] = wh[2];
    P.bias[0] = bq; P.bias[1] = bk; P.bias[2] = bv;
    P.C[0] = pQ;    P.C[1] = pK;   P.C[2] = pV;
    gemm_h_kernel<1><<<dim3(Ndim/128, Mdim/128, 3), 256, G_SMEM_BYTES>>>(
        P, nullptr, nullptr, nullptr, nullptr, pRK);

    // 3) attention over compacted keys
    attn_kernel<<<dim3(Tc/128, Hc, Bc), 256, AT_SMEM_BYTES>>>(pQ, pK, pV, pMB, pNV, pCTX);

    // 4) output projection
    QKVJobs PD = {};
    gemm_h_kernel<0><<<dim3(Ndim/128, Mdim/128), 256, G_SMEM_BYTES>>>(
        PD, pCTX, wh[3], bo, out, nullptr);
}

// round 13
// speedup vs baseline: 11.3160x; 1.0312x over previous
#include <cuda_runtime.h>
#include <cuda_bf16.h>
#include <cuda_fp16.h>
#include <cstdint>

// Problem constants
#define Bc 4
#define Tc 2048
#define Fc 512
#define Hc 8
#define DKc 64
#define Mdim (Bc*Tc)   // 8192
#define Ndim Fc        // 512
#define Kdim Fc        // 512

#define LOG2E 1.44269504088896340736f

// ---- fp16 mma m16n8k16, fp32 accumulate ----
__device__ __forceinline__ void mma_f16(float* c,
                                        uint32_t a0, uint32_t a1, uint32_t a2, uint32_t a3,
                                        uint32_t b0, uint32_t b1) {
    asm volatile("mma.sync.aligned.m16n8k16.row.col.f32.f16.f16.f32 "
                 "{%0,%1,%2,%3}, {%4,%5,%6,%7}, {%8,%9}, {%0,%1,%2,%3};"
                 : "+f"(c[0]), "+f"(c[1]), "+f"(c[2]), "+f"(c[3])
                 : "r"(a0), "r"(a1), "r"(a2), "r"(a3), "r"(b0), "r"(b1));
}
__device__ __forceinline__ uint32_t smem_u32(const void* p) {
    return (uint32_t)__cvta_generic_to_shared(p);
}
__device__ __forceinline__ void cp_async16(uint32_t dst, const void* src) {
    asm volatile("cp.async.cg.shared.global [%0], [%1], 16;" :: "r"(dst), "l"(src));
}
__device__ __forceinline__ void cp_commit() {
    asm volatile("cp.async.commit_group;");
}
__device__ __forceinline__ void ldm_x4(uint32_t& r0, uint32_t& r1, uint32_t& r2, uint32_t& r3,
                                       uint32_t addr) {
    asm volatile("ldmatrix.sync.aligned.m8n8.x4.shared.b16 {%0,%1,%2,%3}, [%4];"
                 : "=r"(r0), "=r"(r1), "=r"(r2), "=r"(r3) : "r"(addr));
}
__device__ __forceinline__ void ldm_x4t(uint32_t& r0, uint32_t& r1, uint32_t& r2, uint32_t& r3,
                                        uint32_t addr) {
    asm volatile("ldmatrix.sync.aligned.m8n8.x4.trans.shared.b16 {%0,%1,%2,%3}, [%4];"
                 : "=r"(r0), "=r"(r1), "=r"(r2), "=r"(r3) : "r"(addr));
}
__device__ __forceinline__ void ldm_x2t(uint32_t& r0, uint32_t& r1, uint32_t addr) {
    asm volatile("ldmatrix.sync.aligned.m8n8.x2.trans.shared.b16 {%0,%1}, [%2];"
                 : "=r"(r0), "=r"(r1) : "r"(addr));
}
__device__ __forceinline__ void ldm_x2(uint32_t& r0, uint32_t& r1, uint32_t addr) {
    asm volatile("ldmatrix.sync.aligned.m8n8.x2.shared.b16 {%0,%1}, [%2];"
                 : "=r"(r0), "=r"(r1) : "r"(addr));
}
__device__ __forceinline__ float ex2(float x) {
    float y; asm("ex2.approx.f32 %0, %1;" : "=f"(y) : "f"(x)); return y;
}
// ---- packed f16x2 ops ----
__device__ __forceinline__ uint32_t cvt_h2(float lo, float hi) {
    uint32_t d; asm("cvt.rn.f16x2.f32 %0, %1, %2;" : "=r"(d) : "f"(hi), "f"(lo)); return d;
}
__device__ __forceinline__ uint32_t add_h2u(uint32_t a, uint32_t b) {
    uint32_t d; asm("add.f16x2 %0, %1, %2;" : "=r"(d) : "r"(a), "r"(b)); return d;
}
__device__ __forceinline__ uint32_t sub_h2u(uint32_t a, uint32_t b) {
    uint32_t d; asm("sub.f16x2 %0, %1, %2;" : "=r"(d) : "r"(a), "r"(b)); return d;
}
__device__ __forceinline__ uint32_t max_h2u(uint32_t a, uint32_t b) {
    uint32_t d; asm("max.f16x2 %0, %1, %2;" : "=r"(d) : "r"(a), "r"(b)); return d;
}
__device__ __forceinline__ uint32_t prmtu(uint32_t a, uint32_t b, uint32_t c) {
    uint32_t d; asm("prmt.b32 %0, %1, %2, %3;" : "=r"(d) : "r"(a), "r"(b), "r"(c)); return d;
}
__device__ __forceinline__ uint32_t ex2_h2u(uint32_t a) {
    uint32_t d; asm("ex2.approx.f16x2 %0, %1;" : "=r"(d) : "r"(a)); return d;
}

// Scratch
__device__ __half g_Xh[3][(size_t)Mdim*Fc];
__device__ __half g_Wh[4][(size_t)Fc*Fc];
__device__ __half g_Qh[(size_t)Bc*Hc*Tc*DKc];
__device__ __half g_Kh[(size_t)Bc*Hc*Tc*DKc];   // compacted per (b,h)
__device__ __half g_Vh[(size_t)Bc*Hc*Tc*DKc];   // compacted; rows >= nv stay 0
__device__ __half g_CTXh[(size_t)Mdim*Fc];
__device__ __half g_MBh[(size_t)Bc*Tc];         // compacted bias: 0 (j<nv) / -inf
__device__ int    g_RK[(size_t)Bc*Tc];          // rank among valid, -1 if masked
__device__ int    g_NV[Bc];                     // valid-key count per batch

// ---------------------------------------------------------------------------
// fp32 -> fp16 convert: all 7 jobs (3 inputs + 4 weights) in one launch.
// ---------------------------------------------------------------------------
struct CvtJobs7 { const float* src[7]; __half* dst[7]; int nblk[7]; };

__global__ __launch_bounds__(256)
void cvt_kernel(CvtJobs7 J)
{
    const int j = blockIdx.y;
    if ((int)blockIdx.x >= J.nblk[j]) return;
    const float* s = J.src[j];
    __half* d = J.dst[j];
    const size_t i = ((size_t)blockIdx.x * 256 + threadIdx.x) * 4;
    float4 v = *(const float4*)(s + i);
    __half2 h0 = __float22half2_rn(make_float2(v.x, v.y));
    __half2 h1 = __float22half2_rn(make_float2(v.z, v.w));
    uint2 o; o.x = *(uint32_t*)&h0; o.y = *(uint32_t*)&h1;
    *(uint2*)(d + i) = o;
}

// ---------------------------------------------------------------------------
// Mask compaction: rank (stable prefix), nv count, compacted fp16 bias.
// ---------------------------------------------------------------------------
__global__ __launch_bounds__(256)
void compact_mask_kernel(const int* __restrict__ m, int* __restrict__ rank,
                         __half* __restrict__ mbc, int* __restrict__ nv)
{
    const int b = blockIdx.x;
    const int tid = threadIdx.x;
    const int lane = tid & 31, wid = tid >> 5;
    const int* mb_ = m + b * Tc;

    int loc[8], s = 0;
    #pragma unroll
    for (int j = 0; j < 8; j++) { loc[j] = mb_[tid*8 + j] ? 1 : 0; s += loc[j]; }

    int inc = s;
    #pragma unroll
    for (int off = 1; off < 32; off <<= 1) {
        int v = __shfl_up_sync(0xffffffffu, inc, off);
        if (lane >= off) inc += v;
    }
    __shared__ int wsum[8], wpre[8], nvsh;
    if (lane == 31) wsum[wid] = inc;
    __syncthreads();
    if (tid == 0) {
        int acc = 0;
        #pragma unroll
        for (int i = 0; i < 8; i++) { wpre[i] = acc; acc += wsum[i]; }
        nv[b] = acc; nvsh = acc;
    }
    __syncthreads();

    int ex = wpre[wid] + inc - s;
    int* rk = rank + b * Tc;
    #pragma unroll
    for (int j = 0; j < 8; j++) {
        rk[tid*8 + j] = loc[j] ? ex : -1;
        ex += loc[j];
    }

    const int NV = nvsh;
    __half* mo = mbc + b * Tc;
    for (int p = tid; p < Tc; p += 256)
        mo[p] = __ushort_as_half(p < NV ? (unsigned short)0x0000
                                        : (unsigned short)0xFC00);
}

// ---------------------------------------------------------------------------
// fp16 GEMM, 3-stage cp.async pipeline; 3 CTAs/SM (reg-capped to 84).
// MODE 0: C fp32 row-major.
// MODE 1: C fp16 scatter to [B,H,T,DK]; z==0 (Q): scale;
//         z==1/2 (K/V): scatter to rank[t] (compaction), skip masked rows.
// ---------------------------------------------------------------------------
#define HAS 40
#define G_STAGE_H (128*HAS)
#define G_SMEM_BYTES (2 * 3 * G_STAGE_H * 2)  // 61440

struct QKVJobs {
    const __half* A[3];
    const __half* W[3];
    const float* bias[3];
    __half* C[3];
};

template<int MODE>
__global__ __launch_bounds__(256, 3)
void gemm_h_kernel(QKVJobs P, const __half* Ao, const __half* Wo,
                   const float* biaso, float* Co, const int* __restrict__ rankArr)
{
    extern __shared__ __half gsm[];
    __half* sA = gsm;
    __half* sW = gsm + 3*G_STAGE_H;

    const int z = (MODE == 1) ? blockIdx.z : 0;
    const __half* A  = (MODE == 1) ? P.A[z] : Ao;
    const __half* W  = (MODE == 1) ? P.W[z] : Wo;
    const float* bias = (MODE == 1) ? P.bias[z] : biaso;
    const float scale = (MODE == 1 && z == 0) ? 0.125f * LOG2E : 1.0f;

    const int tid  = threadIdx.x;
    const int lane = tid & 31;
    const int w    = tid >> 5;
    const int g    = lane >> 2;
    const int t    = lane & 3;
    const int wm   = w & 3;
    const int wn   = w >> 2;
    const int bm = blockIdx.y * 128;
    const int bn = blockIdx.x * 128;

    const uint32_t sAb = smem_u32(sA);
    const uint32_t sWb = smem_u32(sW);

    auto issue = [&](int i) {
        const int buf = i % 3;
        const int k0 = i * 32;
        #pragma unroll
        for (int it = 0; it < 2; it++) {
            const int e = tid + it * 256;
            const int r = e >> 2, s = e & 3;
            cp_async16(sAb + (buf*G_STAGE_H + r*HAS + s*8)*2,
                       A + (size_t)(bm + r) * Kdim + k0 + s*8);
            cp_async16(sWb + (buf*G_STAGE_H + r*HAS + s*8)*2,
                       W + (size_t)(bn + r) * Kdim + k0 + s*8);
        }
    };

    float acc[2][8][4];
    #pragma unroll
    for (int mt = 0; mt < 2; mt++)
        #pragma unroll
        for (int nt = 0; nt < 8; nt++)
            #pragma unroll
            for (int j = 0; j < 4; j++) acc[mt][nt][j] = 0.f;

    issue(0); cp_commit();
    issue(1); cp_commit();

    const int NIT = Kdim / 32;   // 16
    for (int i = 0; i < NIT; i++) {
        const int buf = i % 3;
        if (i + 1 < NIT) asm volatile("cp.async.wait_group 1;");
        else             asm volatile("cp.async.wait_group 0;");
        __syncthreads();

        const uint32_t Ab = sAb + (buf*G_STAGE_H)*2;
        const uint32_t Wb = sWb + (buf*G_STAGE_H)*2;

        #pragma unroll
        for (int kt = 0; kt < 2; kt++) {
            uint32_t a[2][4];
            #pragma unroll
            for (int mt = 0; mt < 2; mt++) {
                const int row = wm*32 + mt*16 + (lane & 15);
                const int col = kt*16 + (lane >> 4) * 8;
                ldm_x4(a[mt][0], a[mt][1], a[mt][2], a[mt][3],
                       Ab + (row*HAS + col)*2);
            }
            #pragma unroll
            for (int nt = 0; nt < 8; nt++) {
                const int row = wn*64 + nt*8 + (lane & 7);
                const int col = kt*16 + ((lane >> 3) & 1) * 8;
                uint32_t b0, b1;
                ldm_x2(b0, b1, Wb + (row*HAS + col)*2);
                mma_f16(acc[0][nt], a[0][0], a[0][1], a[0][2], a[0][3], b0, b1);
                mma_f16(acc[1][nt], a[1][0], a[1][1], a[1][2], a[1][3], b0, b1);
            }
        }
        if (i + 2 < NIT) { issue(i + 2); cp_commit(); }
    }

    if (MODE == 0) {
        #pragma unroll
        for (int nt = 0; nt < 8; nt++) {
            const int col = bn + wn*64 + nt*8 + 2*t;
            const float2 bb = *(const float2*)(bias + col);
            #pragma unroll
            for (int mt = 0; mt < 2; mt++) {
                const int row0 = bm + wm*32 + mt*16 + g;
                const int row1 = row0 + 8;
                float2 v0, v1;
                v0.x = acc[mt][nt][0] + bb.x; v0.y = acc[mt][nt][1] + bb.y;
                v1.x = acc[mt][nt][2] + bb.x; v1.y = acc[mt][nt][3] + bb.y;
                *(float2*)(Co + (size_t)row0 * Ndim + col) = v0;
                *(float2*)(Co + (size_t)row1 * Ndim + col) = v1;
            }
        }
    } else {
        #pragma unroll
        for (int mt = 0; mt < 2; mt++) {
            const int row0 = bm + wm*32 + mt*16 + g;
            const int row1 = row0 + 8;
            const int b0_ = row0 >> 11, t0_ = row0 & 2047;
            const int b1_ = row1 >> 11, t1_ = row1 & 2047;
            int d0 = t0_, d1 = t1_;
            if (z != 0) {
                d0 = rankArr[b0_*Tc + t0_];
                d1 = rankArr[b1_*Tc + t1_];
            }
            #pragma unroll
            for (int nt = 0; nt < 8; nt++) {
                const int col = bn + wn*64 + nt*8 + 2*t;
                const float2 bb = *(const float2*)(bias + col);
                const int h  = col >> 6;
                const int dk = col & 63;
                if (d0 >= 0) {
                    float2 v0;
                    v0.x = (acc[mt][nt][0] + bb.x) * scale;
                    v0.y = (acc[mt][nt][1] + bb.y) * scale;
                    *(__half2*)(P.C[z] + ((((size_t)b0_*Hc + h)*Tc + d0) * DKc) + dk)
                        = __float22half2_rn(v0);
                }
                if (d1 >= 0) {
                    float2 v1;
                    v1.x = (acc[mt][nt][2] + bb.x) * scale;
                    v1.y = (acc[mt][nt][3] + bb.y) * scale;
                    *(__half2*)(P.C[z] + ((((size_t)b1_*Hc + h)*Tc + d1) * DKc) + dk)
                        = __float22half2_rn(v1);
                }
            }
        }
    }
}

// ---------------------------------------------------------------------------
// Flash attention over COMPACTED keys (R11, proven).
// ---------------------------------------------------------------------------
#define HS 72
#define SQ_OFF 0
#define SK_OFF (128*HS)
#define SV_OFF (SK_OFF + 3*64*HS)
#define AT_HALVES (SV_OFF + 3*64*HS)
#define AT_SMEM_BYTES (AT_HALVES * 2)   // 73728

__global__ __launch_bounds__(256, 2)
void attn_kernel(const __half* __restrict__ Q, const __half* __restrict__ K,
                 const __half* __restrict__ V, const __half* __restrict__ maskb,
                 const int* __restrict__ nv, __half* __restrict__ CTX)
{
    extern __shared__ __half hsm[];
    __half* sQ = hsm + SQ_OFF;
    __half* sK = hsm + SK_OFF;
    __half* sV = hsm + SV_OFF;
    __shared__ __half sMBh[3][64];

    const uint32_t sQb = smem_u32(sQ);
    const uint32_t sKb = smem_u32(sK);
    const uint32_t sVb = smem_u32(sV);
    const uint32_t sMBb = smem_u32(&sMBh[0][0]);
    const uint32_t* sMB32 = (const uint32_t*)&sMBh[0][0];

    const int tid  = threadIdx.x;
    const int lane = tid & 31;
    const int w    = tid >> 5;
    const int g    = lane >> 2;
    const int t    = lane & 3;
    const int r0   = w * 16;
    const int qt = blockIdx.x;
    const int h  = blockIdx.y;
    const int b  = blockIdx.z;

    const int NV = nv[b];
    const int NC = (NV + 63) >> 6;

    const size_t head_base = (((size_t)b * Hc + h) * Tc) * DKc;
    const __half* Qb = Q + head_base + (size_t)qt * 128 * DKc;
    const __half* Kb = K + head_base;
    const __half* Vb = V + head_base;
    const __half* MBp = maskb + b * Tc;

    const int l15 = lane & 15;
    const int lhi = lane >> 4;
    const int l7  = lane & 7;
    const int lb8 = (lane >> 3) & 1;
    const uint32_t aQaddr = sQb + ((r0 + l15)*HS + lhi*8)*2;
    const uint32_t bKoff = ((l7 + lhi*8)*HS + lb8*8)*2;
    const uint32_t bVoff = (l15*HS + lhi*8)*2;

    for (int idx = tid; idx < 3*64; idx += 256) {
        uint4 v; v.x = 0x00003C00u; v.y = 0; v.z = 0; v.w = 0;
        *(uint4*)(sV + idx*HS + 64) = v;
    }

    #pragma unroll
    for (int it = 0; it < 4; it++) {
        const int e = tid + it * 256;
        const int r = e >> 3, s = e & 7;
        cp_async16(sQb + (r*HS + s*8)*2, Qb + r*DKc + s*8);
    }

    auto issue_chunk = [&](int kc) {
        const int buf = kc % 3;
        const __half* Kc = Kb + (size_t)kc * 64 * DKc;
        const __half* Vc = Vb + (size_t)kc * 64 * DKc;
        #pragma unroll
        for (int it = 0; it < 2; it++) {
            const int e = tid + it * 256;
            const int r = e >> 3, s = e & 7;
            cp_async16(sKb + ((buf*64 + r)*HS + s*8)*2, Kc + r*DKc + s*8);
            cp_async16(sVb + ((buf*64 + r)*HS + s*8)*2, Vc + r*DKc + s*8);
        }
        if (tid < 8) cp_async16(sMBb + (buf*64 + tid*8)*2, MBp + kc*64 + tid*8);
    };

    if (NC > 0) issue_chunk(0);
    cp_commit();
    if (NC > 1) { issue_chunk(1); cp_commit(); }

    float of[8][4];
    float ofs[4];
    float mi0 = -1e30f, mi1 = -1e30f;
    #pragma unroll
    for (int nt = 0; nt < 8; nt++)
        #pragma unroll
        for (int j = 0; j < 4; j++) of[nt][j] = 0.f;
    ofs[0] = ofs[1] = ofs[2] = ofs[3] = 0.f;

    for (int kc = 0; kc < NC; kc++) {
        const int buf = kc % 3;
        if (kc + 1 < NC) asm volatile("cp.async.wait_group 1;");
        else             asm volatile("cp.async.wait_group 0;");
        __syncthreads();

        const uint32_t Kbuf = sKb + (buf*64*HS)*2;
        const uint32_t Vbuf = sVb + (buf*64*HS)*2;

        float sf[8][4];
        #pragma unroll
        for (int nt = 0; nt < 8; nt++)
            #pragma unroll
            for (int j = 0; j < 4; j++) sf[nt][j] = 0.f;

        #pragma unroll
        for (int kt = 0; kt < 4; kt++) {
            uint32_t a0, a1, a2, a3;
            ldm_x4(a0, a1, a2, a3, aQaddr + kt*32);
            #pragma unroll
            for (int nt = 0; nt < 8; nt += 2) {
                uint32_t b0, b1, b2, b3;
                ldm_x4(b0, b1, b2, b3, Kbuf + (nt*8*HS)*2 + kt*32 + bKoff);
                mma_f16(sf[nt],   a0, a1, a2, a3, b0, b1);
                mma_f16(sf[nt+1], a0, a1, a2, a3, b2, b3);
            }
        }

        uint32_t dh[8][2];
        #pragma unroll
        for (int nt = 0; nt < 8; nt++) {
            const uint32_t mb2 = sMB32[buf*32 + nt*4 + t];
            dh[nt][0] = add_h2u(cvt_h2(sf[nt][0], sf[nt][1]), mb2);
            dh[nt][1] = add_h2u(cvt_h2(sf[nt][2], sf[nt][3]), mb2);
        }
        uint32_t m0 = dh[0][0], m1 = dh[0][1];
        #pragma unroll
        for (int nt = 1; nt < 8; nt++) {
            m0 = max_h2u(m0, dh[nt][0]);
            m1 = max_h2u(m1, dh[nt][1]);
        }
        m0 = max_h2u(m0, prmtu(m0, m0, 0x1032));
        m1 = max_h2u(m1, prmtu(m1, m1, 0x1032));
        uint32_t mx2 = prmtu(m0, m1, 0x5410);
        mx2 = max_h2u(mx2, __shfl_xor_sync(0xffffffffu, mx2, 1));
        mx2 = max_h2u(mx2, __shfl_xor_sync(0xffffffffu, mx2, 2));
        const __half2 mxh = *(const __half2*)&mx2;
        const float mx0 = __low2float(mxh);
        const float mx1 = __high2float(mxh);

        const bool skiprow = (mx0 <= mi0) && (mx1 <= mi1) &&
                             (mi0 >= -60.f) && (mi1 >= -60.f);
        float mn0, mn1;
        if (__all_sync(0xffffffffu, skiprow)) {
            mn0 = mi0; mn1 = mi1;
        } else {
            mn0 = fmaxf(fmaxf(mi0, mx0), -60.f);
            mn1 = fmaxf(fmaxf(mi1, mx1), -60.f);
            const float al0 = ex2(mi0 - mn0);
            const float al1 = ex2(mi1 - mn1);
            mi0 = mn0; mi1 = mn1;
            #pragma unroll
            for (int nt = 0; nt < 8; nt++) {
                of[nt][0] *= al0; of[nt][1] *= al0;
                of[nt][2] *= al1; of[nt][3] *= al1;
            }
            ofs[0] *= al0; ofs[1] *= al0;
            ofs[2] *= al1; ofs[3] *= al1;
        }

        __half2 mh0 = __float2half2_rn(mn0);
        __half2 mh1 = __float2half2_rn(mn1);
        const uint32_t mn0h2 = *(uint32_t*)&mh0;
        const uint32_t mn1h2 = *(uint32_t*)&mh1;
        uint32_t ph[8][2];
        #pragma unroll
        for (int nt = 0; nt < 8; nt++) {
            ph[nt][0] = ex2_h2u(sub_h2u(dh[nt][0], mn0h2));
            ph[nt][1] = ex2_h2u(sub_h2u(dh[nt][1], mn1h2));
        }

        #pragma unroll
        for (int kt = 0; kt < 4; kt++) {
            const uint32_t a0 = ph[2*kt][0];
            const uint32_t a1 = ph[2*kt][1];
            const uint32_t a2 = ph[2*kt+1][0];
            const uint32_t a3 = ph[2*kt+1][1];
            #pragma unroll
            for (int nt = 0; nt < 8; nt += 2) {
                uint32_t b0, b1, b2, b3;
                ldm_x4t(b0, b1, b2, b3, Vbuf + (kt*16*HS + nt*8)*2 + bVoff);
                mma_f16(of[nt],   a0, a1, a2, a3, b0, b1);
                mma_f16(of[nt+1], a0, a1, a2, a3, b2, b3);
            }
            uint32_t s0, s1;
            ldm_x2t(s0, s1, Vbuf + ((kt*16 + l15)*HS + 64)*2);
            mma_f16(ofs, a0, a1, a2, a3, s0, s1);
        }

        if (kc + 2 < NC) { issue_chunk(kc + 2); cp_commit(); }
    }
    if (NC == 0) asm volatile("cp.async.wait_group 0;");

    const float li0 = __shfl_sync(0xffffffffu, ofs[0], lane & 28);
    const float li1 = __shfl_sync(0xffffffffu, ofs[2], lane & 28);
    const float inv0 = (li0 > 0.f) ? (1.0f / li0) : 0.f;
    const float inv1 = (li1 > 0.f) ? (1.0f / li1) : 0.f;
    const int t0 = qt*128 + r0 + g;
    const int t1 = t0 + 8;
    #pragma unroll
    for (int nt = 0; nt < 8; nt++) {
        const int dk = nt*8 + 2*t;
        __half2 w0 = __float22half2_rn(make_float2(of[nt][0] * inv0, of[nt][1] * inv0));
        __half2 w1 = __float22half2_rn(make_float2(of[nt][2] * inv1, of[nt][3] * inv1));
        *(__half2*)(CTX + ((size_t)b * Tc + t0) * Fc + h*DKc + dk) = w0;
        *(__half2*)(CTX + ((size_t)b * Tc + t1) * Fc + h*DKc + dk) = w1;
    }
}

// ---------------------------------------------------------------------------
// Launcher
// ---------------------------------------------------------------------------
extern "C" void kernel_launch(void* const* d_in, const int* in_sizes, int n_in,
                              void* d_out, int out_size)
{
    const float* query = (const float*)d_in[0];
    const float* key   = (const float*)d_in[1];
    const float* value = (const float*)d_in[2];
    const int*   amask = (const int*)  d_in[3];
    const float* Wq = (const float*)d_in[4];
    const float* bq = (const float*)d_in[5];
    const float* Wk = (const float*)d_in[6];
    const float* bk = (const float*)d_in[7];
    const float* Wv = (const float*)d_in[8];
    const float* bv = (const float*)d_in[9];
    const float* Wo = (const float*)d_in[10];
    const float* bo = (const float*)d_in[11];
    float* out = (float*)d_out;

    __half *pXh, *pWh, *pQ, *pK, *pV, *pCTX, *pMB;
    int *pRK, *pNV;
    cudaGetSymbolAddress((void**)&pXh, g_Xh);
    cudaGetSymbolAddress((void**)&pWh, g_Wh);
    cudaGetSymbolAddress((void**)&pQ,  g_Qh);
    cudaGetSymbolAddress((void**)&pK,  g_Kh);
    cudaGetSymbolAddress((void**)&pV,  g_Vh);
    cudaGetSymbolAddress((void**)&pCTX, g_CTXh);
    cudaGetSymbolAddress((void**)&pMB, g_MBh);
    cudaGetSymbolAddress((void**)&pRK, g_RK);
    cudaGetSymbolAddress((void**)&pNV, g_NV);

    __half* xh[3] = { pXh, pXh + (size_t)Mdim*Fc, pXh + 2*(size_t)Mdim*Fc };
    __half* wh[4] = { pWh, pWh + (size_t)Fc*Fc, pWh + 2*(size_t)Fc*Fc, pWh + 3*(size_t)Fc*Fc };

    cudaFuncSetAttribute(attn_kernel,
                         cudaFuncAttributeMaxDynamicSharedMemorySize, AT_SMEM_BYTES);
    cudaFuncSetAttribute(gemm_h_kernel<0>,
                         cudaFuncAttributeMaxDynamicSharedMemorySize, G_SMEM_BYTES);
    cudaFuncSetAttribute(gemm_h_kernel<1>,
                         cudaFuncAttributeMaxDynamicSharedMemorySize, G_SMEM_BYTES);

    // 1) one convert launch (3 inputs + 4 weights) + mask compaction
    const int NB_IN = (Mdim*Fc)/(256*4);   // 4096
    const int NB_W  = (Fc*Fc)/(256*4);     // 256
    CvtJobs7 J;
    J.src[0] = query; J.src[1] = key; J.src[2] = value;
    J.src[3] = Wq; J.src[4] = Wk; J.src[5] = Wv; J.src[6] = Wo;
    J.dst[0] = xh[0]; J.dst[1] = xh[1]; J.dst[2] = xh[2];
    J.dst[3] = wh[0]; J.dst[4] = wh[1]; J.dst[5] = wh[2]; J.dst[6] = wh[3];
    J.nblk[0] = NB_IN; J.nblk[1] = NB_IN; J.nblk[2] = NB_IN;
    J.nblk[3] = NB_W;  J.nblk[4] = NB_W;  J.nblk[5] = NB_W;  J.nblk[6] = NB_W;
    cvt_kernel<<<dim3(NB_IN, 7), 256>>>(J);

    compact_mask_kernel<<<Bc, 256>>>(amask, pRK, pMB, pNV);

    // 2) fused QKV projections; K/V scattered compacted via rank
    QKVJobs P;
    P.A[0] = xh[0]; P.A[1] = xh[1]; P.A[2] = xh[2];
    P.W[0] = wh[0]; P.W[1] = wh[1]; P.W[2] = wh[2];
    P.bias[0] = bq; P.bias[1] = bk; P.bias[2] = bv;
    P.C[0] = pQ;    P.C[1] = pK;   P.C[2] = pV;
    gemm_h_kernel<1><<<dim3(Ndim/128, Mdim/128, 3), 256, G_SMEM_BYTES>>>(
        P, nullptr, nullptr, nullptr, nullptr, pRK);

    // 3) attention over compacted keys
    attn_kernel<<<dim3(Tc/128, Hc, Bc), 256, AT_SMEM_BYTES>>>(pQ, pK, pV, pMB, pNV, pCTX);

    // 4) output projection
    QKVJobs PD = {};
    gemm_h_kernel<0><<<dim3(Ndim/128, Mdim/128), 256, G_SMEM_BYTES>>>(
        PD, pCTX, wh[3], bo, out, nullptr);
}

// round 14
// speedup vs baseline: 12.8677x; 1.1371x over previous
#include <cuda_runtime.h>
#include <cuda_bf16.h>
#include <cuda_fp16.h>
#include <cstdint>

// Problem constants
#define Bc 4
#define Tc 2048
#define Fc 512
#define Hc 8
#define DKc 64
#define Mdim (Bc*Tc)   // 8192
#define Ndim Fc        // 512
#define Kdim Fc        // 512

#define LOG2E 1.44269504088896340736f

// ---- fp16 mma m16n8k16, fp32 accumulate ----
__device__ __forceinline__ void mma_f16(float* c,
                                        uint32_t a0, uint32_t a1, uint32_t a2, uint32_t a3,
                                        uint32_t b0, uint32_t b1) {
    asm volatile("mma.sync.aligned.m16n8k16.row.col.f32.f16.f16.f32 "
                 "{%0,%1,%2,%3}, {%4,%5,%6,%7}, {%8,%9}, {%0,%1,%2,%3};"
                 : "+f"(c[0]), "+f"(c[1]), "+f"(c[2]), "+f"(c[3])
                 : "r"(a0), "r"(a1), "r"(a2), "r"(a3), "r"(b0), "r"(b1));
}
__device__ __forceinline__ uint32_t smem_u32(const void* p) {
    return (uint32_t)__cvta_generic_to_shared(p);
}
__device__ __forceinline__ void cp_async16(uint32_t dst, const void* src) {
    asm volatile("cp.async.cg.shared.global [%0], [%1], 16;" :: "r"(dst), "l"(src));
}
__device__ __forceinline__ void cp_commit() {
    asm volatile("cp.async.commit_group;");
}
__device__ __forceinline__ void ldm_x4(uint32_t& r0, uint32_t& r1, uint32_t& r2, uint32_t& r3,
                                       uint32_t addr) {
    asm volatile("ldmatrix.sync.aligned.m8n8.x4.shared.b16 {%0,%1,%2,%3}, [%4];"
                 : "=r"(r0), "=r"(r1), "=r"(r2), "=r"(r3) : "r"(addr));
}
__device__ __forceinline__ void ldm_x4t(uint32_t& r0, uint32_t& r1, uint32_t& r2, uint32_t& r3,
                                        uint32_t addr) {
    asm volatile("ldmatrix.sync.aligned.m8n8.x4.trans.shared.b16 {%0,%1,%2,%3}, [%4];"
                 : "=r"(r0), "=r"(r1), "=r"(r2), "=r"(r3) : "r"(addr));
}
__device__ __forceinline__ void ldm_x2t(uint32_t& r0, uint32_t& r1, uint32_t addr) {
    asm volatile("ldmatrix.sync.aligned.m8n8.x2.trans.shared.b16 {%0,%1}, [%2];"
                 : "=r"(r0), "=r"(r1) : "r"(addr));
}
__device__ __forceinline__ void ldm_x2(uint32_t& r0, uint32_t& r1, uint32_t addr) {
    asm volatile("ldmatrix.sync.aligned.m8n8.x2.shared.b16 {%0,%1}, [%2];"
                 : "=r"(r0), "=r"(r1) : "r"(addr));
}
__device__ __forceinline__ float ex2(float x) {
    float y; asm("ex2.approx.f32 %0, %1;" : "=f"(y) : "f"(x)); return y;
}
// ---- packed f16x2 ops ----
__device__ __forceinline__ uint32_t cvt_h2(float lo, float hi) {
    uint32_t d; asm("cvt.rn.f16x2.f32 %0, %1, %2;" : "=r"(d) : "f"(hi), "f"(lo)); return d;
}
__device__ __forceinline__ uint32_t add_h2u(uint32_t a, uint32_t b) {
    uint32_t d; asm("add.f16x2 %0, %1, %2;" : "=r"(d) : "r"(a), "r"(b)); return d;
}
__device__ __forceinline__ uint32_t sub_h2u(uint32_t a, uint32_t b) {
    uint32_t d; asm("sub.f16x2 %0, %1, %2;" : "=r"(d) : "r"(a), "r"(b)); return d;
}
__device__ __forceinline__ uint32_t max_h2u(uint32_t a, uint32_t b) {
    uint32_t d; asm("max.f16x2 %0, %1, %2;" : "=r"(d) : "r"(a), "r"(b)); return d;
}
__device__ __forceinline__ uint32_t prmtu(uint32_t a, uint32_t b, uint32_t c) {
    uint32_t d; asm("prmt.b32 %0, %1, %2, %3;" : "=r"(d) : "r"(a), "r"(b), "r"(c)); return d;
}
__device__ __forceinline__ uint32_t ex2_h2u(uint32_t a) {
    uint32_t d; asm("ex2.approx.f16x2 %0, %1;" : "=r"(d) : "r"(a)); return d;
}

// Scratch
__device__ __half g_Xh[3][(size_t)Mdim*Fc];   // [0]=query; [1]/[2]=key/value COMPACTED
__device__ __half g_Wh[4][(size_t)Fc*Fc];
__device__ __half g_Qh[(size_t)Bc*Hc*Tc*DKc];
__device__ __half g_Kh[(size_t)Bc*Hc*Tc*DKc];   // compacted per (b,h)
__device__ __half g_Vh[(size_t)Bc*Hc*Tc*DKc];   // compacted
__device__ __half g_CTXh[(size_t)Mdim*Fc];
__device__ __half g_MBh[(size_t)Bc*Tc];         // compacted bias: 0 (j<nv) / -inf
__device__ int    g_RK[(size_t)Bc*Tc];          // rank among valid, -1 if masked
__device__ int    g_NV[Bc];                     // valid-key count per batch

// ---------------------------------------------------------------------------
// fp32 -> fp16 convert; jobs 1,2 (key,value) gather rows to rank position.
// ---------------------------------------------------------------------------
struct CvtJobs7 { const float* src[7]; __half* dst[7]; int nblk[7]; };

__global__ __launch_bounds__(256)
void cvt_kernel(CvtJobs7 J, const int* __restrict__ rank)
{
    const int j = blockIdx.y;
    if ((int)blockIdx.x >= J.nblk[j]) return;
    const float* s = J.src[j];
    __half* d = J.dst[j];
    const size_t i = ((size_t)blockIdx.x * 256 + threadIdx.x) * 4;

    size_t o = i;
    if (j == 1 || j == 2) {              // key/value: gather to compacted row
        const int row = (int)(i >> 9);   // Fc = 512 floats per row
        const int b = row >> 11, t = row & 2047;
        const int r = rank[b * Tc + t];
        if (r < 0) return;               // masked row: drop (dst rows >= nv stay 0)
        o = (((size_t)(b << 11) + r) << 9) + (i & 511);
    }
    float4 v = *(const float4*)(s + i);
    __half2 h0 = __float22half2_rn(make_float2(v.x, v.y));
    __half2 h1 = __float22half2_rn(make_float2(v.z, v.w));
    uint2 w; w.x = *(uint32_t*)&h0; w.y = *(uint32_t*)&h1;
    *(uint2*)(d + o) = w;
}

// ---------------------------------------------------------------------------
// Mask compaction: rank (stable prefix), nv count, compacted fp16 bias.
// ---------------------------------------------------------------------------
__global__ __launch_bounds__(256)
void compact_mask_kernel(const int* __restrict__ m, int* __restrict__ rank,
                         __half* __restrict__ mbc, int* __restrict__ nv)
{
    const int b = blockIdx.x;
    const int tid = threadIdx.x;
    const int lane = tid & 31, wid = tid >> 5;
    const int* mb_ = m + b * Tc;

    int loc[8], s = 0;
    #pragma unroll
    for (int j = 0; j < 8; j++) { loc[j] = mb_[tid*8 + j] ? 1 : 0; s += loc[j]; }

    int inc = s;
    #pragma unroll
    for (int off = 1; off < 32; off <<= 1) {
        int v = __shfl_up_sync(0xffffffffu, inc, off);
        if (lane >= off) inc += v;
    }
    __shared__ int wsum[8], wpre[8], nvsh;
    if (lane == 31) wsum[wid] = inc;
    __syncthreads();
    if (tid == 0) {
        int acc = 0;
        #pragma unroll
        for (int i = 0; i < 8; i++) { wpre[i] = acc; acc += wsum[i]; }
        nv[b] = acc; nvsh = acc;
    }
    __syncthreads();

    int ex = wpre[wid] + inc - s;
    int* rk = rank + b * Tc;
    #pragma unroll
    for (int j = 0; j < 8; j++) {
        rk[tid*8 + j] = loc[j] ? ex : -1;
        ex += loc[j];
    }

    const int NV = nvsh;
    __half* mo = mbc + b * Tc;
    for (int p = tid; p < Tc; p += 256)
        mo[p] = __ushort_as_half(p < NV ? (unsigned short)0x0000
                                        : (unsigned short)0xFC00);
}

// ---------------------------------------------------------------------------
// fp16 GEMM, 3-stage cp.async pipeline; 3 CTAs/SM.
// MODE 0: C fp32 row-major.
// MODE 1: C fp16 scatter to [B,H,T,DK]; z==0 (Q): scaled identity scatter;
//         z==1/2 (K/V): inputs pre-compacted, identity scatter; row-blocks
//         entirely past nv[b] exit immediately (masked work eliminated).
// ---------------------------------------------------------------------------
#define HAS 40
#define G_STAGE_H (128*HAS)
#define G_SMEM_BYTES (2 * 3 * G_STAGE_H * 2)  // 61440

struct QKVJobs {
    const __half* A[3];
    const __half* W[3];
    const float* bias[3];
    __half* C[3];
};

template<int MODE>
__global__ __launch_bounds__(256, 3)
void gemm_h_kernel(QKVJobs P, const __half* Ao, const __half* Wo,
                   const float* biaso, float* Co, const int* __restrict__ nvArr)
{
    extern __shared__ __half gsm[];
    __half* sA = gsm;
    __half* sW = gsm + 3*G_STAGE_H;

    const int z = (MODE == 1) ? blockIdx.z : 0;
    const int bm = blockIdx.y * 128;
    const int bn = blockIdx.x * 128;

    // K/V row-blocks beyond the valid-key count: nothing to compute.
    if (MODE == 1 && z != 0) {
        if ((bm & 2047) >= nvArr[bm >> 11]) return;
    }

    const __half* A  = (MODE == 1) ? P.A[z] : Ao;
    const __half* W  = (MODE == 1) ? P.W[z] : Wo;
    const float* bias = (MODE == 1) ? P.bias[z] : biaso;
    const float scale = (MODE == 1 && z == 0) ? 0.125f * LOG2E : 1.0f;

    const int tid  = threadIdx.x;
    const int lane = tid & 31;
    const int w    = tid >> 5;
    const int g    = lane >> 2;
    const int t    = lane & 3;
    const int wm   = w & 3;
    const int wn   = w >> 2;

    const uint32_t sAb = smem_u32(sA);
    const uint32_t sWb = smem_u32(sW);

    auto issue = [&](int i) {
        const int buf = i % 3;
        const int k0 = i * 32;
        #pragma unroll
        for (int it = 0; it < 2; it++) {
            const int e = tid + it * 256;
            const int r = e >> 2, s = e & 3;
            cp_async16(sAb + (buf*G_STAGE_H + r*HAS + s*8)*2,
                       A + (size_t)(bm + r) * Kdim + k0 + s*8);
            cp_async16(sWb + (buf*G_STAGE_H + r*HAS + s*8)*2,
                       W + (size_t)(bn + r) * Kdim + k0 + s*8);
        }
    };

    float acc[2][8][4];
    #pragma unroll
    for (int mt = 0; mt < 2; mt++)
        #pragma unroll
        for (int nt = 0; nt < 8; nt++)
            #pragma unroll
            for (int j = 0; j < 4; j++) acc[mt][nt][j] = 0.f;

    issue(0); cp_commit();
    issue(1); cp_commit();

    const int NIT = Kdim / 32;   // 16
    for (int i = 0; i < NIT; i++) {
        const int buf = i % 3;
        if (i + 1 < NIT) asm volatile("cp.async.wait_group 1;");
        else             asm volatile("cp.async.wait_group 0;");
        __syncthreads();

        const uint32_t Ab = sAb + (buf*G_STAGE_H)*2;
        const uint32_t Wb = sWb + (buf*G_STAGE_H)*2;

        #pragma unroll
        for (int kt = 0; kt < 2; kt++) {
            uint32_t a[2][4];
            #pragma unroll
            for (int mt = 0; mt < 2; mt++) {
                const int row = wm*32 + mt*16 + (lane & 15);
                const int col = kt*16 + (lane >> 4) * 8;
                ldm_x4(a[mt][0], a[mt][1], a[mt][2], a[mt][3],
                       Ab + (row*HAS + col)*2);
            }
            #pragma unroll
            for (int nt = 0; nt < 8; nt++) {
                const int row = wn*64 + nt*8 + (lane & 7);
                const int col = kt*16 + ((lane >> 3) & 1) * 8;
                uint32_t b0, b1;
                ldm_x2(b0, b1, Wb + (row*HAS + col)*2);
                mma_f16(acc[0][nt], a[0][0], a[0][1], a[0][2], a[0][3], b0, b1);
                mma_f16(acc[1][nt], a[1][0], a[1][1], a[1][2], a[1][3], b0, b1);
            }
        }
        if (i + 2 < NIT) { issue(i + 2); cp_commit(); }
    }

    if (MODE == 0) {
        #pragma unroll
        for (int nt = 0; nt < 8; nt++) {
            const int col = bn + wn*64 + nt*8 + 2*t;
            const float2 bb = *(const float2*)(bias + col);
            #pragma unroll
            for (int mt = 0; mt < 2; mt++) {
                const int row0 = bm + wm*32 + mt*16 + g;
                const int row1 = row0 + 8;
                float2 v0, v1;
                v0.x = acc[mt][nt][0] + bb.x; v0.y = acc[mt][nt][1] + bb.y;
                v1.x = acc[mt][nt][2] + bb.x; v1.y = acc[mt][nt][3] + bb.y;
                *(float2*)(Co + (size_t)row0 * Ndim + col) = v0;
                *(float2*)(Co + (size_t)row1 * Ndim + col) = v1;
            }
        }
    } else {
        #pragma unroll
        for (int mt = 0; mt < 2; mt++) {
            const int row0 = bm + wm*32 + mt*16 + g;
            const int row1 = row0 + 8;
            const int b0_ = row0 >> 11, t0_ = row0 & 2047;
            const int b1_ = row1 >> 11, t1_ = row1 & 2047;
            #pragma unroll
            for (int nt = 0; nt < 8; nt++) {
                const int col = bn + wn*64 + nt*8 + 2*t;
                const float2 bb = *(const float2*)(bias + col);
                const int h  = col >> 6;
                const int dk = col & 63;
                float2 v0, v1;
                v0.x = (acc[mt][nt][0] + bb.x) * scale;
                v0.y = (acc[mt][nt][1] + bb.y) * scale;
                v1.x = (acc[mt][nt][2] + bb.x) * scale;
                v1.y = (acc[mt][nt][3] + bb.y) * scale;
                *(__half2*)(P.C[z] + ((((size_t)b0_*Hc + h)*Tc + t0_) * DKc) + dk)
                    = __float22half2_rn(v0);
                *(__half2*)(P.C[z] + ((((size_t)b1_*Hc + h)*Tc + t1_) * DKc) + dk)
                    = __float22half2_rn(v1);
            }
        }
    }
}

// ---------------------------------------------------------------------------
// Flash attention over COMPACTED keys (R11/R12, proven).
// ---------------------------------------------------------------------------
#define HS 72
#define SQ_OFF 0
#define SK_OFF (128*HS)
#define SV_OFF (SK_OFF + 3*64*HS)
#define AT_HALVES (SV_OFF + 3*64*HS)
#define AT_SMEM_BYTES (AT_HALVES * 2)   // 73728

__global__ __launch_bounds__(256, 2)
void attn_kernel(const __half* __restrict__ Q, const __half* __restrict__ K,
                 const __half* __restrict__ V, const __half* __restrict__ maskb,
                 const int* __restrict__ nv, __half* __restrict__ CTX)
{
    extern __shared__ __half hsm[];
    __half* sQ = hsm + SQ_OFF;
    __half* sK = hsm + SK_OFF;
    __half* sV = hsm + SV_OFF;
    __shared__ __half sMBh[3][64];

    const uint32_t sQb = smem_u32(sQ);
    const uint32_t sKb = smem_u32(sK);
    const uint32_t sVb = smem_u32(sV);
    const uint32_t sMBb = smem_u32(&sMBh[0][0]);
    const uint32_t* sMB32 = (const uint32_t*)&sMBh[0][0];

    const int tid  = threadIdx.x;
    const int lane = tid & 31;
    const int w    = tid >> 5;
    const int g    = lane >> 2;
    const int t    = lane & 3;
    const int r0   = w * 16;
    const int qt = blockIdx.x;
    const int h  = blockIdx.y;
    const int b  = blockIdx.z;

    const int NV = nv[b];
    const int NC = (NV + 63) >> 6;

    const size_t head_base = (((size_t)b * Hc + h) * Tc) * DKc;
    const __half* Qb = Q + head_base + (size_t)qt * 128 * DKc;
    const __half* Kb = K + head_base;
    const __half* Vb = V + head_base;
    const __half* MBp = maskb + b * Tc;

    const int l15 = lane & 15;
    const int lhi = lane >> 4;
    const int l7  = lane & 7;
    const int lb8 = (lane >> 3) & 1;
    const uint32_t aQaddr = sQb + ((r0 + l15)*HS + lhi*8)*2;
    const uint32_t bKoff = ((l7 + lhi*8)*HS + lb8*8)*2;
    const uint32_t bVoff = (l15*HS + lhi*8)*2;

    for (int idx = tid; idx < 3*64; idx += 256) {
        uint4 v; v.x = 0x00003C00u; v.y = 0; v.z = 0; v.w = 0;
        *(uint4*)(sV + idx*HS + 64) = v;
    }

    #pragma unroll
    for (int it = 0; it < 4; it++) {
        const int e = tid + it * 256;
        const int r = e >> 3, s = e & 7;
        cp_async16(sQb + (r*HS + s*8)*2, Qb + r*DKc + s*8);
    }

    auto issue_chunk = [&](int kc) {
        const int buf = kc % 3;
        const __half* Kc = Kb + (size_t)kc * 64 * DKc;
        const __half* Vc = Vb + (size_t)kc * 64 * DKc;
        #pragma unroll
        for (int it = 0; it < 2; it++) {
            const int e = tid + it * 256;
            const int r = e >> 3, s = e & 7;
            cp_async16(sKb + ((buf*64 + r)*HS + s*8)*2, Kc + r*DKc + s*8);
            cp_async16(sVb + ((buf*64 + r)*HS + s*8)*2, Vc + r*DKc + s*8);
        }
        if (tid < 8) cp_async16(sMBb + (buf*64 + tid*8)*2, MBp + kc*64 + tid*8);
    };

    if (NC > 0) issue_chunk(0);
    cp_commit();
    if (NC > 1) { issue_chunk(1); cp_commit(); }

    float of[8][4];
    float ofs[4];
    float mi0 = -1e30f, mi1 = -1e30f;
    #pragma unroll
    for (int nt = 0; nt < 8; nt++)
        #pragma unroll
        for (int j = 0; j < 4; j++) of[nt][j] = 0.f;
    ofs[0] = ofs[1] = ofs[2] = ofs[3] = 0.f;

    for (int kc = 0; kc < NC; kc++) {
        const int buf = kc % 3;
        if (kc + 1 < NC) asm volatile("cp.async.wait_group 1;");
        else             asm volatile("cp.async.wait_group 0;");
        __syncthreads();

        const uint32_t Kbuf = sKb + (buf*64*HS)*2;
        const uint32_t Vbuf = sVb + (buf*64*HS)*2;

        float sf[8][4];
        #pragma unroll
        for (int nt = 0; nt < 8; nt++)
            #pragma unroll
            for (int j = 0; j < 4; j++) sf[nt][j] = 0.f;

        #pragma unroll
        for (int kt = 0; kt < 4; kt++) {
            uint32_t a0, a1, a2, a3;
            ldm_x4(a0, a1, a2, a3, aQaddr + kt*32);
            #pragma unroll
            for (int nt = 0; nt < 8; nt += 2) {
                uint32_t b0, b1, b2, b3;
                ldm_x4(b0, b1, b2, b3, Kbuf + (nt*8*HS)*2 + kt*32 + bKoff);
                mma_f16(sf[nt],   a0, a1, a2, a3, b0, b1);
                mma_f16(sf[nt+1], a0, a1, a2, a3, b2, b3);
            }
        }

        uint32_t dh[8][2];
        #pragma unroll
        for (int nt = 0; nt < 8; nt++) {
            const uint32_t mb2 = sMB32[buf*32 + nt*4 + t];
            dh[nt][0] = add_h2u(cvt_h2(sf[nt][0], sf[nt][1]), mb2);
            dh[nt][1] = add_h2u(cvt_h2(sf[nt][2], sf[nt][3]), mb2);
        }
        uint32_t m0 = dh[0][0], m1 = dh[0][1];
        #pragma unroll
        for (int nt = 1; nt < 8; nt++) {
            m0 = max_h2u(m0, dh[nt][0]);
            m1 = max_h2u(m1, dh[nt][1]);
        }
        m0 = max_h2u(m0, prmtu(m0, m0, 0x1032));
        m1 = max_h2u(m1, prmtu(m1, m1, 0x1032));
        uint32_t mx2 = prmtu(m0, m1, 0x5410);
        mx2 = max_h2u(mx2, __shfl_xor_sync(0xffffffffu, mx2, 1));
        mx2 = max_h2u(mx2, __shfl_xor_sync(0xffffffffu, mx2, 2));
        const __half2 mxh = *(const __half2*)&mx2;
        const float mx0 = __low2float(mxh);
        const float mx1 = __high2float(mxh);

        const bool skiprow = (mx0 <= mi0) && (mx1 <= mi1) &&
                             (mi0 >= -60.f) && (mi1 >= -60.f);
        float mn0, mn1;
        if (__all_sync(0xffffffffu, skiprow)) {
            mn0 = mi0; mn1 = mi1;
        } else {
            mn0 = fmaxf(fmaxf(mi0, mx0), -60.f);
            mn1 = fmaxf(fmaxf(mi1, mx1), -60.f);
            const float al0 = ex2(mi0 - mn0);
            const float al1 = ex2(mi1 - mn1);
            mi0 = mn0; mi1 = mn1;
            #pragma unroll
            for (int nt = 0; nt < 8; nt++) {
                of[nt][0] *= al0; of[nt][1] *= al0;
                of[nt][2] *= al1; of[nt][3] *= al1;
            }
            ofs[0] *= al0; ofs[1] *= al0;
            ofs[2] *= al1; ofs[3] *= al1;
        }

        __half2 mh0 = __float2half2_rn(mn0);
        __half2 mh1 = __float2half2_rn(mn1);
        const uint32_t mn0h2 = *(uint32_t*)&mh0;
        const uint32_t mn1h2 = *(uint32_t*)&mh1;
        uint32_t ph[8][2];
        #pragma unroll
        for (int nt = 0; nt < 8; nt++) {
            ph[nt][0] = ex2_h2u(sub_h2u(dh[nt][0], mn0h2));
            ph[nt][1] = ex2_h2u(sub_h2u(dh[nt][1], mn1h2));
        }

        #pragma unroll
        for (int kt = 0; kt < 4; kt++) {
            const uint32_t a0 = ph[2*kt][0];
            const uint32_t a1 = ph[2*kt][1];
            const uint32_t a2 = ph[2*kt+1][0];
            const uint32_t a3 = ph[2*kt+1][1];
            #pragma unroll
            for (int nt = 0; nt < 8; nt += 2) {
                uint32_t b0, b1, b2, b3;
                ldm_x4t(b0, b1, b2, b3, Vbuf + (kt*16*HS + nt*8)*2 + bVoff);
                mma_f16(of[nt],   a0, a1, a2, a3, b0, b1);
                mma_f16(of[nt+1], a0, a1, a2, a3, b2, b3);
            }
            uint32_t s0, s1;
            ldm_x2t(s0, s1, Vbuf + ((kt*16 + l15)*HS + 64)*2);
            mma_f16(ofs, a0, a1, a2, a3, s0, s1);
        }

        if (kc + 2 < NC) { issue_chunk(kc + 2); cp_commit(); }
    }
    if (NC == 0) asm volatile("cp.async.wait_group 0;");

    const float li0 = __shfl_sync(0xffffffffu, ofs[0], lane & 28);
    const float li1 = __shfl_sync(0xffffffffu, ofs[2], lane & 28);
    const float inv0 = (li0 > 0.f) ? (1.0f / li0) : 0.f;
    const float inv1 = (li1 > 0.f) ? (1.0f / li1) : 0.f;
    const int t0 = qt*128 + r0 + g;
    const int t1 = t0 + 8;
    #pragma unroll
    for (int nt = 0; nt < 8; nt++) {
        const int dk = nt*8 + 2*t;
        __half2 w0 = __float22half2_rn(make_float2(of[nt][0] * inv0, of[nt][1] * inv0));
        __half2 w1 = __float22half2_rn(make_float2(of[nt][2] * inv1, of[nt][3] * inv1));
        *(__half2*)(CTX + ((size_t)b * Tc + t0) * Fc + h*DKc + dk) = w0;
        *(__half2*)(CTX + ((size_t)b * Tc + t1) * Fc + h*DKc + dk) = w1;
    }
}

// ---------------------------------------------------------------------------
// Launcher
// ---------------------------------------------------------------------------
extern "C" void kernel_launch(void* const* d_in, const int* in_sizes, int n_in,
                              void* d_out, int out_size)
{
    const float* query = (const float*)d_in[0];
    const float* key   = (const float*)d_in[1];
    const float* value = (const float*)d_in[2];
    const int*   amask = (const int*)  d_in[3];
    const float* Wq = (const float*)d_in[4];
    const float* bq = (const float*)d_in[5];
    const float* Wk = (const float*)d_in[6];
    const float* bk = (const float*)d_in[7];
    const float* Wv = (const float*)d_in[8];
    const float* bv = (const float*)d_in[9];
    const float* Wo = (const float*)d_in[10];
    const float* bo = (const float*)d_in[11];
    float* out = (float*)d_out;

    __half *pXh, *pWh, *pQ, *pK, *pV, *pCTX, *pMB;
    int *pRK, *pNV;
    cudaGetSymbolAddress((void**)&pXh, g_Xh);
    cudaGetSymbolAddress((void**)&pWh, g_Wh);
    cudaGetSymbolAddress((void**)&pQ,  g_Qh);
    cudaGetSymbolAddress((void**)&pK,  g_Kh);
    cudaGetSymbolAddress((void**)&pV,  g_Vh);
    cudaGetSymbolAddress((void**)&pCTX, g_CTXh);
    cudaGetSymbolAddress((void**)&pMB, g_MBh);
    cudaGetSymbolAddress((void**)&pRK, g_RK);
    cudaGetSymbolAddress((void**)&pNV, g_NV);

    __half* xh[3] = { pXh, pXh + (size_t)Mdim*Fc, pXh + 2*(size_t)Mdim*Fc };
    __half* wh[4] = { pWh, pWh + (size_t)Fc*Fc, pWh + 2*(size_t)Fc*Fc, pWh + 3*(size_t)Fc*Fc };

    cudaFuncSetAttribute(attn_kernel,
                         cudaFuncAttributeMaxDynamicSharedMemorySize, AT_SMEM_BYTES);
    cudaFuncSetAttribute(gemm_h_kernel<0>,
                         cudaFuncAttributeMaxDynamicSharedMemorySize, G_SMEM_BYTES);
    cudaFuncSetAttribute(gemm_h_kernel<1>,
                         cudaFuncAttributeMaxDynamicSharedMemorySize, G_SMEM_BYTES);

    // 1) mask compaction first (cvt gathers key/value rows by rank)
    compact_mask_kernel<<<Bc, 256>>>(amask, pRK, pMB, pNV);

    const int NB_IN = (Mdim*Fc)/(256*4);   // 4096
    const int NB_W  = (Fc*Fc)/(256*4);     // 256
    CvtJobs7 J;
    J.src[0] = query; J.src[1] = key; J.src[2] = value;
    J.src[3] = Wq; J.src[4] = Wk; J.src[5] = Wv; J.src[6] = Wo;
    J.dst[0] = xh[0]; J.dst[1] = xh[1]; J.dst[2] = xh[2];
    J.dst[3] = wh[0]; J.dst[4] = wh[1]; J.dst[5] = wh[2]; J.dst[6] = wh[3];
    J.nblk[0] = NB_IN; J.nblk[1] = NB_IN; J.nblk[2] = NB_IN;
    J.nblk[3] = NB_W;  J.nblk[4] = NB_W;  J.nblk[5] = NB_W;  J.nblk[6] = NB_W;
    cvt_kernel<<<dim3(NB_IN, 7), 256>>>(J, pRK);

    // 2) fused QKV projections; K/V over compacted inputs, dead blocks skipped
    QKVJobs P;
    P.A[0] = xh[0]; P.A[1] = xh[1]; P.A[2] = xh[2];
    P.W[0] = wh[0]; P.W[1] = wh[1]; P.W[2] = wh[2];
    P.bias[0] = bq; P.bias[1] = bk; P.bias[2] = bv;
    P.C[0] = pQ;    P.C[1] = pK;   P.C[2] = pV;
    gemm_h_kernel<1><<<dim3(Ndim/128, Mdim/128, 3), 256, G_SMEM_BYTES>>>(
        P, nullptr, nullptr, nullptr, nullptr, pNV);

    // 3) attention over compacted keys
    attn_kernel<<<dim3(Tc/128, Hc, Bc), 256, AT_SMEM_BYTES>>>(pQ, pK, pV, pMB, pNV, pCTX);

    // 4) output projection
    QKVJobs PD = {};
    gemm_h_kernel<0><<<dim3(Ndim/128, Mdim/128), 256, G_SMEM_BYTES>>>(
        PD, pCTX, wh[3], bo, out, nullptr);
}